// round 1
// baseline (speedup 1.0000x reference)
#include <cuda_runtime.h>
#include <math_constants.h>
#include <math.h>

// Problem constants
#define BSZ   8
#define TSEQ  1024
#define EMB   1024
#define NHEAD 16
#define HEADD 64
#define MROWS (BSZ * TSEQ)   // 8192
#define FFDIM 4096

// ---------------------------------------------------------------------------
// Scratch (static device globals: allocation-free per harness rules)
// ---------------------------------------------------------------------------
__device__ float g_h   [(size_t)MROWS * EMB];   // ln1 out, reused for ln2 out
__device__ float g_q   [(size_t)MROWS * EMB];
__device__ float g_k   [(size_t)MROWS * EMB];
__device__ float g_v   [(size_t)MROWS * EMB];
__device__ float g_attn[(size_t)MROWS * EMB];
__device__ float g_out1[(size_t)MROWS * EMB];   // x + attn@w_proj + b_proj
__device__ float g_mid [(size_t)MROWS * FFDIM]; // gelu(h2@w1 + b1)

// ---------------------------------------------------------------------------
// LayerNorm: one block (256 threads) per row of 1024 floats
// ---------------------------------------------------------------------------
__global__ __launch_bounds__(256)
void ln_kernel(const float* __restrict__ x, const float* __restrict__ g,
               const float* __restrict__ b, float* __restrict__ out)
{
    int row = blockIdx.x;
    int t   = threadIdx.x;
    const float4* xr = (const float4*)(x + (size_t)row * EMB);
    float4 v = xr[t];
    float s  = v.x + v.y + v.z + v.w;
    float ss = v.x * v.x + v.y * v.y + v.z * v.z + v.w * v.w;

    #pragma unroll
    for (int o = 16; o; o >>= 1) {
        s  += __shfl_xor_sync(0xffffffffu, s,  o);
        ss += __shfl_xor_sync(0xffffffffu, ss, o);
    }
    __shared__ float rs_[8], rss_[8];
    __shared__ float mu_s, rstd_s;
    int warp = t >> 5, lane = t & 31;
    if (lane == 0) { rs_[warp] = s; rss_[warp] = ss; }
    __syncthreads();
    if (t == 0) {
        float S = 0.f, SS = 0.f;
        #pragma unroll
        for (int i = 0; i < 8; i++) { S += rs_[i]; SS += rss_[i]; }
        float mu  = S * (1.0f / EMB);
        float var = SS * (1.0f / EMB) - mu * mu;
        mu_s   = mu;
        rstd_s = rsqrtf(var + 1e-5f);
    }
    __syncthreads();
    float mu = mu_s, r = rstd_s;
    float4 gv = ((const float4*)g)[t];
    float4 bv = ((const float4*)b)[t];
    float4 o4;
    o4.x = (v.x - mu) * r * gv.x + bv.x;
    o4.y = (v.y - mu) * r * gv.y + bv.y;
    o4.z = (v.z - mu) * r * gv.z + bv.z;
    o4.w = (v.w - mu) * r * gv.w + bv.w;
    ((float4*)(out + (size_t)row * EMB))[t] = o4;
}

// ---------------------------------------------------------------------------
// SGEMM: C[M,N] = A[M,K] @ B[K,N] (+bias)(+res)(GELU)
// 128x128 tile, BK=16, 256 threads, 8x8 microtile per thread.
// All dims assumed multiples of the tile sizes (true for this problem).
// ---------------------------------------------------------------------------
template<bool GELU>
__global__ __launch_bounds__(256)
void sgemm_kernel(const float* __restrict__ A, const float* __restrict__ B,
                  const float* __restrict__ bias, const float* __restrict__ res,
                  float* __restrict__ C, int M, int N, int K)
{
    __shared__ float As[16][132];  // padded, transposed A tile
    __shared__ float Bs[16][132];
    int tid = threadIdx.x;
    int tx = tid & 15, ty = tid >> 4;
    int rowBase = blockIdx.y * 128;
    int colBase = blockIdx.x * 128;

    float acc[8][8];
    #pragma unroll
    for (int i = 0; i < 8; i++)
        #pragma unroll
        for (int j = 0; j < 8; j++) acc[i][j] = 0.f;

    for (int k0 = 0; k0 < K; k0 += 16) {
        // A tile: 128 rows x 16 cols = 512 float4, transpose into As
        #pragma unroll
        for (int s = 0; s < 2; s++) {
            int idx = tid + s * 256;
            int r = idx >> 2, c4 = idx & 3;
            float4 a = *(const float4*)(A + (size_t)(rowBase + r) * K + k0 + c4 * 4);
            As[c4 * 4 + 0][r] = a.x;
            As[c4 * 4 + 1][r] = a.y;
            As[c4 * 4 + 2][r] = a.z;
            As[c4 * 4 + 3][r] = a.w;
        }
        // B tile: 16 rows x 128 cols = 512 float4
        #pragma unroll
        for (int s = 0; s < 2; s++) {
            int idx = tid + s * 256;
            int r = idx >> 5, c4 = idx & 31;
            *(float4*)&Bs[r][c4 * 4] =
                *(const float4*)(B + (size_t)(k0 + r) * N + colBase + c4 * 4);
        }
        __syncthreads();
        #pragma unroll
        for (int kk = 0; kk < 16; kk++) {
            float4 a0 = *(float4*)&As[kk][ty * 8];
            float4 a1 = *(float4*)&As[kk][ty * 8 + 4];
            float4 b0 = *(float4*)&Bs[kk][tx * 8];
            float4 b1 = *(float4*)&Bs[kk][tx * 8 + 4];
            float ar[8] = {a0.x, a0.y, a0.z, a0.w, a1.x, a1.y, a1.z, a1.w};
            float br[8] = {b0.x, b0.y, b0.z, b0.w, b1.x, b1.y, b1.z, b1.w};
            #pragma unroll
            for (int i = 0; i < 8; i++)
                #pragma unroll
                for (int j = 0; j < 8; j++)
                    acc[i][j] += ar[i] * br[j];
        }
        __syncthreads();
    }

    #pragma unroll
    for (int i = 0; i < 8; i++) {
        int row = rowBase + ty * 8 + i;
        #pragma unroll
        for (int j = 0; j < 8; j++) {
            int col = colBase + tx * 8 + j;
            float v = acc[i][j];
            if (bias) v += bias[col];
            if (res)  v += res[(size_t)row * N + col];
            if (GELU) v = 0.5f * v * (1.0f + erff(v * 0.70710678118654752f));
            C[(size_t)row * N + col] = v;
        }
    }
}

// ---------------------------------------------------------------------------
// Causal flash attention, fp32. D=64.
// grid = (T/64, NHEAD, BSZ), 256 threads (16x16, each thread 4x4 microtile).
// Q/K/V layout: row (b*T + t), col (h*64 + d).
// ---------------------------------------------------------------------------
#define ATP 68  // padded tile row width

__global__ __launch_bounds__(256)
void attn_kernel(const float* __restrict__ Q, const float* __restrict__ K,
                 const float* __restrict__ V, float* __restrict__ Out)
{
    extern __shared__ float sm[];
    float (*Qs)[ATP] = (float(*)[ATP])(sm);
    float (*Ks)[ATP] = (float(*)[ATP])(sm + 64 * ATP);
    float (*Vs)[ATP] = (float(*)[ATP])(sm + 2 * 64 * ATP);
    float (*Ps)[ATP] = (float(*)[ATP])(sm + 3 * 64 * ATP);

    int it = blockIdx.x, h = blockIdx.y, bb = blockIdx.z;
    int tid = threadIdx.x;
    int tx = tid & 15, ty = tid >> 4;

    // Load Q tile [64][64]
    size_t qbase = ((size_t)(bb * TSEQ + it * 64)) * EMB + h * HEADD;
    #pragma unroll
    for (int s = 0; s < 4; s++) {
        int idx = tid + s * 256;
        int r = idx >> 4, c4 = idx & 15;
        *(float4*)&Qs[r][c4 * 4] = *(const float4*)(Q + qbase + (size_t)r * EMB + c4 * 4);
    }

    float m[4], l[4], acc[4][4];
    #pragma unroll
    for (int i = 0; i < 4; i++) {
        m[i] = -CUDART_INF_F;
        l[i] = 0.f;
        #pragma unroll
        for (int j = 0; j < 4; j++) acc[i][j] = 0.f;
    }
    const float scale = 0.125f;  // 64^-0.5

    for (int jt = 0; jt <= it; jt++) {
        __syncthreads();  // previous tile's P.V reads done before overwriting K/V/P
        size_t kbase = ((size_t)(bb * TSEQ + jt * 64)) * EMB + h * HEADD;
        #pragma unroll
        for (int s = 0; s < 4; s++) {
            int idx = tid + s * 256;
            int r = idx >> 4, c4 = idx & 15;
            *(float4*)&Ks[r][c4 * 4] = *(const float4*)(K + kbase + (size_t)r * EMB + c4 * 4);
            *(float4*)&Vs[r][c4 * 4] = *(const float4*)(V + kbase + (size_t)r * EMB + c4 * 4);
        }
        __syncthreads();

        // S = scale * Q K^T  (each thread 4x4 of the 64x64 tile)
        float sreg[4][4];
        #pragma unroll
        for (int i = 0; i < 4; i++)
            #pragma unroll
            for (int j = 0; j < 4; j++) sreg[i][j] = 0.f;

        #pragma unroll
        for (int d4 = 0; d4 < 16; d4++) {
            float qr[4][4], kr[4][4];
            #pragma unroll
            for (int i = 0; i < 4; i++) {
                float4 t = *(float4*)&Qs[ty * 4 + i][d4 * 4];
                qr[i][0] = t.x; qr[i][1] = t.y; qr[i][2] = t.z; qr[i][3] = t.w;
            }
            #pragma unroll
            for (int j = 0; j < 4; j++) {
                float4 t = *(float4*)&Ks[tx * 4 + j][d4 * 4];
                kr[j][0] = t.x; kr[j][1] = t.y; kr[j][2] = t.z; kr[j][3] = t.w;
            }
            #pragma unroll
            for (int i = 0; i < 4; i++)
                #pragma unroll
                for (int j = 0; j < 4; j++)
                    sreg[i][j] += qr[i][0] * kr[j][0] + qr[i][1] * kr[j][1]
                                + qr[i][2] * kr[j][2] + qr[i][3] * kr[j][3];
        }

        bool diag = (jt == it);
        #pragma unroll
        for (int i = 0; i < 4; i++)
            #pragma unroll
            for (int j = 0; j < 4; j++) {
                float sv = sreg[i][j] * scale;
                if (diag && (tx * 4 + j) > (ty * 4 + i)) sv = -CUDART_INF_F;
                sreg[i][j] = sv;
            }

        // Online softmax update (row groups = 16 lanes within a half-warp)
        #pragma unroll
        for (int i = 0; i < 4; i++) {
            float rm = fmaxf(fmaxf(sreg[i][0], sreg[i][1]), fmaxf(sreg[i][2], sreg[i][3]));
            #pragma unroll
            for (int o = 8; o; o >>= 1)
                rm = fmaxf(rm, __shfl_xor_sync(0xffffffffu, rm, o, 16));
            float mn = fmaxf(m[i], rm);
            float alpha = expf(m[i] - mn);
            float psum = 0.f;
            #pragma unroll
            for (int j = 0; j < 4; j++) {
                float p = expf(sreg[i][j] - mn);
                sreg[i][j] = p;
                psum += p;
            }
            #pragma unroll
            for (int o = 8; o; o >>= 1)
                psum += __shfl_xor_sync(0xffffffffu, psum, o, 16);
            l[i] = l[i] * alpha + psum;
            m[i] = mn;
            #pragma unroll
            for (int j = 0; j < 4; j++) acc[i][j] *= alpha;
        }

        // Write P tile to shared
        #pragma unroll
        for (int i = 0; i < 4; i++)
            #pragma unroll
            for (int j = 0; j < 4; j++)
                Ps[ty * 4 + i][tx * 4 + j] = sreg[i][j];
        __syncthreads();

        // acc += P @ V
        #pragma unroll
        for (int k4 = 0; k4 < 16; k4++) {
            float pr[4][4], vr[4][4];
            #pragma unroll
            for (int i = 0; i < 4; i++) {
                float4 t = *(float4*)&Ps[ty * 4 + i][k4 * 4];
                pr[i][0] = t.x; pr[i][1] = t.y; pr[i][2] = t.z; pr[i][3] = t.w;
            }
            #pragma unroll
            for (int s = 0; s < 4; s++) {
                float4 t = *(float4*)&Vs[k4 * 4 + s][tx * 4];
                vr[s][0] = t.x; vr[s][1] = t.y; vr[s][2] = t.z; vr[s][3] = t.w;
            }
            #pragma unroll
            for (int i = 0; i < 4; i++)
                #pragma unroll
                for (int j = 0; j < 4; j++)
                    acc[i][j] += pr[i][0] * vr[0][j] + pr[i][1] * vr[1][j]
                               + pr[i][2] * vr[2][j] + pr[i][3] * vr[3][j];
        }
    }

    // Normalize and store: out[b, q, h*64+d]
    #pragma unroll
    for (int i = 0; i < 4; i++) {
        float inv = 1.0f / l[i];
        size_t obase = ((size_t)(bb * TSEQ + it * 64 + ty * 4 + i)) * EMB + h * HEADD + tx * 4;
        float4 o4 = make_float4(acc[i][0] * inv, acc[i][1] * inv,
                                acc[i][2] * inv, acc[i][3] * inv);
        *(float4*)(Out + obase) = o4;
    }
}

// ---------------------------------------------------------------------------
// Launch
// ---------------------------------------------------------------------------
extern "C" void kernel_launch(void* const* d_in, const int* in_sizes, int n_in,
                              void* d_out, int out_size)
{
    const float* x      = (const float*)d_in[0];
    const float* ln1_g  = (const float*)d_in[1];
    const float* ln1_b  = (const float*)d_in[2];
    const float* wq     = (const float*)d_in[3];
    const float* wk     = (const float*)d_in[4];
    const float* wv     = (const float*)d_in[5];
    const float* w_proj = (const float*)d_in[6];
    const float* b_proj = (const float*)d_in[7];
    const float* ln2_g  = (const float*)d_in[8];
    const float* ln2_b  = (const float*)d_in[9];
    const float* w1     = (const float*)d_in[10];
    const float* b1     = (const float*)d_in[11];
    const float* w2     = (const float*)d_in[12];
    const float* b2     = (const float*)d_in[13];
    float* out = (float*)d_out;

    float *h, *q, *k, *v, *attn, *out1, *mid;
    cudaGetSymbolAddress((void**)&h,    g_h);
    cudaGetSymbolAddress((void**)&q,    g_q);
    cudaGetSymbolAddress((void**)&k,    g_k);
    cudaGetSymbolAddress((void**)&v,    g_v);
    cudaGetSymbolAddress((void**)&attn, g_attn);
    cudaGetSymbolAddress((void**)&out1, g_out1);
    cudaGetSymbolAddress((void**)&mid,  g_mid);

    const int attn_smem = 4 * 64 * ATP * (int)sizeof(float);  // 69632 B
    cudaFuncSetAttribute(attn_kernel, cudaFuncAttributeMaxDynamicSharedMemorySize, attn_smem);

    // 1. LN1
    ln_kernel<<<MROWS, 256>>>(x, ln1_g, ln1_b, h);

    // 2. QKV projections
    dim3 gE(EMB / 128, MROWS / 128);
    sgemm_kernel<false><<<gE, 256>>>(h, wq, nullptr, nullptr, q, MROWS, EMB, EMB);
    sgemm_kernel<false><<<gE, 256>>>(h, wk, nullptr, nullptr, k, MROWS, EMB, EMB);
    sgemm_kernel<false><<<gE, 256>>>(h, wv, nullptr, nullptr, v, MROWS, EMB, EMB);

    // 3. Causal attention
    attn_kernel<<<dim3(TSEQ / 64, NHEAD, BSZ), 256, attn_smem>>>(q, k, v, attn);

    // 4. Projection + residual: out1 = x + attn @ w_proj + b_proj
    sgemm_kernel<false><<<gE, 256>>>(attn, w_proj, b_proj, x, out1, MROWS, EMB, EMB);

    // 5. LN2
    ln_kernel<<<MROWS, 256>>>(out1, ln2_g, ln2_b, h);

    // 6. MLP up + exact GELU
    dim3 gF(FFDIM / 128, MROWS / 128);
    sgemm_kernel<true><<<gF, 256>>>(h, w1, b1, nullptr, mid, MROWS, FFDIM, EMB);

    // 7. MLP down + bias + residual -> final output
    sgemm_kernel<false><<<gE, 256>>>(mid, w2, b2, out1, out, MROWS, EMB, FFDIM);
}

// round 3
// speedup vs baseline: 2.5356x; 2.5356x over previous
#include <cuda_runtime.h>
#include <math_constants.h>
#include <math.h>
#include <stdint.h>

#define BSZ   8
#define TSEQ  1024
#define EMB   1024
#define NHEAD 16
#define HEADD 64
#define MROWS (BSZ * TSEQ)   // 8192
#define FFDIM 4096

// ---------------------------------------------------------------------------
// Scratch
// ---------------------------------------------------------------------------
__device__ float g_h   [(size_t)MROWS * EMB];
__device__ float g_q   [(size_t)MROWS * EMB];
__device__ float g_k   [(size_t)MROWS * EMB];
__device__ float g_v   [(size_t)MROWS * EMB];
__device__ float g_attn[(size_t)MROWS * EMB];
__device__ float g_out1[(size_t)MROWS * EMB];
__device__ float g_mid [(size_t)MROWS * FFDIM];
// transposed + tf32-rounded weights: Wt[n][k] = round_tf32(W[k][n])
__device__ float g_wqT[(size_t)EMB * EMB];
__device__ float g_wkT[(size_t)EMB * EMB];
__device__ float g_wvT[(size_t)EMB * EMB];
__device__ float g_wpT[(size_t)EMB * EMB];
__device__ float g_w1T[(size_t)EMB * FFDIM];
__device__ float g_w2T[(size_t)FFDIM * EMB];

// ---------------------------------------------------------------------------
// Helpers
// ---------------------------------------------------------------------------
__device__ __forceinline__ float tf32r(float x) {
    uint32_t u;
    asm("cvt.rna.tf32.f32 %0, %1;" : "=r"(u) : "f"(x));
    return __uint_as_float(u);
}

__device__ __forceinline__ uint32_t smem_u32(const void* p) {
    uint32_t a;
    asm("{ .reg .u64 t; cvta.to.shared.u64 t, %1; cvt.u32.u64 %0, t; }" : "=r"(a) : "l"(p));
    return a;
}

__device__ __forceinline__ void cp16(uint32_t dst, const void* src) {
    asm volatile("cp.async.cg.shared.global [%0], [%1], 16;" :: "r"(dst), "l"(src) : "memory");
}
__device__ __forceinline__ void cp_commit() {
    asm volatile("cp.async.commit_group;" ::: "memory");
}
template<int N>
__device__ __forceinline__ void cp_wait() {
    asm volatile("cp.async.wait_group %0;" :: "n"(N) : "memory");
}

__device__ __forceinline__ void mma_tf32(float& c0, float& c1, float& c2, float& c3,
                                         uint32_t a0, uint32_t a1, uint32_t a2, uint32_t a3,
                                         uint32_t b0, uint32_t b1) {
    asm volatile(
        "mma.sync.aligned.m16n8k8.row.col.f32.tf32.tf32.f32 "
        "{%0,%1,%2,%3}, {%4,%5,%6,%7}, {%8,%9}, {%0,%1,%2,%3};"
        : "+f"(c0), "+f"(c1), "+f"(c2), "+f"(c3)
        : "r"(a0), "r"(a1), "r"(a2), "r"(a3), "r"(b0), "r"(b1));
}

// ---------------------------------------------------------------------------
// Transpose + tf32-round weights: in[K][N] -> out[N][K]
// ---------------------------------------------------------------------------
__global__ __launch_bounds__(256)
void transpose_round_kernel(const float* __restrict__ in, float* __restrict__ out,
                            int K, int N)
{
    __shared__ float t[32][33];
    int n0 = blockIdx.x * 32, k0 = blockIdx.y * 32;
    int tx = threadIdx.x, ty = threadIdx.y;  // 32 x 8
    #pragma unroll
    for (int i = 0; i < 32; i += 8)
        t[ty + i][tx] = in[(size_t)(k0 + ty + i) * N + n0 + tx];
    __syncthreads();
    #pragma unroll
    for (int i = 0; i < 32; i += 8)
        out[(size_t)(n0 + ty + i) * K + k0 + tx] = tf32r(t[tx][ty + i]);
}

// ---------------------------------------------------------------------------
// LayerNorm (outputs tf32-rounded: they feed MMA A operands)
// ---------------------------------------------------------------------------
__global__ __launch_bounds__(256)
void ln_kernel(const float* __restrict__ x, const float* __restrict__ g,
               const float* __restrict__ b, float* __restrict__ out)
{
    int row = blockIdx.x;
    int t   = threadIdx.x;
    const float4* xr = (const float4*)(x + (size_t)row * EMB);
    float4 v = xr[t];
    float s  = v.x + v.y + v.z + v.w;
    float ss = v.x * v.x + v.y * v.y + v.z * v.z + v.w * v.w;
    #pragma unroll
    for (int o = 16; o; o >>= 1) {
        s  += __shfl_xor_sync(0xffffffffu, s,  o);
        ss += __shfl_xor_sync(0xffffffffu, ss, o);
    }
    __shared__ float rs_[8], rss_[8];
    __shared__ float mu_s, rstd_s;
    int warp = t >> 5, lane = t & 31;
    if (lane == 0) { rs_[warp] = s; rss_[warp] = ss; }
    __syncthreads();
    if (t == 0) {
        float S = 0.f, SS = 0.f;
        #pragma unroll
        for (int i = 0; i < 8; i++) { S += rs_[i]; SS += rss_[i]; }
        float mu  = S * (1.0f / EMB);
        float var = SS * (1.0f / EMB) - mu * mu;
        mu_s = mu;
        rstd_s = rsqrtf(var + 1e-5f);
    }
    __syncthreads();
    float mu = mu_s, r = rstd_s;
    float4 gv = ((const float4*)g)[t];
    float4 bv = ((const float4*)b)[t];
    float4 o4;
    o4.x = tf32r((v.x - mu) * r * gv.x + bv.x);
    o4.y = tf32r((v.y - mu) * r * gv.y + bv.y);
    o4.z = tf32r((v.z - mu) * r * gv.z + bv.z);
    o4.w = tf32r((v.w - mu) * r * gv.w + bv.w);
    ((float4*)(out + (size_t)row * EMB))[t] = o4;
}

// ---------------------------------------------------------------------------
// tf32 mma.sync GEMM: C[M,N] = A[M,K] @ Bt[N,K]^T (+bias)(+res)(GELU)(ROUND)
// CTA 128x128, BK=32, 256 threads (8 warps, warp tile 64x32), double-buffered
// cp.async smem. Smem rows padded to 36 floats (conflict-free fragment LDS).
// ---------------------------------------------------------------------------
#define GM_STRIDE 36                       // floats per smem row
#define GM_TILE_BYTES (128 * GM_STRIDE * 4)   // 18432 per operand tile
#define GM_BUF_BYTES  (2 * GM_TILE_BYTES)     // A+B per stage
#define GM_SMEM (2 * GM_BUF_BYTES)            // 73728

template<bool GELU, bool ROUND>
__global__ __launch_bounds__(256)
void gemm_mma_kernel(const float* __restrict__ A, const float* __restrict__ Bt,
                     const float* __restrict__ bias, const float* __restrict__ res,
                     float* __restrict__ C, int N_, int K_)
{
    extern __shared__ char smem[];
    const uint32_t sb = smem_u32(smem);
    int tid  = threadIdx.x;
    int lane = tid & 31, warp = tid >> 5;
    int wm = warp >> 2;   // 0..1  (64-row slab)
    int wn = warp & 3;    // 0..3  (32-col slab)
    int rowBase = blockIdx.y * 128;
    int colBase = blockIdx.x * 128;

    const int C_CHUNKS = K_ >> 5;

    // issue cp.async for chunk c into buffer b
    auto load_chunk = [&](int c, int b) {
        int k0 = c << 5;
        uint32_t aBase = sb + b * GM_BUF_BYTES;
        uint32_t bBase = aBase + GM_TILE_BYTES;
        #pragma unroll
        for (int s = 0; s < 4; s++) {
            int idx = tid + s * 256;          // 1024 chunks of 16B
            int r = idx >> 3, ch = idx & 7;
            cp16(aBase + (uint32_t)(r * GM_STRIDE * 4 + ch * 16),
                 A + (size_t)(rowBase + r) * K_ + k0 + ch * 4);
        }
        #pragma unroll
        for (int s = 0; s < 4; s++) {
            int idx = tid + s * 256;
            int r = idx >> 3, ch = idx & 7;
            cp16(bBase + (uint32_t)(r * GM_STRIDE * 4 + ch * 16),
                 Bt + (size_t)(colBase + r) * K_ + k0 + ch * 4);
        }
        cp_commit();
    };

    float acc[4][4][4];
    #pragma unroll
    for (int i = 0; i < 4; i++)
        #pragma unroll
        for (int j = 0; j < 4; j++)
            #pragma unroll
            for (int r = 0; r < 4; r++) acc[i][j][r] = 0.f;

    load_chunk(0, 0);

    int lq = lane >> 2;   // 0..7
    int lr = lane & 3;    // 0..3

    for (int c = 0; c < C_CHUNKS; c++) {
        int b = c & 1;
        if (c + 1 < C_CHUNKS) {
            load_chunk(c + 1, 1 - b);
            cp_wait<1>();
        } else {
            cp_wait<0>();
        }
        __syncthreads();

        const float* As = (const float*)(smem + b * GM_BUF_BYTES);
        const float* Bs = (const float*)(smem + b * GM_BUF_BYTES + GM_TILE_BYTES);

        #pragma unroll
        for (int ks = 0; ks < 4; ks++) {
            int kk = ks * 8;
            uint32_t a[4][4];
            #pragma unroll
            for (int mt = 0; mt < 4; mt++) {
                int r0 = wm * 64 + mt * 16 + lq;
                a[mt][0] = __float_as_uint(As[r0 * GM_STRIDE + kk + lr]);
                a[mt][1] = __float_as_uint(As[(r0 + 8) * GM_STRIDE + kk + lr]);
                a[mt][2] = __float_as_uint(As[r0 * GM_STRIDE + kk + lr + 4]);
                a[mt][3] = __float_as_uint(As[(r0 + 8) * GM_STRIDE + kk + lr + 4]);
            }
            uint32_t bf[4][2];
            #pragma unroll
            for (int nt = 0; nt < 4; nt++) {
                int n = wn * 32 + nt * 8 + lq;
                bf[nt][0] = __float_as_uint(Bs[n * GM_STRIDE + kk + lr]);
                bf[nt][1] = __float_as_uint(Bs[n * GM_STRIDE + kk + lr + 4]);
            }
            #pragma unroll
            for (int mt = 0; mt < 4; mt++)
                #pragma unroll
                for (int nt = 0; nt < 4; nt++)
                    mma_tf32(acc[mt][nt][0], acc[mt][nt][1], acc[mt][nt][2], acc[mt][nt][3],
                             a[mt][0], a[mt][1], a[mt][2], a[mt][3],
                             bf[nt][0], bf[nt][1]);
        }
        __syncthreads();
    }

    // Epilogue
    #pragma unroll
    for (int mt = 0; mt < 4; mt++) {
        int row0 = rowBase + wm * 64 + mt * 16 + lq;
        #pragma unroll
        for (int nt = 0; nt < 4; nt++) {
            int col = colBase + wn * 32 + nt * 8 + lr * 2;
            float2 p0 = make_float2(acc[mt][nt][0], acc[mt][nt][1]);
            float2 p1 = make_float2(acc[mt][nt][2], acc[mt][nt][3]);
            if (bias) {
                float2 bv = *(const float2*)(bias + col);
                p0.x += bv.x; p0.y += bv.y;
                p1.x += bv.x; p1.y += bv.y;
            }
            if (res) {
                float2 r0 = *(const float2*)(res + (size_t)row0 * N_ + col);
                float2 r1 = *(const float2*)(res + (size_t)(row0 + 8) * N_ + col);
                p0.x += r0.x; p0.y += r0.y;
                p1.x += r1.x; p1.y += r1.y;
            }
            if (GELU) {
                p0.x = 0.5f * p0.x * (1.0f + erff(p0.x * 0.70710678118654752f));
                p0.y = 0.5f * p0.y * (1.0f + erff(p0.y * 0.70710678118654752f));
                p1.x = 0.5f * p1.x * (1.0f + erff(p1.x * 0.70710678118654752f));
                p1.y = 0.5f * p1.y * (1.0f + erff(p1.y * 0.70710678118654752f));
            }
            if (ROUND) {
                p0.x = tf32r(p0.x); p0.y = tf32r(p0.y);
                p1.x = tf32r(p1.x); p1.y = tf32r(p1.y);
            }
            *(float2*)(C + (size_t)row0 * N_ + col) = p0;
            *(float2*)(C + (size_t)(row0 + 8) * N_ + col) = p1;
        }
    }
}

// ---------------------------------------------------------------------------
// Causal flash attention, fp32, D=64 (output tf32-rounded)
// ---------------------------------------------------------------------------
#define ATP 68

__global__ __launch_bounds__(256)
void attn_kernel(const float* __restrict__ Q, const float* __restrict__ K,
                 const float* __restrict__ V, float* __restrict__ Out)
{
    extern __shared__ float sm[];
    float (*Qs)[ATP] = (float(*)[ATP])(sm);
    float (*Ks)[ATP] = (float(*)[ATP])(sm + 64 * ATP);
    float (*Vs)[ATP] = (float(*)[ATP])(sm + 2 * 64 * ATP);
    float (*Ps)[ATP] = (float(*)[ATP])(sm + 3 * 64 * ATP);

    int it = blockIdx.x, h = blockIdx.y, bb = blockIdx.z;
    int tid = threadIdx.x;
    int tx = tid & 15, ty = tid >> 4;

    size_t qbase = ((size_t)(bb * TSEQ + it * 64)) * EMB + h * HEADD;
    #pragma unroll
    for (int s = 0; s < 4; s++) {
        int idx = tid + s * 256;
        int r = idx >> 4, c4 = idx & 15;
        *(float4*)&Qs[r][c4 * 4] = *(const float4*)(Q + qbase + (size_t)r * EMB + c4 * 4);
    }

    float m[4], l[4], acc[4][4];
    #pragma unroll
    for (int i = 0; i < 4; i++) {
        m[i] = -CUDART_INF_F;
        l[i] = 0.f;
        #pragma unroll
        for (int j = 0; j < 4; j++) acc[i][j] = 0.f;
    }
    const float scale = 0.125f;

    for (int jt = 0; jt <= it; jt++) {
        __syncthreads();
        size_t kbase = ((size_t)(bb * TSEQ + jt * 64)) * EMB + h * HEADD;
        #pragma unroll
        for (int s = 0; s < 4; s++) {
            int idx = tid + s * 256;
            int r = idx >> 4, c4 = idx & 15;
            *(float4*)&Ks[r][c4 * 4] = *(const float4*)(K + kbase + (size_t)r * EMB + c4 * 4);
            *(float4*)&Vs[r][c4 * 4] = *(const float4*)(V + kbase + (size_t)r * EMB + c4 * 4);
        }
        __syncthreads();

        float sreg[4][4];
        #pragma unroll
        for (int i = 0; i < 4; i++)
            #pragma unroll
            for (int j = 0; j < 4; j++) sreg[i][j] = 0.f;

        #pragma unroll
        for (int d4 = 0; d4 < 16; d4++) {
            float qr[4][4], kr[4][4];
            #pragma unroll
            for (int i = 0; i < 4; i++) {
                float4 t = *(float4*)&Qs[ty * 4 + i][d4 * 4];
                qr[i][0] = t.x; qr[i][1] = t.y; qr[i][2] = t.z; qr[i][3] = t.w;
            }
            #pragma unroll
            for (int j = 0; j < 4; j++) {
                float4 t = *(float4*)&Ks[tx * 4 + j][d4 * 4];
                kr[j][0] = t.x; kr[j][1] = t.y; kr[j][2] = t.z; kr[j][3] = t.w;
            }
            #pragma unroll
            for (int i = 0; i < 4; i++)
                #pragma unroll
                for (int j = 0; j < 4; j++)
                    sreg[i][j] += qr[i][0] * kr[j][0] + qr[i][1] * kr[j][1]
                                + qr[i][2] * kr[j][2] + qr[i][3] * kr[j][3];
        }

        bool diag = (jt == it);
        #pragma unroll
        for (int i = 0; i < 4; i++)
            #pragma unroll
            for (int j = 0; j < 4; j++) {
                float sv = sreg[i][j] * scale;
                if (diag && (tx * 4 + j) > (ty * 4 + i)) sv = -CUDART_INF_F;
                sreg[i][j] = sv;
            }

        #pragma unroll
        for (int i = 0; i < 4; i++) {
            float rm = fmaxf(fmaxf(sreg[i][0], sreg[i][1]), fmaxf(sreg[i][2], sreg[i][3]));
            #pragma unroll
            for (int o = 8; o; o >>= 1)
                rm = fmaxf(rm, __shfl_xor_sync(0xffffffffu, rm, o, 16));
            float mn = fmaxf(m[i], rm);
            float alpha = expf(m[i] - mn);
            float psum = 0.f;
            #pragma unroll
            for (int j = 0; j < 4; j++) {
                float p = expf(sreg[i][j] - mn);
                sreg[i][j] = p;
                psum += p;
            }
            #pragma unroll
            for (int o = 8; o; o >>= 1)
                psum += __shfl_xor_sync(0xffffffffu, psum, o, 16);
            l[i] = l[i] * alpha + psum;
            m[i] = mn;
            #pragma unroll
            for (int j = 0; j < 4; j++) acc[i][j] *= alpha;
        }

        #pragma unroll
        for (int i = 0; i < 4; i++)
            #pragma unroll
            for (int j = 0; j < 4; j++)
                Ps[ty * 4 + i][tx * 4 + j] = sreg[i][j];
        __syncthreads();

        #pragma unroll
        for (int k4 = 0; k4 < 16; k4++) {
            float pr[4][4], vr[4][4];
            #pragma unroll
            for (int i = 0; i < 4; i++) {
                float4 t = *(float4*)&Ps[ty * 4 + i][k4 * 4];
                pr[i][0] = t.x; pr[i][1] = t.y; pr[i][2] = t.z; pr[i][3] = t.w;
            }
            #pragma unroll
            for (int s = 0; s < 4; s++) {
                float4 t = *(float4*)&Vs[k4 * 4 + s][tx * 4];
                vr[s][0] = t.x; vr[s][1] = t.y; vr[s][2] = t.z; vr[s][3] = t.w;
            }
            #pragma unroll
            for (int i = 0; i < 4; i++)
                #pragma unroll
                for (int j = 0; j < 4; j++)
                    acc[i][j] += pr[i][0] * vr[0][j] + pr[i][1] * vr[1][j]
                               + pr[i][2] * vr[2][j] + pr[i][3] * vr[3][j];
        }
    }

    #pragma unroll
    for (int i = 0; i < 4; i++) {
        float inv = 1.0f / l[i];
        size_t obase = ((size_t)(bb * TSEQ + it * 64 + ty * 4 + i)) * EMB + h * HEADD + tx * 4;
        float4 o4 = make_float4(tf32r(acc[i][0] * inv), tf32r(acc[i][1] * inv),
                                tf32r(acc[i][2] * inv), tf32r(acc[i][3] * inv));
        *(float4*)(Out + obase) = o4;
    }
}

// ---------------------------------------------------------------------------
// Launch
// ---------------------------------------------------------------------------
extern "C" void kernel_launch(void* const* d_in, const int* in_sizes, int n_in,
                              void* d_out, int out_size)
{
    const float* x      = (const float*)d_in[0];
    const float* ln1_g  = (const float*)d_in[1];
    const float* ln1_b  = (const float*)d_in[2];
    const float* wq     = (const float*)d_in[3];
    const float* wk     = (const float*)d_in[4];
    const float* wv     = (const float*)d_in[5];
    const float* w_proj = (const float*)d_in[6];
    const float* b_proj = (const float*)d_in[7];
    const float* ln2_g  = (const float*)d_in[8];
    const float* ln2_b  = (const float*)d_in[9];
    const float* w1     = (const float*)d_in[10];
    const float* b1     = (const float*)d_in[11];
    const float* w2     = (const float*)d_in[12];
    const float* b2     = (const float*)d_in[13];
    float* out = (float*)d_out;

    float *h, *q, *k, *v, *attn, *out1, *mid;
    float *wqT, *wkT, *wvT, *wpT, *w1T, *w2T;
    cudaGetSymbolAddress((void**)&h,    g_h);
    cudaGetSymbolAddress((void**)&q,    g_q);
    cudaGetSymbolAddress((void**)&k,    g_k);
    cudaGetSymbolAddress((void**)&v,    g_v);
    cudaGetSymbolAddress((void**)&attn, g_attn);
    cudaGetSymbolAddress((void**)&out1, g_out1);
    cudaGetSymbolAddress((void**)&mid,  g_mid);
    cudaGetSymbolAddress((void**)&wqT,  g_wqT);
    cudaGetSymbolAddress((void**)&wkT,  g_wkT);
    cudaGetSymbolAddress((void**)&wvT,  g_wvT);
    cudaGetSymbolAddress((void**)&wpT,  g_wpT);
    cudaGetSymbolAddress((void**)&w1T,  g_w1T);
    cudaGetSymbolAddress((void**)&w2T,  g_w2T);

    cudaFuncSetAttribute(gemm_mma_kernel<false, false>,
                         cudaFuncAttributeMaxDynamicSharedMemorySize, GM_SMEM);
    cudaFuncSetAttribute(gemm_mma_kernel<true, true>,
                         cudaFuncAttributeMaxDynamicSharedMemorySize, GM_SMEM);
    const int attn_smem = 4 * 64 * ATP * (int)sizeof(float);
    cudaFuncSetAttribute(attn_kernel, cudaFuncAttributeMaxDynamicSharedMemorySize, attn_smem);

    // 0. Transpose + tf32-round weights
    dim3 tb(32, 8);
    transpose_round_kernel<<<dim3(EMB / 32,   EMB / 32),   tb>>>(wq,     wqT, EMB,   EMB);
    transpose_round_kernel<<<dim3(EMB / 32,   EMB / 32),   tb>>>(wk,     wkT, EMB,   EMB);
    transpose_round_kernel<<<dim3(EMB / 32,   EMB / 32),   tb>>>(wv,     wvT, EMB,   EMB);
    transpose_round_kernel<<<dim3(EMB / 32,   EMB / 32),   tb>>>(w_proj, wpT, EMB,   EMB);
    transpose_round_kernel<<<dim3(FFDIM / 32, EMB / 32),   tb>>>(w1,     w1T, EMB,   FFDIM);
    transpose_round_kernel<<<dim3(EMB / 32,   FFDIM / 32), tb>>>(w2,     w2T, FFDIM, EMB);

    // 1. LN1
    ln_kernel<<<MROWS, 256>>>(x, ln1_g, ln1_b, h);

    // 2. QKV projections (tf32 mma)
    dim3 gE(EMB / 128, MROWS / 128);   // (8, 64)
    gemm_mma_kernel<false, false><<<gE, 256, GM_SMEM>>>(h, wqT, nullptr, nullptr, q, EMB, EMB);
    gemm_mma_kernel<false, false><<<gE, 256, GM_SMEM>>>(h, wkT, nullptr, nullptr, k, EMB, EMB);
    gemm_mma_kernel<false, false><<<gE, 256, GM_SMEM>>>(h, wvT, nullptr, nullptr, v, EMB, EMB);

    // 3. Causal attention (fp32)
    attn_kernel<<<dim3(TSEQ / 64, NHEAD, BSZ), 256, attn_smem>>>(q, k, v, attn);

    // 4. out1 = x + attn @ w_proj + b_proj
    gemm_mma_kernel<false, false><<<gE, 256, GM_SMEM>>>(attn, wpT, b_proj, x, out1, EMB, EMB);

    // 5. LN2
    ln_kernel<<<MROWS, 256>>>(out1, ln2_g, ln2_b, h);

    // 6. mid = gelu(h @ w1 + b1), tf32-rounded (A of next GEMM)
    dim3 gF(FFDIM / 128, MROWS / 128);  // (32, 64)
    gemm_mma_kernel<true, true><<<gF, 256, GM_SMEM>>>(h, w1T, b1, nullptr, mid, FFDIM, EMB);

    // 7. out = out1 + mid @ w2 + b2
    gemm_mma_kernel<false, false><<<gE, 256, GM_SMEM>>>(mid, w2T, b2, out1, out, EMB, FFDIM);
}

// round 4
// speedup vs baseline: 3.6151x; 1.4258x over previous
#include <cuda_runtime.h>
#include <math_constants.h>
#include <math.h>
#include <stdint.h>

#define BSZ   8
#define TSEQ  1024
#define EMB   1024
#define NHEAD 16
#define HEADD 64
#define MROWS (BSZ * TSEQ)   // 8192
#define FFDIM 4096

// ---------------------------------------------------------------------------
// Scratch
// ---------------------------------------------------------------------------
__device__ float g_h   [(size_t)MROWS * EMB];
__device__ float g_q   [(size_t)MROWS * EMB];
__device__ float g_k   [(size_t)MROWS * EMB];
__device__ float g_v   [(size_t)MROWS * EMB];
__device__ float g_attn[(size_t)MROWS * EMB];
__device__ float g_out1[(size_t)MROWS * EMB];
__device__ float g_mid [(size_t)MROWS * FFDIM];
__device__ float g_wqT[(size_t)EMB * EMB];
__device__ float g_wkT[(size_t)EMB * EMB];
__device__ float g_wvT[(size_t)EMB * EMB];
__device__ float g_wpT[(size_t)EMB * EMB];
__device__ float g_w1T[(size_t)EMB * FFDIM];
__device__ float g_w2T[(size_t)FFDIM * EMB];

// ---------------------------------------------------------------------------
// Helpers
// ---------------------------------------------------------------------------
__device__ __forceinline__ float tf32r(float x) {
    uint32_t u;
    asm("cvt.rna.tf32.f32 %0, %1;" : "=r"(u) : "f"(x));
    return __uint_as_float(u);
}

__device__ __forceinline__ uint32_t smem_u32(const void* p) {
    uint32_t a;
    asm("{ .reg .u64 t; cvta.to.shared.u64 t, %1; cvt.u32.u64 %0, t; }" : "=r"(a) : "l"(p));
    return a;
}

__device__ __forceinline__ void cp16(uint32_t dst, const void* src) {
    asm volatile("cp.async.cg.shared.global [%0], [%1], 16;" :: "r"(dst), "l"(src) : "memory");
}
__device__ __forceinline__ void cp_commit() {
    asm volatile("cp.async.commit_group;" ::: "memory");
}
template<int N>
__device__ __forceinline__ void cp_wait() {
    asm volatile("cp.async.wait_group %0;" :: "n"(N) : "memory");
}

__device__ __forceinline__ void mma_tf32(float& c0, float& c1, float& c2, float& c3,
                                         uint32_t a0, uint32_t a1, uint32_t a2, uint32_t a3,
                                         uint32_t b0, uint32_t b1) {
    asm volatile(
        "mma.sync.aligned.m16n8k8.row.col.f32.tf32.tf32.f32 "
        "{%0,%1,%2,%3}, {%4,%5,%6,%7}, {%8,%9}, {%0,%1,%2,%3};"
        : "+f"(c0), "+f"(c1), "+f"(c2), "+f"(c3)
        : "r"(a0), "r"(a1), "r"(a2), "r"(a3), "r"(b0), "r"(b1));
}

// ---------------------------------------------------------------------------
// Transpose + tf32-round weights: in[K][N] -> out[N][K]
// ---------------------------------------------------------------------------
__global__ __launch_bounds__(256)
void transpose_round_kernel(const float* __restrict__ in, float* __restrict__ out,
                            int K, int N)
{
    __shared__ float t[32][33];
    int n0 = blockIdx.x * 32, k0 = blockIdx.y * 32;
    int tx = threadIdx.x, ty = threadIdx.y;
    #pragma unroll
    for (int i = 0; i < 32; i += 8)
        t[ty + i][tx] = in[(size_t)(k0 + ty + i) * N + n0 + tx];
    __syncthreads();
    #pragma unroll
    for (int i = 0; i < 32; i += 8)
        out[(size_t)(n0 + ty + i) * K + k0 + tx] = tf32r(t[tx][ty + i]);
}

// ---------------------------------------------------------------------------
// LayerNorm (tf32-rounded output)
// ---------------------------------------------------------------------------
__global__ __launch_bounds__(256)
void ln_kernel(const float* __restrict__ x, const float* __restrict__ g,
               const float* __restrict__ b, float* __restrict__ out)
{
    int row = blockIdx.x;
    int t   = threadIdx.x;
    const float4* xr = (const float4*)(x + (size_t)row * EMB);
    float4 v = xr[t];
    float s  = v.x + v.y + v.z + v.w;
    float ss = v.x * v.x + v.y * v.y + v.z * v.z + v.w * v.w;
    #pragma unroll
    for (int o = 16; o; o >>= 1) {
        s  += __shfl_xor_sync(0xffffffffu, s,  o);
        ss += __shfl_xor_sync(0xffffffffu, ss, o);
    }
    __shared__ float rs_[8], rss_[8];
    __shared__ float mu_s, rstd_s;
    int warp = t >> 5, lane = t & 31;
    if (lane == 0) { rs_[warp] = s; rss_[warp] = ss; }
    __syncthreads();
    if (t == 0) {
        float S = 0.f, SS = 0.f;
        #pragma unroll
        for (int i = 0; i < 8; i++) { S += rs_[i]; SS += rss_[i]; }
        float mu  = S * (1.0f / EMB);
        float var = SS * (1.0f / EMB) - mu * mu;
        mu_s = mu;
        rstd_s = rsqrtf(var + 1e-5f);
    }
    __syncthreads();
    float mu = mu_s, r = rstd_s;
    float4 gv = ((const float4*)g)[t];
    float4 bv = ((const float4*)b)[t];
    float4 o4;
    o4.x = tf32r((v.x - mu) * r * gv.x + bv.x);
    o4.y = tf32r((v.y - mu) * r * gv.y + bv.y);
    o4.z = tf32r((v.z - mu) * r * gv.z + bv.z);
    o4.w = tf32r((v.w - mu) * r * gv.w + bv.w);
    ((float4*)(out + (size_t)row * EMB))[t] = o4;
}

// ---------------------------------------------------------------------------
// tf32 mma.sync GEMM (unchanged from R2)
// ---------------------------------------------------------------------------
#define GM_STRIDE 36
#define GM_TILE_BYTES (128 * GM_STRIDE * 4)
#define GM_BUF_BYTES  (2 * GM_TILE_BYTES)
#define GM_SMEM (2 * GM_BUF_BYTES)

template<bool GELU, bool ROUND>
__global__ __launch_bounds__(256)
void gemm_mma_kernel(const float* __restrict__ A, const float* __restrict__ Bt,
                     const float* __restrict__ bias, const float* __restrict__ res,
                     float* __restrict__ C, int N_, int K_)
{
    extern __shared__ char smem[];
    const uint32_t sb = smem_u32(smem);
    int tid  = threadIdx.x;
    int lane = tid & 31, warp = tid >> 5;
    int wm = warp >> 2;
    int wn = warp & 3;
    int rowBase = blockIdx.y * 128;
    int colBase = blockIdx.x * 128;

    const int C_CHUNKS = K_ >> 5;

    auto load_chunk = [&](int c, int b) {
        int k0 = c << 5;
        uint32_t aBase = sb + b * GM_BUF_BYTES;
        uint32_t bBase = aBase + GM_TILE_BYTES;
        #pragma unroll
        for (int s = 0; s < 4; s++) {
            int idx = tid + s * 256;
            int r = idx >> 3, ch = idx & 7;
            cp16(aBase + (uint32_t)(r * GM_STRIDE * 4 + ch * 16),
                 A + (size_t)(rowBase + r) * K_ + k0 + ch * 4);
        }
        #pragma unroll
        for (int s = 0; s < 4; s++) {
            int idx = tid + s * 256;
            int r = idx >> 3, ch = idx & 7;
            cp16(bBase + (uint32_t)(r * GM_STRIDE * 4 + ch * 16),
                 Bt + (size_t)(colBase + r) * K_ + k0 + ch * 4);
        }
        cp_commit();
    };

    float acc[4][4][4];
    #pragma unroll
    for (int i = 0; i < 4; i++)
        #pragma unroll
        for (int j = 0; j < 4; j++)
            #pragma unroll
            for (int r = 0; r < 4; r++) acc[i][j][r] = 0.f;

    load_chunk(0, 0);

    int lq = lane >> 2;
    int lr = lane & 3;

    for (int c = 0; c < C_CHUNKS; c++) {
        int b = c & 1;
        if (c + 1 < C_CHUNKS) {
            load_chunk(c + 1, 1 - b);
            cp_wait<1>();
        } else {
            cp_wait<0>();
        }
        __syncthreads();

        const float* As = (const float*)(smem + b * GM_BUF_BYTES);
        const float* Bs = (const float*)(smem + b * GM_BUF_BYTES + GM_TILE_BYTES);

        #pragma unroll
        for (int ks = 0; ks < 4; ks++) {
            int kk = ks * 8;
            uint32_t a[4][4];
            #pragma unroll
            for (int mt = 0; mt < 4; mt++) {
                int r0 = wm * 64 + mt * 16 + lq;
                a[mt][0] = __float_as_uint(As[r0 * GM_STRIDE + kk + lr]);
                a[mt][1] = __float_as_uint(As[(r0 + 8) * GM_STRIDE + kk + lr]);
                a[mt][2] = __float_as_uint(As[r0 * GM_STRIDE + kk + lr + 4]);
                a[mt][3] = __float_as_uint(As[(r0 + 8) * GM_STRIDE + kk + lr + 4]);
            }
            uint32_t bf[4][2];
            #pragma unroll
            for (int nt = 0; nt < 4; nt++) {
                int n = wn * 32 + nt * 8 + lq;
                bf[nt][0] = __float_as_uint(Bs[n * GM_STRIDE + kk + lr]);
                bf[nt][1] = __float_as_uint(Bs[n * GM_STRIDE + kk + lr + 4]);
            }
            #pragma unroll
            for (int mt = 0; mt < 4; mt++)
                #pragma unroll
                for (int nt = 0; nt < 4; nt++)
                    mma_tf32(acc[mt][nt][0], acc[mt][nt][1], acc[mt][nt][2], acc[mt][nt][3],
                             a[mt][0], a[mt][1], a[mt][2], a[mt][3],
                             bf[nt][0], bf[nt][1]);
        }
        __syncthreads();
    }

    #pragma unroll
    for (int mt = 0; mt < 4; mt++) {
        int row0 = rowBase + wm * 64 + mt * 16 + lq;
        #pragma unroll
        for (int nt = 0; nt < 4; nt++) {
            int col = colBase + wn * 32 + nt * 8 + lr * 2;
            float2 p0 = make_float2(acc[mt][nt][0], acc[mt][nt][1]);
            float2 p1 = make_float2(acc[mt][nt][2], acc[mt][nt][3]);
            if (bias) {
                float2 bv = *(const float2*)(bias + col);
                p0.x += bv.x; p0.y += bv.y;
                p1.x += bv.x; p1.y += bv.y;
            }
            if (res) {
                float2 r0 = *(const float2*)(res + (size_t)row0 * N_ + col);
                float2 r1 = *(const float2*)(res + (size_t)(row0 + 8) * N_ + col);
                p0.x += r0.x; p0.y += r0.y;
                p1.x += r1.x; p1.y += r1.y;
            }
            if (GELU) {
                p0.x = 0.5f * p0.x * (1.0f + erff(p0.x * 0.70710678118654752f));
                p0.y = 0.5f * p0.y * (1.0f + erff(p0.y * 0.70710678118654752f));
                p1.x = 0.5f * p1.x * (1.0f + erff(p1.x * 0.70710678118654752f));
                p1.y = 0.5f * p1.y * (1.0f + erff(p1.y * 0.70710678118654752f));
            }
            if (ROUND) {
                p0.x = tf32r(p0.x); p0.y = tf32r(p0.y);
                p1.x = tf32r(p1.x); p1.y = tf32r(p1.y);
            }
            *(float2*)(C + (size_t)row0 * N_ + col) = p0;
            *(float2*)(C + (size_t)(row0 + 8) * N_ + col) = p1;
        }
    }
}

// ---------------------------------------------------------------------------
// Flash attention via tf32 mma.sync.
// CTA: 64 Q rows x one (b,h). 4 warps, 16-row warp tiles. KV blocks of 64.
// smem strides: A-operands (Q,P) 68 floats; B-operand V 72; K 68.
// ---------------------------------------------------------------------------
#define AQS 68
#define AVS 72
#define AT_SMEM ((3 * 64 * AQS + 64 * AVS) * 4)   // 70656 B

__global__ __launch_bounds__(128)
void attn_mma_kernel(const float* __restrict__ Qp, const float* __restrict__ Kp,
                     const float* __restrict__ Vp, float* __restrict__ Out)
{
    extern __shared__ float sm[];
    float* Qs = sm;                       // [64][68]
    float* Ks = sm + 64 * AQS;            // [64][68]  (kv row, d col)
    float* Vs = sm + 2 * 64 * AQS;        // [64][72]  (kv row, d col)
    float* Ps = sm + 2 * 64 * AQS + 64 * AVS;  // [64][68]

    int qb = blockIdx.x, h = blockIdx.y, bb = blockIdx.z;
    int tid = threadIdx.x;
    int lane = tid & 31, warp = tid >> 5;
    int lq = lane >> 2, lr = lane & 3;

    // Load Q tile [64][64]
    size_t qbase = ((size_t)(bb * TSEQ + qb * 64)) * EMB + h * HEADD;
    #pragma unroll
    for (int s = 0; s < 8; s++) {
        int idx = tid + s * 128;
        int r = idx >> 4, c4 = idx & 15;
        *(float4*)(Qs + r * AQS + c4 * 4) =
            *(const float4*)(Qp + qbase + (size_t)r * EMB + c4 * 4);
    }

    float m0 = -CUDART_INF_F, m1 = -CUDART_INF_F;
    float l0 = 0.f, l1 = 0.f;
    float o[8][4];
    #pragma unroll
    for (int nt = 0; nt < 8; nt++)
        #pragma unroll
        for (int r = 0; r < 4; r++) o[nt][r] = 0.f;

    const float* qrow = Qs + warp * 16 * AQS;
    float* prow = Ps + warp * 16 * AQS;

    for (int jt = 0; jt <= qb; jt++) {
        __syncthreads();   // prior K/V reads done (also orders Q store->read on jt=0)
        size_t kbase = ((size_t)(bb * TSEQ + jt * 64)) * EMB + h * HEADD;
        #pragma unroll
        for (int s = 0; s < 8; s++) {
            int idx = tid + s * 128;
            int r = idx >> 4, c4 = idx & 15;
            *(float4*)(Ks + r * AQS + c4 * 4) =
                *(const float4*)(Kp + kbase + (size_t)r * EMB + c4 * 4);
            *(float4*)(Vs + r * AVS + c4 * 4) =
                *(const float4*)(Vp + kbase + (size_t)r * EMB + c4 * 4);
        }
        __syncthreads();

        // S = Q K^T : 8 n-tiles x 8 k-steps of m16n8k8
        float s[8][4];
        #pragma unroll
        for (int nt = 0; nt < 8; nt++)
            #pragma unroll
            for (int r = 0; r < 4; r++) s[nt][r] = 0.f;

        #pragma unroll
        for (int ks = 0; ks < 8; ks++) {
            int k0 = ks * 8;
            uint32_t a0 = __float_as_uint(qrow[lq * AQS + k0 + lr]);
            uint32_t a1 = __float_as_uint(qrow[(lq + 8) * AQS + k0 + lr]);
            uint32_t a2 = __float_as_uint(qrow[lq * AQS + k0 + lr + 4]);
            uint32_t a3 = __float_as_uint(qrow[(lq + 8) * AQS + k0 + lr + 4]);
            #pragma unroll
            for (int nt = 0; nt < 8; nt++) {
                uint32_t b0 = __float_as_uint(Ks[(nt * 8 + lq) * AQS + k0 + lr]);
                uint32_t b1 = __float_as_uint(Ks[(nt * 8 + lq) * AQS + k0 + lr + 4]);
                mma_tf32(s[nt][0], s[nt][1], s[nt][2], s[nt][3], a0, a1, a2, a3, b0, b1);
            }
        }

        // scale + causal mask (diagonal block only)
        const float scale = 0.125f;
        bool diag = (jt == qb);
        int row0 = warp * 16 + lq;
        #pragma unroll
        for (int nt = 0; nt < 8; nt++) {
            int col = nt * 8 + 2 * lr;
            s[nt][0] *= scale; s[nt][1] *= scale;
            s[nt][2] *= scale; s[nt][3] *= scale;
            if (diag) {
                if (col     > row0)     s[nt][0] = -CUDART_INF_F;
                if (col + 1 > row0)     s[nt][1] = -CUDART_INF_F;
                if (col     > row0 + 8) s[nt][2] = -CUDART_INF_F;
                if (col + 1 > row0 + 8) s[nt][3] = -CUDART_INF_F;
            }
        }

        // online softmax, row lq
        {
            float rm = -CUDART_INF_F;
            #pragma unroll
            for (int nt = 0; nt < 8; nt++) rm = fmaxf(rm, fmaxf(s[nt][0], s[nt][1]));
            rm = fmaxf(rm, __shfl_xor_sync(0xffffffffu, rm, 1));
            rm = fmaxf(rm, __shfl_xor_sync(0xffffffffu, rm, 2));
            float mn = fmaxf(m0, rm);
            float alpha = __expf(m0 - mn);
            float ps = 0.f;
            #pragma unroll
            for (int nt = 0; nt < 8; nt++) {
                s[nt][0] = __expf(s[nt][0] - mn);
                s[nt][1] = __expf(s[nt][1] - mn);
                ps += s[nt][0] + s[nt][1];
            }
            ps += __shfl_xor_sync(0xffffffffu, ps, 1);
            ps += __shfl_xor_sync(0xffffffffu, ps, 2);
            l0 = l0 * alpha + ps;
            m0 = mn;
            #pragma unroll
            for (int nt = 0; nt < 8; nt++) { o[nt][0] *= alpha; o[nt][1] *= alpha; }
        }
        // row lq + 8
        {
            float rm = -CUDART_INF_F;
            #pragma unroll
            for (int nt = 0; nt < 8; nt++) rm = fmaxf(rm, fmaxf(s[nt][2], s[nt][3]));
            rm = fmaxf(rm, __shfl_xor_sync(0xffffffffu, rm, 1));
            rm = fmaxf(rm, __shfl_xor_sync(0xffffffffu, rm, 2));
            float mn = fmaxf(m1, rm);
            float alpha = __expf(m1 - mn);
            float ps = 0.f;
            #pragma unroll
            for (int nt = 0; nt < 8; nt++) {
                s[nt][2] = __expf(s[nt][2] - mn);
                s[nt][3] = __expf(s[nt][3] - mn);
                ps += s[nt][2] + s[nt][3];
            }
            ps += __shfl_xor_sync(0xffffffffu, ps, 1);
            ps += __shfl_xor_sync(0xffffffffu, ps, 2);
            l1 = l1 * alpha + ps;
            m1 = mn;
            #pragma unroll
            for (int nt = 0; nt < 8; nt++) { o[nt][2] *= alpha; o[nt][3] *= alpha; }
        }

        // store P (tf32-rounded) to smem; warp-private region
        #pragma unroll
        for (int nt = 0; nt < 8; nt++) {
            *(float2*)(prow + lq * AQS + nt * 8 + 2 * lr) =
                make_float2(tf32r(s[nt][0]), tf32r(s[nt][1]));
            *(float2*)(prow + (lq + 8) * AQS + nt * 8 + 2 * lr) =
                make_float2(tf32r(s[nt][2]), tf32r(s[nt][3]));
        }
        __syncwarp();

        // O += P V
        #pragma unroll
        for (int ks = 0; ks < 8; ks++) {
            int k0 = ks * 8;
            uint32_t a0 = __float_as_uint(prow[lq * AQS + k0 + lr]);
            uint32_t a1 = __float_as_uint(prow[(lq + 8) * AQS + k0 + lr]);
            uint32_t a2 = __float_as_uint(prow[lq * AQS + k0 + lr + 4]);
            uint32_t a3 = __float_as_uint(prow[(lq + 8) * AQS + k0 + lr + 4]);
            #pragma unroll
            for (int nt = 0; nt < 8; nt++) {
                uint32_t b0 = __float_as_uint(Vs[(k0 + lr) * AVS + nt * 8 + lq]);
                uint32_t b1 = __float_as_uint(Vs[(k0 + lr + 4) * AVS + nt * 8 + lq]);
                mma_tf32(o[nt][0], o[nt][1], o[nt][2], o[nt][3], a0, a1, a2, a3, b0, b1);
            }
        }
        __syncwarp();
    }

    // epilogue: normalize, round, store
    float inv0 = 1.0f / l0, inv1 = 1.0f / l1;
    size_t r0 = (size_t)(bb * TSEQ + qb * 64 + warp * 16 + lq);
    size_t r1 = r0 + 8;
    #pragma unroll
    for (int nt = 0; nt < 8; nt++) {
        int col = h * HEADD + nt * 8 + 2 * lr;
        *(float2*)(Out + r0 * EMB + col) =
            make_float2(tf32r(o[nt][0] * inv0), tf32r(o[nt][1] * inv0));
        *(float2*)(Out + r1 * EMB + col) =
            make_float2(tf32r(o[nt][2] * inv1), tf32r(o[nt][3] * inv1));
    }
}

// ---------------------------------------------------------------------------
// Launch
// ---------------------------------------------------------------------------
extern "C" void kernel_launch(void* const* d_in, const int* in_sizes, int n_in,
                              void* d_out, int out_size)
{
    const float* x      = (const float*)d_in[0];
    const float* ln1_g  = (const float*)d_in[1];
    const float* ln1_b  = (const float*)d_in[2];
    const float* wq     = (const float*)d_in[3];
    const float* wk     = (const float*)d_in[4];
    const float* wv     = (const float*)d_in[5];
    const float* w_proj = (const float*)d_in[6];
    const float* b_proj = (const float*)d_in[7];
    const float* ln2_g  = (const float*)d_in[8];
    const float* ln2_b  = (const float*)d_in[9];
    const float* w1     = (const float*)d_in[10];
    const float* b1     = (const float*)d_in[11];
    const float* w2     = (const float*)d_in[12];
    const float* b2     = (const float*)d_in[13];
    float* out = (float*)d_out;

    float *h, *q, *k, *v, *attn, *out1, *mid;
    float *wqT, *wkT, *wvT, *wpT, *w1T, *w2T;
    cudaGetSymbolAddress((void**)&h,    g_h);
    cudaGetSymbolAddress((void**)&q,    g_q);
    cudaGetSymbolAddress((void**)&k,    g_k);
    cudaGetSymbolAddress((void**)&v,    g_v);
    cudaGetSymbolAddress((void**)&attn, g_attn);
    cudaGetSymbolAddress((void**)&out1, g_out1);
    cudaGetSymbolAddress((void**)&mid,  g_mid);
    cudaGetSymbolAddress((void**)&wqT,  g_wqT);
    cudaGetSymbolAddress((void**)&wkT,  g_wkT);
    cudaGetSymbolAddress((void**)&wvT,  g_wvT);
    cudaGetSymbolAddress((void**)&wpT,  g_wpT);
    cudaGetSymbolAddress((void**)&w1T,  g_w1T);
    cudaGetSymbolAddress((void**)&w2T,  g_w2T);

    cudaFuncSetAttribute(gemm_mma_kernel<false, false>,
                         cudaFuncAttributeMaxDynamicSharedMemorySize, GM_SMEM);
    cudaFuncSetAttribute(gemm_mma_kernel<false, true>,
                         cudaFuncAttributeMaxDynamicSharedMemorySize, GM_SMEM);
    cudaFuncSetAttribute(gemm_mma_kernel<true, true>,
                         cudaFuncAttributeMaxDynamicSharedMemorySize, GM_SMEM);
    cudaFuncSetAttribute(attn_mma_kernel,
                         cudaFuncAttributeMaxDynamicSharedMemorySize, AT_SMEM);

    // 0. Transpose + tf32-round weights
    dim3 tb(32, 8);
    transpose_round_kernel<<<dim3(EMB / 32,   EMB / 32),   tb>>>(wq,     wqT, EMB,   EMB);
    transpose_round_kernel<<<dim3(EMB / 32,   EMB / 32),   tb>>>(wk,     wkT, EMB,   EMB);
    transpose_round_kernel<<<dim3(EMB / 32,   EMB / 32),   tb>>>(wv,     wvT, EMB,   EMB);
    transpose_round_kernel<<<dim3(EMB / 32,   EMB / 32),   tb>>>(w_proj, wpT, EMB,   EMB);
    transpose_round_kernel<<<dim3(FFDIM / 32, EMB / 32),   tb>>>(w1,     w1T, EMB,   FFDIM);
    transpose_round_kernel<<<dim3(EMB / 32,   FFDIM / 32), tb>>>(w2,     w2T, FFDIM, EMB);

    // 1. LN1
    ln_kernel<<<MROWS, 256>>>(x, ln1_g, ln1_b, h);

    // 2. QKV projections (tf32 mma; outputs rounded to tf32 for attention)
    dim3 gE(EMB / 128, MROWS / 128);
    gemm_mma_kernel<false, true><<<gE, 256, GM_SMEM>>>(h, wqT, nullptr, nullptr, q, EMB, EMB);
    gemm_mma_kernel<false, true><<<gE, 256, GM_SMEM>>>(h, wkT, nullptr, nullptr, k, EMB, EMB);
    gemm_mma_kernel<false, true><<<gE, 256, GM_SMEM>>>(h, wvT, nullptr, nullptr, v, EMB, EMB);

    // 3. Causal flash attention (tf32 mma)
    attn_mma_kernel<<<dim3(TSEQ / 64, NHEAD, BSZ), 128, AT_SMEM>>>(q, k, v, attn);

    // 4. out1 = x + attn @ w_proj + b_proj
    gemm_mma_kernel<false, false><<<gE, 256, GM_SMEM>>>(attn, wpT, b_proj, x, out1, EMB, EMB);

    // 5. LN2
    ln_kernel<<<MROWS, 256>>>(out1, ln2_g, ln2_b, h);

    // 6. mid = gelu(h @ w1 + b1), tf32-rounded
    dim3 gF(FFDIM / 128, MROWS / 128);
    gemm_mma_kernel<true, true><<<gF, 256, GM_SMEM>>>(h, w1T, b1, nullptr, mid, FFDIM, EMB);

    // 7. out = out1 + mid @ w2 + b2
    gemm_mma_kernel<false, false><<<gE, 256, GM_SMEM>>>(mid, w2T, b2, out1, out, EMB, FFDIM);
}

// round 5
// speedup vs baseline: 5.0250x; 1.3900x over previous
#include <cuda_runtime.h>
#include <cuda_fp16.h>
#include <math_constants.h>
#include <math.h>
#include <stdint.h>

#define BSZ   8
#define TSEQ  1024
#define EMB   1024
#define NHEAD 16
#define HEADD 64
#define MROWS (BSZ * TSEQ)   // 8192
#define FFDIM 4096

// ---------------------------------------------------------------------------
// Scratch
// ---------------------------------------------------------------------------
__device__ __half g_h   [(size_t)MROWS * EMB];
__device__ __half g_q   [(size_t)MROWS * EMB];
__device__ __half g_k   [(size_t)MROWS * EMB];
__device__ __half g_v   [(size_t)MROWS * EMB];
__device__ __half g_attn[(size_t)MROWS * EMB];
__device__ float  g_out1[(size_t)MROWS * EMB];
__device__ __half g_mid [(size_t)MROWS * FFDIM];
__device__ __half g_wqT[(size_t)EMB * EMB];
__device__ __half g_wkT[(size_t)EMB * EMB];
__device__ __half g_wvT[(size_t)EMB * EMB];
__device__ __half g_wpT[(size_t)EMB * EMB];
__device__ __half g_w1T[(size_t)EMB * FFDIM];
__device__ __half g_w2T[(size_t)FFDIM * EMB];

// ---------------------------------------------------------------------------
// Helpers
// ---------------------------------------------------------------------------
__device__ __forceinline__ uint32_t smem_u32(const void* p) {
    uint32_t a;
    asm("{ .reg .u64 t; cvta.to.shared.u64 t, %1; cvt.u32.u64 %0, t; }" : "=r"(a) : "l"(p));
    return a;
}

__device__ __forceinline__ void cp16(uint32_t dst, const void* src) {
    asm volatile("cp.async.cg.shared.global [%0], [%1], 16;" :: "r"(dst), "l"(src) : "memory");
}
__device__ __forceinline__ void cp_commit() {
    asm volatile("cp.async.commit_group;" ::: "memory");
}
template<int N>
__device__ __forceinline__ void cp_wait() {
    asm volatile("cp.async.wait_group %0;" :: "n"(N) : "memory");
}

__device__ __forceinline__ void ldsm_x4(uint32_t& r0, uint32_t& r1, uint32_t& r2, uint32_t& r3,
                                        uint32_t addr) {
    asm volatile("ldmatrix.sync.aligned.m8n8.x4.shared.b16 {%0,%1,%2,%3}, [%4];"
                 : "=r"(r0), "=r"(r1), "=r"(r2), "=r"(r3) : "r"(addr));
}
__device__ __forceinline__ void ldsm_x4t(uint32_t& r0, uint32_t& r1, uint32_t& r2, uint32_t& r3,
                                         uint32_t addr) {
    asm volatile("ldmatrix.sync.aligned.m8n8.x4.trans.shared.b16 {%0,%1,%2,%3}, [%4];"
                 : "=r"(r0), "=r"(r1), "=r"(r2), "=r"(r3) : "r"(addr));
}

__device__ __forceinline__ void mma_f16(float& c0, float& c1, float& c2, float& c3,
                                        uint32_t a0, uint32_t a1, uint32_t a2, uint32_t a3,
                                        uint32_t b0, uint32_t b1) {
    asm volatile(
        "mma.sync.aligned.m16n8k16.row.col.f32.f16.f16.f32 "
        "{%0,%1,%2,%3}, {%4,%5,%6,%7}, {%8,%9}, {%0,%1,%2,%3};"
        : "+f"(c0), "+f"(c1), "+f"(c2), "+f"(c3)
        : "r"(a0), "r"(a1), "r"(a2), "r"(a3), "r"(b0), "r"(b1));
}

// ---------------------------------------------------------------------------
// Transpose + fp16 weights: in[K][N] float -> out[N][K] half
// ---------------------------------------------------------------------------
__global__ __launch_bounds__(256)
void transpose_h_kernel(const float* __restrict__ in, __half* __restrict__ out,
                        int K, int N)
{
    __shared__ float t[32][33];
    int n0 = blockIdx.x * 32, k0 = blockIdx.y * 32;
    int tx = threadIdx.x, ty = threadIdx.y;
    #pragma unroll
    for (int i = 0; i < 32; i += 8)
        t[ty + i][tx] = in[(size_t)(k0 + ty + i) * N + n0 + tx];
    __syncthreads();
    #pragma unroll
    for (int i = 0; i < 32; i += 8)
        out[(size_t)(n0 + ty + i) * K + k0 + tx] = __float2half_rn(t[tx][ty + i]);
}

// ---------------------------------------------------------------------------
// LayerNorm: float in -> half out
// ---------------------------------------------------------------------------
__global__ __launch_bounds__(256)
void ln_kernel(const float* __restrict__ x, const float* __restrict__ g,
               const float* __restrict__ b, __half* __restrict__ out)
{
    int row = blockIdx.x;
    int t   = threadIdx.x;
    const float4* xr = (const float4*)(x + (size_t)row * EMB);
    float4 v = xr[t];
    float s  = v.x + v.y + v.z + v.w;
    float ss = v.x * v.x + v.y * v.y + v.z * v.z + v.w * v.w;
    #pragma unroll
    for (int o = 16; o; o >>= 1) {
        s  += __shfl_xor_sync(0xffffffffu, s,  o);
        ss += __shfl_xor_sync(0xffffffffu, ss, o);
    }
    __shared__ float rs_[8], rss_[8];
    __shared__ float mu_s, rstd_s;
    int warp = t >> 5, lane = t & 31;
    if (lane == 0) { rs_[warp] = s; rss_[warp] = ss; }
    __syncthreads();
    if (t == 0) {
        float S = 0.f, SS = 0.f;
        #pragma unroll
        for (int i = 0; i < 8; i++) { S += rs_[i]; SS += rss_[i]; }
        float mu  = S * (1.0f / EMB);
        float var = SS * (1.0f / EMB) - mu * mu;
        mu_s = mu;
        rstd_s = rsqrtf(var + 1e-5f);
    }
    __syncthreads();
    float mu = mu_s, r = rstd_s;
    float4 gv = ((const float4*)g)[t];
    float4 bv = ((const float4*)b)[t];
    __half2* orow = (__half2*)(out + (size_t)row * EMB);
    orow[2 * t]     = __floats2half2_rn((v.x - mu) * r * gv.x + bv.x,
                                        (v.y - mu) * r * gv.y + bv.y);
    orow[2 * t + 1] = __floats2half2_rn((v.z - mu) * r * gv.z + bv.z,
                                        (v.w - mu) * r * gv.w + bv.w);
}

// ---------------------------------------------------------------------------
// fp16 mma GEMM: C[M,N] = A[M,K] @ Bt[N,K]^T (+bias)(+res)(GELU)
// CTA 128x128, BK=32, 8 warps (warp 64x32), 3-stage cp.async, ldmatrix frags.
// smem rows stride 40 halves (80B) -> conflict-free ldmatrix.
// ---------------------------------------------------------------------------
#define GH_STRIDE 40
#define GH_TILE  (128 * GH_STRIDE * 2)   // 10240 B
#define GH_STAGE (2 * GH_TILE)           // 20480 B
#define GH_SMEM  (3 * GH_STAGE)          // 61440 B

template<bool GELU, bool HALF_OUT>
__global__ __launch_bounds__(256, 1)
void gemm_h_kernel(const __half* __restrict__ A, const __half* __restrict__ Bt,
                   const float* __restrict__ bias, const float* __restrict__ res,
                   void* __restrict__ Cv, int N_, int K_)
{
    extern __shared__ char smem[];
    const uint32_t sb = smem_u32(smem);
    int tid  = threadIdx.x;
    int lane = tid & 31, warp = tid >> 5;
    int wm = warp >> 2;   // 0..1
    int wn = warp & 3;    // 0..3
    int rowBase = blockIdx.y * 128;
    int colBase = blockIdx.x * 128;
    const int C_CHUNKS = K_ >> 5;

    auto load_chunk = [&](int c, int st) {
        int k0 = c << 5;
        uint32_t aB = sb + st * GH_STAGE;
        uint32_t bB = aB + GH_TILE;
        #pragma unroll
        for (int s = 0; s < 2; s++) {
            int idx = tid + s * 256;            // 512 chunks of 8 halves
            int r = idx >> 2, ch = idx & 3;
            cp16(aB + (uint32_t)(r * GH_STRIDE + ch * 8) * 2,
                 A + (size_t)(rowBase + r) * K_ + k0 + ch * 8);
        }
        #pragma unroll
        for (int s = 0; s < 2; s++) {
            int idx = tid + s * 256;
            int r = idx >> 2, ch = idx & 3;
            cp16(bB + (uint32_t)(r * GH_STRIDE + ch * 8) * 2,
                 Bt + (size_t)(colBase + r) * K_ + k0 + ch * 8);
        }
        cp_commit();
    };

    float acc[4][4][4];
    #pragma unroll
    for (int i = 0; i < 4; i++)
        #pragma unroll
        for (int j = 0; j < 4; j++)
            #pragma unroll
            for (int r = 0; r < 4; r++) acc[i][j][r] = 0.f;

    load_chunk(0, 0);
    load_chunk(1, 1);

    for (int c = 0; c < C_CHUNKS; c++) {
        if (c + 2 < C_CHUNKS) load_chunk(c + 2, (c + 2) % 3);
        else cp_commit();
        cp_wait<2>();
        __syncthreads();

        int st = c % 3;
        uint32_t aBase = sb + st * GH_STAGE;
        uint32_t bBase = aBase + GH_TILE;

        #pragma unroll
        for (int ks = 0; ks < 2; ks++) {
            int k0 = ks * 16;
            uint32_t a[4][4];
            #pragma unroll
            for (int mt = 0; mt < 4; mt++) {
                uint32_t addr = aBase +
                    (uint32_t)((wm * 64 + mt * 16 + (lane & 15)) * GH_STRIDE
                               + k0 + ((lane >> 4) << 3)) * 2;
                ldsm_x4(a[mt][0], a[mt][1], a[mt][2], a[mt][3], addr);
            }
            uint32_t bf[4][2];
            #pragma unroll
            for (int np = 0; np < 2; np++) {
                int n = wn * 32 + np * 16 + ((lane >> 4) << 3) + (lane & 7);
                int koff = ((lane >> 3) & 1) << 3;
                uint32_t addr = bBase + (uint32_t)(n * GH_STRIDE + k0 + koff) * 2;
                ldsm_x4(bf[np * 2][0], bf[np * 2][1], bf[np * 2 + 1][0], bf[np * 2 + 1][1], addr);
            }
            #pragma unroll
            for (int mt = 0; mt < 4; mt++)
                #pragma unroll
                for (int nt = 0; nt < 4; nt++)
                    mma_f16(acc[mt][nt][0], acc[mt][nt][1], acc[mt][nt][2], acc[mt][nt][3],
                            a[mt][0], a[mt][1], a[mt][2], a[mt][3],
                            bf[nt][0], bf[nt][1]);
        }
        __syncthreads();
    }

    // Epilogue
    int lq = lane >> 2, lr = lane & 3;
    __half* Ch = (__half*)Cv;
    float*  Cf = (float*)Cv;
    #pragma unroll
    for (int mt = 0; mt < 4; mt++) {
        int row0 = rowBase + wm * 64 + mt * 16 + lq;
        #pragma unroll
        for (int nt = 0; nt < 4; nt++) {
            int col = colBase + wn * 32 + nt * 8 + lr * 2;
            float2 p0 = make_float2(acc[mt][nt][0], acc[mt][nt][1]);
            float2 p1 = make_float2(acc[mt][nt][2], acc[mt][nt][3]);
            if (bias) {
                float2 bv = *(const float2*)(bias + col);
                p0.x += bv.x; p0.y += bv.y;
                p1.x += bv.x; p1.y += bv.y;
            }
            if (res) {
                float2 r0 = *(const float2*)(res + (size_t)row0 * N_ + col);
                float2 r1 = *(const float2*)(res + (size_t)(row0 + 8) * N_ + col);
                p0.x += r0.x; p0.y += r0.y;
                p1.x += r1.x; p1.y += r1.y;
            }
            if (GELU) {
                p0.x = 0.5f * p0.x * (1.0f + erff(p0.x * 0.70710678118654752f));
                p0.y = 0.5f * p0.y * (1.0f + erff(p0.y * 0.70710678118654752f));
                p1.x = 0.5f * p1.x * (1.0f + erff(p1.x * 0.70710678118654752f));
                p1.y = 0.5f * p1.y * (1.0f + erff(p1.y * 0.70710678118654752f));
            }
            if (HALF_OUT) {
                *(__half2*)(Ch + (size_t)row0 * N_ + col) = __floats2half2_rn(p0.x, p0.y);
                *(__half2*)(Ch + (size_t)(row0 + 8) * N_ + col) = __floats2half2_rn(p1.x, p1.y);
            } else {
                *(float2*)(Cf + (size_t)row0 * N_ + col) = p0;
                *(float2*)(Cf + (size_t)(row0 + 8) * N_ + col) = p1;
            }
        }
    }
}

// ---------------------------------------------------------------------------
// fp16 flash attention. CTA: 64 Q rows x one (b,h). 4 warps (16-row tiles).
// KV blocks of 64. All tiles stride 72 halves (144B) -> conflict-free ldmatrix.
// ---------------------------------------------------------------------------
#define AHS 72
#define AH_SMEM (4 * 64 * AHS * 2)   // 36864 B

__global__ __launch_bounds__(128)
void attn_h_kernel(const __half* __restrict__ Qp, const __half* __restrict__ Kp,
                   const __half* __restrict__ Vp, __half* __restrict__ Out)
{
    extern __shared__ char smraw[];
    __half* sm = (__half*)smraw;
    __half* Qs = sm;
    __half* Ks = sm + 64 * AHS;
    __half* Vs = sm + 2 * 64 * AHS;
    __half* Ps = sm + 3 * 64 * AHS;
    const uint32_t sQ = smem_u32(Qs), sK = smem_u32(Ks), sV = smem_u32(Vs), sP = smem_u32(Ps);

    int qb = blockIdx.x, h = blockIdx.y, bb = blockIdx.z;
    int tid = threadIdx.x;
    int lane = tid & 31, warp = tid >> 5;
    int lq = lane >> 2, lr = lane & 3;

    // Load Q tile [64][64] halves
    size_t qbase = ((size_t)(bb * TSEQ + qb * 64)) * EMB + h * HEADD;
    #pragma unroll
    for (int s = 0; s < 4; s++) {
        int idx = tid + s * 128;
        int r = idx >> 3, ch = idx & 7;
        *(float4*)(Qs + r * AHS + ch * 8) =
            *(const float4*)(Qp + qbase + (size_t)r * EMB + ch * 8);
    }

    float m0 = -CUDART_INF_F, m1 = -CUDART_INF_F;
    float l0 = 0.f, l1 = 0.f;
    float o[8][4];
    #pragma unroll
    for (int nt = 0; nt < 8; nt++)
        #pragma unroll
        for (int r = 0; r < 4; r++) o[nt][r] = 0.f;

    const uint32_t sPw = sP + (uint32_t)(warp * 16 * AHS) * 2;
    __half* prow = Ps + warp * 16 * AHS;

    for (int jt = 0; jt <= qb; jt++) {
        __syncthreads();   // prior K/V reads done; also orders Q store->ldmatrix on jt=0
        size_t kbase = ((size_t)(bb * TSEQ + jt * 64)) * EMB + h * HEADD;
        #pragma unroll
        for (int s = 0; s < 4; s++) {
            int idx = tid + s * 128;
            int r = idx >> 3, ch = idx & 7;
            *(float4*)(Ks + r * AHS + ch * 8) =
                *(const float4*)(Kp + kbase + (size_t)r * EMB + ch * 8);
            *(float4*)(Vs + r * AHS + ch * 8) =
                *(const float4*)(Vp + kbase + (size_t)r * EMB + ch * 8);
        }
        __syncthreads();

        // S = Q K^T : 8 n-tiles (8 kv each) x 4 k16-steps
        float s[8][4];
        #pragma unroll
        for (int nt = 0; nt < 8; nt++)
            #pragma unroll
            for (int r = 0; r < 4; r++) s[nt][r] = 0.f;

        #pragma unroll
        for (int ks = 0; ks < 4; ks++) {
            int k0 = ks * 16;
            uint32_t a0, a1, a2, a3;
            ldsm_x4(a0, a1, a2, a3,
                    sQ + (uint32_t)((warp * 16 + (lane & 15)) * AHS
                                    + k0 + ((lane >> 4) << 3)) * 2);
            #pragma unroll
            for (int np = 0; np < 4; np++) {
                int n = np * 16 + ((lane >> 4) << 3) + (lane & 7);
                int koff = ((lane >> 3) & 1) << 3;
                uint32_t b0, b1, b2, b3;
                ldsm_x4(b0, b1, b2, b3,
                        sK + (uint32_t)(n * AHS + k0 + koff) * 2);
                mma_f16(s[np * 2][0], s[np * 2][1], s[np * 2][2], s[np * 2][3],
                        a0, a1, a2, a3, b0, b1);
                mma_f16(s[np * 2 + 1][0], s[np * 2 + 1][1], s[np * 2 + 1][2], s[np * 2 + 1][3],
                        a0, a1, a2, a3, b2, b3);
            }
        }

        // scale + causal mask (diagonal block only)
        const float scale = 0.125f;
        bool diag = (jt == qb);
        int row0 = warp * 16 + lq;
        #pragma unroll
        for (int nt = 0; nt < 8; nt++) {
            int col = nt * 8 + 2 * lr;
            s[nt][0] *= scale; s[nt][1] *= scale;
            s[nt][2] *= scale; s[nt][3] *= scale;
            if (diag) {
                if (col     > row0)     s[nt][0] = -CUDART_INF_F;
                if (col + 1 > row0)     s[nt][1] = -CUDART_INF_F;
                if (col     > row0 + 8) s[nt][2] = -CUDART_INF_F;
                if (col + 1 > row0 + 8) s[nt][3] = -CUDART_INF_F;
            }
        }

        // online softmax rows lq / lq+8
        {
            float rm = -CUDART_INF_F;
            #pragma unroll
            for (int nt = 0; nt < 8; nt++) rm = fmaxf(rm, fmaxf(s[nt][0], s[nt][1]));
            rm = fmaxf(rm, __shfl_xor_sync(0xffffffffu, rm, 1));
            rm = fmaxf(rm, __shfl_xor_sync(0xffffffffu, rm, 2));
            float mn = fmaxf(m0, rm);
            float alpha = __expf(m0 - mn);
            float ps = 0.f;
            #pragma unroll
            for (int nt = 0; nt < 8; nt++) {
                s[nt][0] = __expf(s[nt][0] - mn);
                s[nt][1] = __expf(s[nt][1] - mn);
                ps += s[nt][0] + s[nt][1];
            }
            ps += __shfl_xor_sync(0xffffffffu, ps, 1);
            ps += __shfl_xor_sync(0xffffffffu, ps, 2);
            l0 = l0 * alpha + ps;
            m0 = mn;
            #pragma unroll
            for (int nt = 0; nt < 8; nt++) { o[nt][0] *= alpha; o[nt][1] *= alpha; }
        }
        {
            float rm = -CUDART_INF_F;
            #pragma unroll
            for (int nt = 0; nt < 8; nt++) rm = fmaxf(rm, fmaxf(s[nt][2], s[nt][3]));
            rm = fmaxf(rm, __shfl_xor_sync(0xffffffffu, rm, 1));
            rm = fmaxf(rm, __shfl_xor_sync(0xffffffffu, rm, 2));
            float mn = fmaxf(m1, rm);
            float alpha = __expf(m1 - mn);
            float ps = 0.f;
            #pragma unroll
            for (int nt = 0; nt < 8; nt++) {
                s[nt][2] = __expf(s[nt][2] - mn);
                s[nt][3] = __expf(s[nt][3] - mn);
                ps += s[nt][2] + s[nt][3];
            }
            ps += __shfl_xor_sync(0xffffffffu, ps, 1);
            ps += __shfl_xor_sync(0xffffffffu, ps, 2);
            l1 = l1 * alpha + ps;
            m1 = mn;
            #pragma unroll
            for (int nt = 0; nt < 8; nt++) { o[nt][2] *= alpha; o[nt][3] *= alpha; }
        }

        // store P (half) to warp-private smem
        #pragma unroll
        for (int nt = 0; nt < 8; nt++) {
            *(__half2*)(prow + lq * AHS + nt * 8 + 2 * lr) =
                __floats2half2_rn(s[nt][0], s[nt][1]);
            *(__half2*)(prow + (lq + 8) * AHS + nt * 8 + 2 * lr) =
                __floats2half2_rn(s[nt][2], s[nt][3]);
        }
        __syncwarp();

        // O += P V : 4 kv k16-steps; V via ldmatrix.trans
        #pragma unroll
        for (int ks = 0; ks < 4; ks++) {
            int k0 = ks * 16;
            uint32_t a0, a1, a2, a3;
            ldsm_x4(a0, a1, a2, a3,
                    sPw + (uint32_t)((lane & 15) * AHS + k0 + ((lane >> 4) << 3)) * 2);
            #pragma unroll
            for (int dp = 0; dp < 4; dp++) {
                uint32_t b0, b1, b2, b3;
                ldsm_x4t(b0, b1, b2, b3,
                         sV + (uint32_t)((k0 + (lane & 15)) * AHS
                                         + dp * 16 + ((lane >> 4) << 3)) * 2);
                mma_f16(o[dp * 2][0], o[dp * 2][1], o[dp * 2][2], o[dp * 2][3],
                        a0, a1, a2, a3, b0, b1);
                mma_f16(o[dp * 2 + 1][0], o[dp * 2 + 1][1], o[dp * 2 + 1][2], o[dp * 2 + 1][3],
                        a0, a1, a2, a3, b2, b3);
            }
        }
        __syncwarp();
    }

    // epilogue
    float inv0 = 1.0f / l0, inv1 = 1.0f / l1;
    size_t r0 = (size_t)(bb * TSEQ + qb * 64 + warp * 16 + lq);
    size_t r1 = r0 + 8;
    #pragma unroll
    for (int nt = 0; nt < 8; nt++) {
        int col = h * HEADD + nt * 8 + 2 * lr;
        *(__half2*)(Out + r0 * EMB + col) = __floats2half2_rn(o[nt][0] * inv0, o[nt][1] * inv0);
        *(__half2*)(Out + r1 * EMB + col) = __floats2half2_rn(o[nt][2] * inv1, o[nt][3] * inv1);
    }
}

// ---------------------------------------------------------------------------
// Launch
// ---------------------------------------------------------------------------
extern "C" void kernel_launch(void* const* d_in, const int* in_sizes, int n_in,
                              void* d_out, int out_size)
{
    const float* x      = (const float*)d_in[0];
    const float* ln1_g  = (const float*)d_in[1];
    const float* ln1_b  = (const float*)d_in[2];
    const float* wq     = (const float*)d_in[3];
    const float* wk     = (const float*)d_in[4];
    const float* wv     = (const float*)d_in[5];
    const float* w_proj = (const float*)d_in[6];
    const float* b_proj = (const float*)d_in[7];
    const float* ln2_g  = (const float*)d_in[8];
    const float* ln2_b  = (const float*)d_in[9];
    const float* w1     = (const float*)d_in[10];
    const float* b1     = (const float*)d_in[11];
    const float* w2     = (const float*)d_in[12];
    const float* b2     = (const float*)d_in[13];
    float* out = (float*)d_out;

    __half *h, *q, *k, *v, *attn, *mid;
    float  *out1;
    __half *wqT, *wkT, *wvT, *wpT, *w1T, *w2T;
    cudaGetSymbolAddress((void**)&h,    g_h);
    cudaGetSymbolAddress((void**)&q,    g_q);
    cudaGetSymbolAddress((void**)&k,    g_k);
    cudaGetSymbolAddress((void**)&v,    g_v);
    cudaGetSymbolAddress((void**)&attn, g_attn);
    cudaGetSymbolAddress((void**)&out1, g_out1);
    cudaGetSymbolAddress((void**)&mid,  g_mid);
    cudaGetSymbolAddress((void**)&wqT,  g_wqT);
    cudaGetSymbolAddress((void**)&wkT,  g_wkT);
    cudaGetSymbolAddress((void**)&wvT,  g_wvT);
    cudaGetSymbolAddress((void**)&wpT,  g_wpT);
    cudaGetSymbolAddress((void**)&w1T,  g_w1T);
    cudaGetSymbolAddress((void**)&w2T,  g_w2T);

    cudaFuncSetAttribute(gemm_h_kernel<false, false>,
                         cudaFuncAttributeMaxDynamicSharedMemorySize, GH_SMEM);
    cudaFuncSetAttribute(gemm_h_kernel<false, true>,
                         cudaFuncAttributeMaxDynamicSharedMemorySize, GH_SMEM);
    cudaFuncSetAttribute(gemm_h_kernel<true, true>,
                         cudaFuncAttributeMaxDynamicSharedMemorySize, GH_SMEM);
    cudaFuncSetAttribute(attn_h_kernel,
                         cudaFuncAttributeMaxDynamicSharedMemorySize, AH_SMEM);

    // 0. Transpose + fp16 weights
    dim3 tb(32, 8);
    transpose_h_kernel<<<dim3(EMB / 32,   EMB / 32),   tb>>>(wq,     wqT, EMB,   EMB);
    transpose_h_kernel<<<dim3(EMB / 32,   EMB / 32),   tb>>>(wk,     wkT, EMB,   EMB);
    transpose_h_kernel<<<dim3(EMB / 32,   EMB / 32),   tb>>>(wv,     wvT, EMB,   EMB);
    transpose_h_kernel<<<dim3(EMB / 32,   EMB / 32),   tb>>>(w_proj, wpT, EMB,   EMB);
    transpose_h_kernel<<<dim3(FFDIM / 32, EMB / 32),   tb>>>(w1,     w1T, EMB,   FFDIM);
    transpose_h_kernel<<<dim3(EMB / 32,   FFDIM / 32), tb>>>(w2,     w2T, FFDIM, EMB);

    // 1. LN1 -> half
    ln_kernel<<<MROWS, 256>>>(x, ln1_g, ln1_b, h);

    // 2. QKV projections (fp16 mma, half out)
    dim3 gE(EMB / 128, MROWS / 128);
    gemm_h_kernel<false, true><<<gE, 256, GH_SMEM>>>(h, wqT, nullptr, nullptr, q, EMB, EMB);
    gemm_h_kernel<false, true><<<gE, 256, GH_SMEM>>>(h, wkT, nullptr, nullptr, k, EMB, EMB);
    gemm_h_kernel<false, true><<<gE, 256, GH_SMEM>>>(h, wvT, nullptr, nullptr, v, EMB, EMB);

    // 3. Causal flash attention (fp16 mma), half out
    attn_h_kernel<<<dim3(TSEQ / 64, NHEAD, BSZ), 128, AH_SMEM>>>(q, k, v, attn);

    // 4. out1 = x + attn @ w_proj + b_proj  (float out)
    gemm_h_kernel<false, false><<<gE, 256, GH_SMEM>>>(attn, wpT, b_proj, x, out1, EMB, EMB);

    // 5. LN2 -> half
    ln_kernel<<<MROWS, 256>>>(out1, ln2_g, ln2_b, h);

    // 6. mid = gelu(h @ w1 + b1)  (half out)
    dim3 gF(FFDIM / 128, MROWS / 128);
    gemm_h_kernel<true, true><<<gF, 256, GH_SMEM>>>(h, w1T, b1, nullptr, mid, FFDIM, EMB);

    // 7. out = out1 + mid @ w2 + b2  (float out)
    gemm_h_kernel<false, false><<<gE, 256, GH_SMEM>>>(mid, w2T, b2, out1, out, EMB, FFDIM);
}

// round 9
// speedup vs baseline: 5.7335x; 1.1410x over previous
#include <cuda_runtime.h>
#include <cuda_fp16.h>
#include <math_constants.h>
#include <math.h>
#include <stdint.h>

#define BSZ   8
#define TSEQ  1024
#define EMB   1024
#define NHEAD 16
#define HEADD 64
#define MROWS (BSZ * TSEQ)   // 8192
#define FFDIM 4096
#define QKV_N 3072

// ---------------------------------------------------------------------------
// Scratch
// ---------------------------------------------------------------------------
__device__ __half g_h    [(size_t)MROWS * EMB];
__device__ __half g_qkv  [(size_t)MROWS * QKV_N];
__device__ __half g_attn [(size_t)MROWS * EMB];
__device__ float  g_out1 [(size_t)MROWS * EMB];
__device__ __half g_mid  [(size_t)MROWS * FFDIM];
__device__ __half g_wqkvT[(size_t)QKV_N * EMB];   // [3072][1024]: q rows 0..1023, k, v
__device__ __half g_wpT  [(size_t)EMB * EMB];
__device__ __half g_w1T  [(size_t)EMB * FFDIM];
__device__ __half g_w2T  [(size_t)FFDIM * EMB];

// ---------------------------------------------------------------------------
// Helpers
// ---------------------------------------------------------------------------
__device__ __forceinline__ uint32_t smem_u32(const void* p) {
    uint32_t a;
    asm("{ .reg .u64 t; cvta.to.shared.u64 t, %1; cvt.u32.u64 %0, t; }" : "=r"(a) : "l"(p));
    return a;
}

__device__ __forceinline__ void cp16(uint32_t dst, const void* src) {
    asm volatile("cp.async.cg.shared.global [%0], [%1], 16;" :: "r"(dst), "l"(src) : "memory");
}
__device__ __forceinline__ void cp_commit() {
    asm volatile("cp.async.commit_group;" ::: "memory");
}
template<int N>
__device__ __forceinline__ void cp_wait() {
    asm volatile("cp.async.wait_group %0;" :: "n"(N) : "memory");
}

__device__ __forceinline__ void ldsm_x4(uint32_t& r0, uint32_t& r1, uint32_t& r2, uint32_t& r3,
                                        uint32_t addr) {
    asm volatile("ldmatrix.sync.aligned.m8n8.x4.shared.b16 {%0,%1,%2,%3}, [%4];"
                 : "=r"(r0), "=r"(r1), "=r"(r2), "=r"(r3) : "r"(addr));
}
__device__ __forceinline__ void ldsm_x4t(uint32_t& r0, uint32_t& r1, uint32_t& r2, uint32_t& r3,
                                         uint32_t addr) {
    asm volatile("ldmatrix.sync.aligned.m8n8.x4.trans.shared.b16 {%0,%1,%2,%3}, [%4];"
                 : "=r"(r0), "=r"(r1), "=r"(r2), "=r"(r3) : "r"(addr));
}

__device__ __forceinline__ void mma_f16(float& c0, float& c1, float& c2, float& c3,
                                        uint32_t a0, uint32_t a1, uint32_t a2, uint32_t a3,
                                        uint32_t b0, uint32_t b1) {
    asm volatile(
        "mma.sync.aligned.m16n8k16.row.col.f32.f16.f16.f32 "
        "{%0,%1,%2,%3}, {%4,%5,%6,%7}, {%8,%9}, {%0,%1,%2,%3};"
        : "+f"(c0), "+f"(c1), "+f"(c2), "+f"(c3)
        : "r"(a0), "r"(a1), "r"(a2), "r"(a3), "r"(b0), "r"(b1));
}

// ---------------------------------------------------------------------------
// Transpose + fp16 weights: in[K][N] float -> out[N][K] half
// ---------------------------------------------------------------------------
__global__ __launch_bounds__(256)
void transpose_h_kernel(const float* __restrict__ in, __half* __restrict__ out,
                        int K, int N)
{
    __shared__ float t[32][33];
    int n0 = blockIdx.x * 32, k0 = blockIdx.y * 32;
    int tx = threadIdx.x, ty = threadIdx.y;
    #pragma unroll
    for (int i = 0; i < 32; i += 8)
        t[ty + i][tx] = in[(size_t)(k0 + ty + i) * N + n0 + tx];
    __syncthreads();
    #pragma unroll
    for (int i = 0; i < 32; i += 8)
        out[(size_t)(n0 + ty + i) * K + k0 + tx] = __float2half_rn(t[tx][ty + i]);
}

// ---------------------------------------------------------------------------
// LayerNorm: float in -> half out
// ---------------------------------------------------------------------------
__global__ __launch_bounds__(256)
void ln_kernel(const float* __restrict__ x, const float* __restrict__ g,
               const float* __restrict__ b, __half* __restrict__ out)
{
    int row = blockIdx.x;
    int t   = threadIdx.x;
    const float4* xr = (const float4*)(x + (size_t)row * EMB);
    float4 v = xr[t];
    float s  = v.x + v.y + v.z + v.w;
    float ss = v.x * v.x + v.y * v.y + v.z * v.z + v.w * v.w;
    #pragma unroll
    for (int o = 16; o; o >>= 1) {
        s  += __shfl_xor_sync(0xffffffffu, s,  o);
        ss += __shfl_xor_sync(0xffffffffu, ss, o);
    }
    __shared__ float rs_[8], rss_[8];
    __shared__ float mu_s, rstd_s;
    int warp = t >> 5, lane = t & 31;
    if (lane == 0) { rs_[warp] = s; rss_[warp] = ss; }
    __syncthreads();
    if (t == 0) {
        float S = 0.f, SS = 0.f;
        #pragma unroll
        for (int i = 0; i < 8; i++) { S += rs_[i]; SS += rss_[i]; }
        float mu  = S * (1.0f / EMB);
        float var = SS * (1.0f / EMB) - mu * mu;
        mu_s = mu;
        rstd_s = rsqrtf(var + 1e-5f);
    }
    __syncthreads();
    float mu = mu_s, r = rstd_s;
    float4 gv = ((const float4*)g)[t];
    float4 bv = ((const float4*)b)[t];
    __half2* orow = (__half2*)(out + (size_t)row * EMB);
    orow[2 * t]     = __floats2half2_rn((v.x - mu) * r * gv.x + bv.x,
                                        (v.y - mu) * r * gv.y + bv.y);
    orow[2 * t + 1] = __floats2half2_rn((v.z - mu) * r * gv.z + bv.z,
                                        (v.w - mu) * r * gv.w + bv.w);
}

// ---------------------------------------------------------------------------
// fp16 mma GEMM v2: C[M,N] = A[M,K] @ Bt[N,K]^T (+bias)(+res)(GELU)
// CTA 128x256, BK=32, 8 warps (warp 64x64), 3-stage cp.async, ldmatrix.
// smem rows stride 40 halves -> conflict-free ldmatrix.
// ---------------------------------------------------------------------------
#define G2_STRIDE 40
#define G2_ATILE (128 * G2_STRIDE * 2)   // 10240 B
#define G2_BTILE (256 * G2_STRIDE * 2)   // 20480 B
#define G2_STAGE (G2_ATILE + G2_BTILE)   // 30720 B
#define G2_SMEM  (3 * G2_STAGE)          // 92160 B

template<bool GELU, bool HALF_OUT>
__global__ __launch_bounds__(256)
void gemm_h_kernel(const __half* __restrict__ A, const __half* __restrict__ Bt,
                   const float* __restrict__ bias, const float* __restrict__ res,
                   void* __restrict__ Cv, int N_, int K_)
{
    extern __shared__ char smem[];
    const uint32_t sb = smem_u32(smem);
    int tid  = threadIdx.x;
    int lane = tid & 31, warp = tid >> 5;
    int wm = warp >> 2;   // 0..1 (64-row slab)
    int wn = warp & 3;    // 0..3 (64-col slab)
    int rowBase = blockIdx.y * 128;
    int colBase = blockIdx.x * 256;
    const int C_CHUNKS = K_ >> 5;

    auto load_chunk = [&](int c, int st) {
        int k0 = c << 5;
        uint32_t aB = sb + st * G2_STAGE;
        uint32_t bB = aB + G2_ATILE;
        #pragma unroll
        for (int s = 0; s < 2; s++) {          // A: 512 x 16B
            int idx = tid + s * 256;
            int r = idx >> 2, ch = idx & 3;
            cp16(aB + (uint32_t)(r * G2_STRIDE + ch * 8) * 2,
                 A + (size_t)(rowBase + r) * K_ + k0 + ch * 8);
        }
        #pragma unroll
        for (int s = 0; s < 4; s++) {          // B: 1024 x 16B
            int idx = tid + s * 256;
            int r = idx >> 2, ch = idx & 3;
            cp16(bB + (uint32_t)(r * G2_STRIDE + ch * 8) * 2,
                 Bt + (size_t)(colBase + r) * K_ + k0 + ch * 8);
        }
        cp_commit();
    };

    float acc[4][8][4];
    #pragma unroll
    for (int i = 0; i < 4; i++)
        #pragma unroll
        for (int j = 0; j < 8; j++)
            #pragma unroll
            for (int r = 0; r < 4; r++) acc[i][j][r] = 0.f;

    load_chunk(0, 0);
    load_chunk(1, 1);

    for (int c = 0; c < C_CHUNKS; c++) {
        if (c + 2 < C_CHUNKS) load_chunk(c + 2, (c + 2) % 3);
        else cp_commit();
        cp_wait<2>();
        __syncthreads();

        int st = c % 3;
        uint32_t aBase = sb + st * G2_STAGE;
        uint32_t bBase = aBase + G2_ATILE;

        #pragma unroll
        for (int ks = 0; ks < 2; ks++) {
            int k0 = ks * 16;
            uint32_t a[4][4];
            #pragma unroll
            for (int mt = 0; mt < 4; mt++) {
                uint32_t addr = aBase +
                    (uint32_t)((wm * 64 + mt * 16 + (lane & 15)) * G2_STRIDE
                               + k0 + ((lane >> 4) << 3)) * 2;
                ldsm_x4(a[mt][0], a[mt][1], a[mt][2], a[mt][3], addr);
            }
            uint32_t bf[8][2];
            #pragma unroll
            for (int np = 0; np < 4; np++) {
                int n = wn * 64 + np * 16 + ((lane >> 4) << 3) + (lane & 7);
                int koff = ((lane >> 3) & 1) << 3;
                uint32_t addr = bBase + (uint32_t)(n * G2_STRIDE + k0 + koff) * 2;
                ldsm_x4(bf[np * 2][0], bf[np * 2][1], bf[np * 2 + 1][0], bf[np * 2 + 1][1], addr);
            }
            #pragma unroll
            for (int mt = 0; mt < 4; mt++)
                #pragma unroll
                for (int nt = 0; nt < 8; nt++)
                    mma_f16(acc[mt][nt][0], acc[mt][nt][1], acc[mt][nt][2], acc[mt][nt][3],
                            a[mt][0], a[mt][1], a[mt][2], a[mt][3],
                            bf[nt][0], bf[nt][1]);
        }
        __syncthreads();
    }

    // Epilogue
    int lq = lane >> 2, lr = lane & 3;
    __half* Ch = (__half*)Cv;
    float*  Cf = (float*)Cv;
    #pragma unroll
    for (int mt = 0; mt < 4; mt++) {
        int row0 = rowBase + wm * 64 + mt * 16 + lq;
        #pragma unroll
        for (int nt = 0; nt < 8; nt++) {
            int col = colBase + wn * 64 + nt * 8 + lr * 2;
            float2 p0 = make_float2(acc[mt][nt][0], acc[mt][nt][1]);
            float2 p1 = make_float2(acc[mt][nt][2], acc[mt][nt][3]);
            if (bias) {
                float2 bv = *(const float2*)(bias + col);
                p0.x += bv.x; p0.y += bv.y;
                p1.x += bv.x; p1.y += bv.y;
            }
            if (res) {
                float2 r0 = *(const float2*)(res + (size_t)row0 * N_ + col);
                float2 r1 = *(const float2*)(res + (size_t)(row0 + 8) * N_ + col);
                p0.x += r0.x; p0.y += r0.y;
                p1.x += r1.x; p1.y += r1.y;
            }
            if (GELU) {
                p0.x = 0.5f * p0.x * (1.0f + erff(p0.x * 0.70710678118654752f));
                p0.y = 0.5f * p0.y * (1.0f + erff(p0.y * 0.70710678118654752f));
                p1.x = 0.5f * p1.x * (1.0f + erff(p1.x * 0.70710678118654752f));
                p1.y = 0.5f * p1.y * (1.0f + erff(p1.y * 0.70710678118654752f));
            }
            if (HALF_OUT) {
                *(__half2*)(Ch + (size_t)row0 * N_ + col) = __floats2half2_rn(p0.x, p0.y);
                *(__half2*)(Ch + (size_t)(row0 + 8) * N_ + col) = __floats2half2_rn(p1.x, p1.y);
            } else {
                *(float2*)(Cf + (size_t)row0 * N_ + col) = p0;
                *(float2*)(Cf + (size_t)(row0 + 8) * N_ + col) = p1;
            }
        }
    }
}

// ---------------------------------------------------------------------------
// fp16 flash attention reading fused QKV buffer (row stride QKV_N).
// CTA: 64 Q rows x one (b,h). 4 warps. KV blocks of 64. stride-72 smem.
// ---------------------------------------------------------------------------
#define AHS 72
#define AH_SMEM (4 * 64 * AHS * 2)   // 36864 B

__global__ __launch_bounds__(128)
void attn_h_kernel(const __half* __restrict__ QKV, __half* __restrict__ Out)
{
    extern __shared__ char smraw[];
    __half* sm = (__half*)smraw;
    __half* Qs = sm;
    __half* Ks = sm + 64 * AHS;
    __half* Vs = sm + 2 * 64 * AHS;
    __half* Ps = sm + 3 * 64 * AHS;
    const uint32_t sQ = smem_u32(Qs), sK = smem_u32(Ks), sV = smem_u32(Vs), sP = smem_u32(Ps);

    int qb = blockIdx.x, h = blockIdx.y, bb = blockIdx.z;
    int tid = threadIdx.x;
    int lane = tid & 31, warp = tid >> 5;
    int lq = lane >> 2, lr = lane & 3;

    const __half* Qp = QKV + h * HEADD;
    const __half* Kp = QKV + EMB + h * HEADD;
    const __half* Vp = QKV + 2 * EMB + h * HEADD;

    // Load Q tile [64][64] halves
    size_t qbase = (size_t)(bb * TSEQ + qb * 64) * QKV_N;
    #pragma unroll
    for (int s = 0; s < 4; s++) {
        int idx = tid + s * 128;
        int r = idx >> 3, ch = idx & 7;
        *(float4*)(Qs + r * AHS + ch * 8) =
            *(const float4*)(Qp + qbase + (size_t)r * QKV_N + ch * 8);
    }

    float m0 = -CUDART_INF_F, m1 = -CUDART_INF_F;
    float l0 = 0.f, l1 = 0.f;
    float o[8][4];
    #pragma unroll
    for (int nt = 0; nt < 8; nt++)
        #pragma unroll
        for (int r = 0; r < 4; r++) o[nt][r] = 0.f;

    const uint32_t sPw = sP + (uint32_t)(warp * 16 * AHS) * 2;
    __half* prow = Ps + warp * 16 * AHS;

    for (int jt = 0; jt <= qb; jt++) {
        __syncthreads();
        size_t kbase = (size_t)(bb * TSEQ + jt * 64) * QKV_N;
        #pragma unroll
        for (int s = 0; s < 4; s++) {
            int idx = tid + s * 128;
            int r = idx >> 3, ch = idx & 7;
            *(float4*)(Ks + r * AHS + ch * 8) =
                *(const float4*)(Kp + kbase + (size_t)r * QKV_N + ch * 8);
            *(float4*)(Vs + r * AHS + ch * 8) =
                *(const float4*)(Vp + kbase + (size_t)r * QKV_N + ch * 8);
        }
        __syncthreads();

        float s[8][4];
        #pragma unroll
        for (int nt = 0; nt < 8; nt++)
            #pragma unroll
            for (int r = 0; r < 4; r++) s[nt][r] = 0.f;

        #pragma unroll
        for (int ks = 0; ks < 4; ks++) {
            int k0 = ks * 16;
            uint32_t a0, a1, a2, a3;
            ldsm_x4(a0, a1, a2, a3,
                    sQ + (uint32_t)((warp * 16 + (lane & 15)) * AHS
                                    + k0 + ((lane >> 4) << 3)) * 2);
            #pragma unroll
            for (int np = 0; np < 4; np++) {
                int n = np * 16 + ((lane >> 4) << 3) + (lane & 7);
                int koff = ((lane >> 3) & 1) << 3;
                uint32_t b0, b1, b2, b3;
                ldsm_x4(b0, b1, b2, b3,
                        sK + (uint32_t)(n * AHS + k0 + koff) * 2);
                mma_f16(s[np * 2][0], s[np * 2][1], s[np * 2][2], s[np * 2][3],
                        a0, a1, a2, a3, b0, b1);
                mma_f16(s[np * 2 + 1][0], s[np * 2 + 1][1], s[np * 2 + 1][2], s[np * 2 + 1][3],
                        a0, a1, a2, a3, b2, b3);
            }
        }

        const float scale = 0.125f;
        bool diag = (jt == qb);
        int row0 = warp * 16 + lq;
        #pragma unroll
        for (int nt = 0; nt < 8; nt++) {
            int col = nt * 8 + 2 * lr;
            s[nt][0] *= scale; s[nt][1] *= scale;
            s[nt][2] *= scale; s[nt][3] *= scale;
            if (diag) {
                if (col     > row0)     s[nt][0] = -CUDART_INF_F;
                if (col + 1 > row0)     s[nt][1] = -CUDART_INF_F;
                if (col     > row0 + 8) s[nt][2] = -CUDART_INF_F;
                if (col + 1 > row0 + 8) s[nt][3] = -CUDART_INF_F;
            }
        }

        {
            float rm = -CUDART_INF_F;
            #pragma unroll
            for (int nt = 0; nt < 8; nt++) rm = fmaxf(rm, fmaxf(s[nt][0], s[nt][1]));
            rm = fmaxf(rm, __shfl_xor_sync(0xffffffffu, rm, 1));
            rm = fmaxf(rm, __shfl_xor_sync(0xffffffffu, rm, 2));
            float mn = fmaxf(m0, rm);
            float alpha = __expf(m0 - mn);
            float ps = 0.f;
            #pragma unroll
            for (int nt = 0; nt < 8; nt++) {
                s[nt][0] = __expf(s[nt][0] - mn);
                s[nt][1] = __expf(s[nt][1] - mn);
                ps += s[nt][0] + s[nt][1];
            }
            ps += __shfl_xor_sync(0xffffffffu, ps, 1);
            ps += __shfl_xor_sync(0xffffffffu, ps, 2);
            l0 = l0 * alpha + ps;
            m0 = mn;
            #pragma unroll
            for (int nt = 0; nt < 8; nt++) { o[nt][0] *= alpha; o[nt][1] *= alpha; }
        }
        {
            float rm = -CUDART_INF_F;
            #pragma unroll
            for (int nt = 0; nt < 8; nt++) rm = fmaxf(rm, fmaxf(s[nt][2], s[nt][3]));
            rm = fmaxf(rm, __shfl_xor_sync(0xffffffffu, rm, 1));
            rm = fmaxf(rm, __shfl_xor_sync(0xffffffffu, rm, 2));
            float mn = fmaxf(m1, rm);
            float alpha = __expf(m1 - mn);
            float ps = 0.f;
            #pragma unroll
            for (int nt = 0; nt < 8; nt++) {
                s[nt][2] = __expf(s[nt][2] - mn);
                s[nt][3] = __expf(s[nt][3] - mn);
                ps += s[nt][2] + s[nt][3];
            }
            ps += __shfl_xor_sync(0xffffffffu, ps, 1);
            ps += __shfl_xor_sync(0xffffffffu, ps, 2);
            l1 = l1 * alpha + ps;
            m1 = mn;
            #pragma unroll
            for (int nt = 0; nt < 8; nt++) { o[nt][2] *= alpha; o[nt][3] *= alpha; }
        }

        #pragma unroll
        for (int nt = 0; nt < 8; nt++) {
            *(__half2*)(prow + lq * AHS + nt * 8 + 2 * lr) =
                __floats2half2_rn(s[nt][0], s[nt][1]);
            *(__half2*)(prow + (lq + 8) * AHS + nt * 8 + 2 * lr) =
                __floats2half2_rn(s[nt][2], s[nt][3]);
        }
        __syncwarp();

        #pragma unroll
        for (int ks = 0; ks < 4; ks++) {
            int k0 = ks * 16;
            uint32_t a0, a1, a2, a3;
            ldsm_x4(a0, a1, a2, a3,
                    sPw + (uint32_t)((lane & 15) * AHS + k0 + ((lane >> 4) << 3)) * 2);
            #pragma unroll
            for (int dp = 0; dp < 4; dp++) {
                uint32_t b0, b1, b2, b3;
                ldsm_x4t(b0, b1, b2, b3,
                         sV + (uint32_t)((k0 + (lane & 15)) * AHS
                                         + dp * 16 + ((lane >> 4) << 3)) * 2);
                mma_f16(o[dp * 2][0], o[dp * 2][1], o[dp * 2][2], o[dp * 2][3],
                        a0, a1, a2, a3, b0, b1);
                mma_f16(o[dp * 2 + 1][0], o[dp * 2 + 1][1], o[dp * 2 + 1][2], o[dp * 2 + 1][3],
                        a0, a1, a2, a3, b2, b3);
            }
        }
        __syncwarp();
    }

    float inv0 = 1.0f / l0, inv1 = 1.0f / l1;
    size_t r0 = (size_t)(bb * TSEQ + qb * 64 + warp * 16 + lq);
    size_t r1 = r0 + 8;
    #pragma unroll
    for (int nt = 0; nt < 8; nt++) {
        int col = h * HEADD + nt * 8 + 2 * lr;
        *(__half2*)(Out + r0 * EMB + col) = __floats2half2_rn(o[nt][0] * inv0, o[nt][1] * inv0);
        *(__half2*)(Out + r1 * EMB + col) = __floats2half2_rn(o[nt][2] * inv1, o[nt][3] * inv1);
    }
}

// ---------------------------------------------------------------------------
// Launch
// ---------------------------------------------------------------------------
extern "C" void kernel_launch(void* const* d_in, const int* in_sizes, int n_in,
                              void* d_out, int out_size)
{
    const float* x      = (const float*)d_in[0];
    const float* ln1_g  = (const float*)d_in[1];
    const float* ln1_b  = (const float*)d_in[2];
    const float* wq     = (const float*)d_in[3];
    const float* wk     = (const float*)d_in[4];
    const float* wv     = (const float*)d_in[5];
    const float* w_proj = (const float*)d_in[6];
    const float* b_proj = (const float*)d_in[7];
    const float* ln2_g  = (const float*)d_in[8];
    const float* ln2_b  = (const float*)d_in[9];
    const float* w1     = (const float*)d_in[10];
    const float* b1     = (const float*)d_in[11];
    const float* w2     = (const float*)d_in[12];
    const float* b2     = (const float*)d_in[13];
    float* out = (float*)d_out;

    __half *h, *qkv, *attn, *mid;
    float  *out1;
    __half *wqkvT, *wpT, *w1T, *w2T;
    cudaGetSymbolAddress((void**)&h,     g_h);
    cudaGetSymbolAddress((void**)&qkv,   g_qkv);
    cudaGetSymbolAddress((void**)&attn,  g_attn);
    cudaGetSymbolAddress((void**)&out1,  g_out1);
    cudaGetSymbolAddress((void**)&mid,   g_mid);
    cudaGetSymbolAddress((void**)&wqkvT, g_wqkvT);
    cudaGetSymbolAddress((void**)&wpT,   g_wpT);
    cudaGetSymbolAddress((void**)&w1T,   g_w1T);
    cudaGetSymbolAddress((void**)&w2T,   g_w2T);

    cudaFuncSetAttribute(gemm_h_kernel<false, false>,
                         cudaFuncAttributeMaxDynamicSharedMemorySize, G2_SMEM);
    cudaFuncSetAttribute(gemm_h_kernel<false, true>,
                         cudaFuncAttributeMaxDynamicSharedMemorySize, G2_SMEM);
    cudaFuncSetAttribute(gemm_h_kernel<true, true>,
                         cudaFuncAttributeMaxDynamicSharedMemorySize, G2_SMEM);
    cudaFuncSetAttribute(attn_h_kernel,
                         cudaFuncAttributeMaxDynamicSharedMemorySize, AH_SMEM);

    // 0. Transpose + fp16 weights (q/k/v into one fused buffer)
    dim3 tb(32, 8);
    transpose_h_kernel<<<dim3(EMB / 32,   EMB / 32),   tb>>>(wq, wqkvT,                        EMB, EMB);
    transpose_h_kernel<<<dim3(EMB / 32,   EMB / 32),   tb>>>(wk, wqkvT + (size_t)EMB * EMB,     EMB, EMB);
    transpose_h_kernel<<<dim3(EMB / 32,   EMB / 32),   tb>>>(wv, wqkvT + (size_t)2 * EMB * EMB, EMB, EMB);
    transpose_h_kernel<<<dim3(EMB / 32,   EMB / 32),   tb>>>(w_proj, wpT, EMB, EMB);
    transpose_h_kernel<<<dim3(FFDIM / 32, EMB / 32),   tb>>>(w1, w1T, EMB, FFDIM);
    transpose_h_kernel<<<dim3(EMB / 32,   FFDIM / 32), tb>>>(w2, w2T, FFDIM, EMB);

    // 1. LN1 -> half
    ln_kernel<<<MROWS, 256>>>(x, ln1_g, ln1_b, h);

    // 2. Fused QKV projection (N=3072)
    dim3 gQKV(QKV_N / 256, MROWS / 128);
    gemm_h_kernel<false, true><<<gQKV, 256, G2_SMEM>>>(h, wqkvT, nullptr, nullptr, qkv, QKV_N, EMB);

    // 3. Causal flash attention (fp16 mma)
    attn_h_kernel<<<dim3(TSEQ / 64, NHEAD, BSZ), 128, AH_SMEM>>>(qkv, attn);

    // 4. out1 = x + attn @ w_proj + b_proj  (float out)
    dim3 gE(EMB / 256, MROWS / 128);
    gemm_h_kernel<false, false><<<gE, 256, G2_SMEM>>>(attn, wpT, b_proj, x, out1, EMB, EMB);

    // 5. LN2 -> half
    ln_kernel<<<MROWS, 256>>>(out1, ln2_g, ln2_b, h);

    // 6. mid = gelu(h @ w1 + b1)  (half out)
    dim3 gF(FFDIM / 256, MROWS / 128);
    gemm_h_kernel<true, true><<<gF, 256, G2_SMEM>>>(h, w1T, b1, nullptr, mid, FFDIM, EMB);

    // 7. out = out1 + mid @ w2 + b2  (float out)
    gemm_h_kernel<false, false><<<gE, 256, G2_SMEM>>>(mid, w2T, b2, out1, out, EMB, FFDIM);
}

// round 10
// speedup vs baseline: 5.7971x; 1.0111x over previous
#include <cuda_runtime.h>
#include <cuda_fp16.h>
#include <math_constants.h>
#include <math.h>
#include <stdint.h>

#define BSZ   8
#define TSEQ  1024
#define EMB   1024
#define NHEAD 16
#define HEADD 64
#define MROWS (BSZ * TSEQ)   // 8192
#define FFDIM 4096
#define QKV_N 3072

// ---------------------------------------------------------------------------
// Scratch
// ---------------------------------------------------------------------------
__device__ __half g_h    [(size_t)MROWS * EMB];
__device__ __half g_qkv  [(size_t)MROWS * QKV_N];
__device__ __half g_attn [(size_t)MROWS * EMB];
__device__ float  g_out1 [(size_t)MROWS * EMB];
__device__ __half g_mid  [(size_t)MROWS * FFDIM];
__device__ __half g_wqkvT[(size_t)QKV_N * EMB];
__device__ __half g_wpT  [(size_t)EMB * EMB];
__device__ __half g_w1T  [(size_t)EMB * FFDIM];
__device__ __half g_w2T  [(size_t)FFDIM * EMB];

// ---------------------------------------------------------------------------
// Helpers
// ---------------------------------------------------------------------------
__device__ __forceinline__ uint32_t smem_u32(const void* p) {
    uint32_t a;
    asm("{ .reg .u64 t; cvta.to.shared.u64 t, %1; cvt.u32.u64 %0, t; }" : "=r"(a) : "l"(p));
    return a;
}

__device__ __forceinline__ void cp16(uint32_t dst, const void* src) {
    asm volatile("cp.async.cg.shared.global [%0], [%1], 16;" :: "r"(dst), "l"(src) : "memory");
}
__device__ __forceinline__ void cp_commit() {
    asm volatile("cp.async.commit_group;" ::: "memory");
}
template<int N>
__device__ __forceinline__ void cp_wait() {
    asm volatile("cp.async.wait_group %0;" :: "n"(N) : "memory");
}

__device__ __forceinline__ void ldsm_x4(uint32_t& r0, uint32_t& r1, uint32_t& r2, uint32_t& r3,
                                        uint32_t addr) {
    asm volatile("ldmatrix.sync.aligned.m8n8.x4.shared.b16 {%0,%1,%2,%3}, [%4];"
                 : "=r"(r0), "=r"(r1), "=r"(r2), "=r"(r3) : "r"(addr));
}
__device__ __forceinline__ void ldsm_x4t(uint32_t& r0, uint32_t& r1, uint32_t& r2, uint32_t& r3,
                                         uint32_t addr) {
    asm volatile("ldmatrix.sync.aligned.m8n8.x4.trans.shared.b16 {%0,%1,%2,%3}, [%4];"
                 : "=r"(r0), "=r"(r1), "=r"(r2), "=r"(r3) : "r"(addr));
}

__device__ __forceinline__ void mma_f16(float& c0, float& c1, float& c2, float& c3,
                                        uint32_t a0, uint32_t a1, uint32_t a2, uint32_t a3,
                                        uint32_t b0, uint32_t b1) {
    asm volatile(
        "mma.sync.aligned.m16n8k16.row.col.f32.f16.f16.f32 "
        "{%0,%1,%2,%3}, {%4,%5,%6,%7}, {%8,%9}, {%0,%1,%2,%3};"
        : "+f"(c0), "+f"(c1), "+f"(c2), "+f"(c3)
        : "r"(a0), "r"(a1), "r"(a2), "r"(a3), "r"(b0), "r"(b1));
}

// ---------------------------------------------------------------------------
// Batched transpose + fp16 of all 6 weight matrices in ONE launch.
// ---------------------------------------------------------------------------
struct TransArgs {
    const float* in[6];
    __half*      out[6];
    int K[6], N[6];
    int off[6];   // cumulative tile offsets
};

__global__ __launch_bounds__(256)
void transpose6_kernel(TransArgs A)
{
    __shared__ float t[32][33];
    int tb = blockIdx.x;
    int m = 0;
    #pragma unroll
    for (int i = 1; i < 6; i++) if (tb >= A.off[i]) m = i;
    int lt = tb - A.off[m];
    int N = A.N[m], K = A.K[m];
    int ntx = N >> 5;
    int n0 = (lt % ntx) * 32, k0 = (lt / ntx) * 32;
    const float* in = A.in[m];
    __half* out = A.out[m];

    int tx = threadIdx.x, ty = threadIdx.y;
    #pragma unroll
    for (int i = 0; i < 32; i += 8)
        t[ty + i][tx] = in[(size_t)(k0 + ty + i) * N + n0 + tx];
    __syncthreads();
    #pragma unroll
    for (int i = 0; i < 32; i += 8)
        out[(size_t)(n0 + ty + i) * K + k0 + tx] = __float2half_rn(t[tx][ty + i]);
}

// ---------------------------------------------------------------------------
// LayerNorm: float in -> half out
// ---------------------------------------------------------------------------
__global__ __launch_bounds__(256)
void ln_kernel(const float* __restrict__ x, const float* __restrict__ g,
               const float* __restrict__ b, __half* __restrict__ out)
{
    int row = blockIdx.x;
    int t   = threadIdx.x;
    const float4* xr = (const float4*)(x + (size_t)row * EMB);
    float4 v = xr[t];
    float s  = v.x + v.y + v.z + v.w;
    float ss = v.x * v.x + v.y * v.y + v.z * v.z + v.w * v.w;
    #pragma unroll
    for (int o = 16; o; o >>= 1) {
        s  += __shfl_xor_sync(0xffffffffu, s,  o);
        ss += __shfl_xor_sync(0xffffffffu, ss, o);
    }
    __shared__ float rs_[8], rss_[8];
    __shared__ float mu_s, rstd_s;
    int warp = t >> 5, lane = t & 31;
    if (lane == 0) { rs_[warp] = s; rss_[warp] = ss; }
    __syncthreads();
    if (t == 0) {
        float S = 0.f, SS = 0.f;
        #pragma unroll
        for (int i = 0; i < 8; i++) { S += rs_[i]; SS += rss_[i]; }
        float mu  = S * (1.0f / EMB);
        float var = SS * (1.0f / EMB) - mu * mu;
        mu_s = mu;
        rstd_s = rsqrtf(var + 1e-5f);
    }
    __syncthreads();
    float mu = mu_s, r = rstd_s;
    float4 gv = ((const float4*)g)[t];
    float4 bv = ((const float4*)b)[t];
    __half2* orow = (__half2*)(out + (size_t)row * EMB);
    orow[2 * t]     = __floats2half2_rn((v.x - mu) * r * gv.x + bv.x,
                                        (v.y - mu) * r * gv.y + bv.y);
    orow[2 * t + 1] = __floats2half2_rn((v.z - mu) * r * gv.z + bv.z,
                                        (v.w - mu) * r * gv.w + bv.w);
}

// ---------------------------------------------------------------------------
// fp16 mma GEMM: CTA 128x256, BK=32, 8 warps (64x64), 3-stage cp.async.
// ---------------------------------------------------------------------------
#define G2_STRIDE 40
#define G2_ATILE (128 * G2_STRIDE * 2)
#define G2_BTILE (256 * G2_STRIDE * 2)
#define G2_STAGE (G2_ATILE + G2_BTILE)
#define G2_SMEM  (3 * G2_STAGE)          // 92160 B

template<bool GELU, bool HALF_OUT>
__global__ __launch_bounds__(256)
void gemm_h_kernel(const __half* __restrict__ A, const __half* __restrict__ Bt,
                   const float* __restrict__ bias, const float* __restrict__ res,
                   void* __restrict__ Cv, int N_, int K_)
{
    extern __shared__ char smem[];
    const uint32_t sb = smem_u32(smem);
    int tid  = threadIdx.x;
    int lane = tid & 31, warp = tid >> 5;
    int wm = warp >> 2;
    int wn = warp & 3;
    int rowBase = blockIdx.y * 128;
    int colBase = blockIdx.x * 256;
    const int C_CHUNKS = K_ >> 5;

    auto load_chunk = [&](int c, int st) {
        int k0 = c << 5;
        uint32_t aB = sb + st * G2_STAGE;
        uint32_t bB = aB + G2_ATILE;
        #pragma unroll
        for (int s = 0; s < 2; s++) {
            int idx = tid + s * 256;
            int r = idx >> 2, ch = idx & 3;
            cp16(aB + (uint32_t)(r * G2_STRIDE + ch * 8) * 2,
                 A + (size_t)(rowBase + r) * K_ + k0 + ch * 8);
        }
        #pragma unroll
        for (int s = 0; s < 4; s++) {
            int idx = tid + s * 256;
            int r = idx >> 2, ch = idx & 3;
            cp16(bB + (uint32_t)(r * G2_STRIDE + ch * 8) * 2,
                 Bt + (size_t)(colBase + r) * K_ + k0 + ch * 8);
        }
        cp_commit();
    };

    float acc[4][8][4];
    #pragma unroll
    for (int i = 0; i < 4; i++)
        #pragma unroll
        for (int j = 0; j < 8; j++)
            #pragma unroll
            for (int r = 0; r < 4; r++) acc[i][j][r] = 0.f;

    load_chunk(0, 0);
    load_chunk(1, 1);

    for (int c = 0; c < C_CHUNKS; c++) {
        if (c + 2 < C_CHUNKS) load_chunk(c + 2, (c + 2) % 3);
        else cp_commit();
        cp_wait<2>();
        __syncthreads();

        int st = c % 3;
        uint32_t aBase = sb + st * G2_STAGE;
        uint32_t bBase = aBase + G2_ATILE;

        #pragma unroll
        for (int ks = 0; ks < 2; ks++) {
            int k0 = ks * 16;
            uint32_t a[4][4];
            #pragma unroll
            for (int mt = 0; mt < 4; mt++) {
                uint32_t addr = aBase +
                    (uint32_t)((wm * 64 + mt * 16 + (lane & 15)) * G2_STRIDE
                               + k0 + ((lane >> 4) << 3)) * 2;
                ldsm_x4(a[mt][0], a[mt][1], a[mt][2], a[mt][3], addr);
            }
            uint32_t bf[8][2];
            #pragma unroll
            for (int np = 0; np < 4; np++) {
                int n = wn * 64 + np * 16 + ((lane >> 4) << 3) + (lane & 7);
                int koff = ((lane >> 3) & 1) << 3;
                uint32_t addr = bBase + (uint32_t)(n * G2_STRIDE + k0 + koff) * 2;
                ldsm_x4(bf[np * 2][0], bf[np * 2][1], bf[np * 2 + 1][0], bf[np * 2 + 1][1], addr);
            }
            #pragma unroll
            for (int mt = 0; mt < 4; mt++)
                #pragma unroll
                for (int nt = 0; nt < 8; nt++)
                    mma_f16(acc[mt][nt][0], acc[mt][nt][1], acc[mt][nt][2], acc[mt][nt][3],
                            a[mt][0], a[mt][1], a[mt][2], a[mt][3],
                            bf[nt][0], bf[nt][1]);
        }
        __syncthreads();
    }

    int lq = lane >> 2, lr = lane & 3;
    __half* Ch = (__half*)Cv;
    float*  Cf = (float*)Cv;
    #pragma unroll
    for (int mt = 0; mt < 4; mt++) {
        int row0 = rowBase + wm * 64 + mt * 16 + lq;
        #pragma unroll
        for (int nt = 0; nt < 8; nt++) {
            int col = colBase + wn * 64 + nt * 8 + lr * 2;
            float2 p0 = make_float2(acc[mt][nt][0], acc[mt][nt][1]);
            float2 p1 = make_float2(acc[mt][nt][2], acc[mt][nt][3]);
            if (bias) {
                float2 bv = *(const float2*)(bias + col);
                p0.x += bv.x; p0.y += bv.y;
                p1.x += bv.x; p1.y += bv.y;
            }
            if (res) {
                float2 r0 = *(const float2*)(res + (size_t)row0 * N_ + col);
                float2 r1 = *(const float2*)(res + (size_t)(row0 + 8) * N_ + col);
                p0.x += r0.x; p0.y += r0.y;
                p1.x += r1.x; p1.y += r1.y;
            }
            if (GELU) {
                p0.x = 0.5f * p0.x * (1.0f + erff(p0.x * 0.70710678118654752f));
                p0.y = 0.5f * p0.y * (1.0f + erff(p0.y * 0.70710678118654752f));
                p1.x = 0.5f * p1.x * (1.0f + erff(p1.x * 0.70710678118654752f));
                p1.y = 0.5f * p1.y * (1.0f + erff(p1.y * 0.70710678118654752f));
            }
            if (HALF_OUT) {
                *(__half2*)(Ch + (size_t)row0 * N_ + col) = __floats2half2_rn(p0.x, p0.y);
                *(__half2*)(Ch + (size_t)(row0 + 8) * N_ + col) = __floats2half2_rn(p1.x, p1.y);
            } else {
                *(float2*)(Cf + (size_t)row0 * N_ + col) = p0;
                *(float2*)(Cf + (size_t)(row0 + 8) * N_ + col) = p1;
            }
        }
    }
}

// ---------------------------------------------------------------------------
// fp16 flash attention, cp.async double-buffered K/V.
// CTA: 64 Q rows x one (b,h). 4 warps. KV blocks of 64. stride-72 smem.
// ---------------------------------------------------------------------------
#define AHS 72
#define AKV (64 * AHS)                    // halves per tile
#define AH_SMEM (6 * AKV * 2)             // Q + 2K + 2V + P = 55296 B

__global__ __launch_bounds__(128)
void attn_h_kernel(const __half* __restrict__ QKV, __half* __restrict__ Out)
{
    extern __shared__ char smraw[];
    __half* sm = (__half*)smraw;
    __half* Qs = sm;                      // [64][72]
    __half* Ks = sm + AKV;                // 2 buffers
    __half* Vs = sm + 3 * AKV;            // 2 buffers
    __half* Ps = sm + 5 * AKV;
    const uint32_t sQ = smem_u32(Qs), sK0 = smem_u32(Ks), sV0 = smem_u32(Vs),
                   sP = smem_u32(Ps);

    int qb = blockIdx.x, h = blockIdx.y, bb = blockIdx.z;
    int tid = threadIdx.x;
    int lane = tid & 31, warp = tid >> 5;
    int lq = lane >> 2, lr = lane & 3;

    const __half* Qp = QKV + h * HEADD;
    const __half* Kp = QKV + EMB + h * HEADD;
    const __half* Vp = QKV + 2 * EMB + h * HEADD;

    // Load Q tile [64][64] halves (plain stores; ordered by first loop barrier)
    size_t qbase = (size_t)(bb * TSEQ + qb * 64) * QKV_N;
    #pragma unroll
    for (int s = 0; s < 4; s++) {
        int idx = tid + s * 128;
        int r = idx >> 3, ch = idx & 7;
        *(float4*)(Qs + r * AHS + ch * 8) =
            *(const float4*)(Qp + qbase + (size_t)r * QKV_N + ch * 8);
    }

    // cp.async loader for KV block jt into buffer b
    auto load_kv = [&](int jt, int b) {
        size_t kbase = (size_t)(bb * TSEQ + jt * 64) * QKV_N;
        uint32_t kB = sK0 + (uint32_t)(b * AKV) * 2;
        uint32_t vB = sV0 + (uint32_t)(b * AKV) * 2;
        #pragma unroll
        for (int s = 0; s < 4; s++) {
            int idx = tid + s * 128;
            int r = idx >> 3, ch = idx & 7;
            cp16(kB + (uint32_t)(r * AHS + ch * 8) * 2,
                 Kp + kbase + (size_t)r * QKV_N + ch * 8);
            cp16(vB + (uint32_t)(r * AHS + ch * 8) * 2,
                 Vp + kbase + (size_t)r * QKV_N + ch * 8);
        }
        cp_commit();
    };

    float m0 = -CUDART_INF_F, m1 = -CUDART_INF_F;
    float l0 = 0.f, l1 = 0.f;
    float o[8][4];
    #pragma unroll
    for (int nt = 0; nt < 8; nt++)
        #pragma unroll
        for (int r = 0; r < 4; r++) o[nt][r] = 0.f;

    const uint32_t sPw = sP + (uint32_t)(warp * 16 * AHS) * 2;
    __half* prow = Ps + warp * 16 * AHS;

    load_kv(0, 0);

    for (int jt = 0; jt <= qb; jt++) {
        cp_wait<0>();
        __syncthreads();          // KV(jt) ready AND all warps done with buffer being refilled
        if (jt < qb) load_kv(jt + 1, (jt + 1) & 1);

        uint32_t sK = sK0 + (uint32_t)((jt & 1) * AKV) * 2;
        uint32_t sV = sV0 + (uint32_t)((jt & 1) * AKV) * 2;

        // S = Q K^T
        float s[8][4];
        #pragma unroll
        for (int nt = 0; nt < 8; nt++)
            #pragma unroll
            for (int r = 0; r < 4; r++) s[nt][r] = 0.f;

        #pragma unroll
        for (int ks = 0; ks < 4; ks++) {
            int k0 = ks * 16;
            uint32_t a0, a1, a2, a3;
            ldsm_x4(a0, a1, a2, a3,
                    sQ + (uint32_t)((warp * 16 + (lane & 15)) * AHS
                                    + k0 + ((lane >> 4) << 3)) * 2);
            #pragma unroll
            for (int np = 0; np < 4; np++) {
                int n = np * 16 + ((lane >> 4) << 3) + (lane & 7);
                int koff = ((lane >> 3) & 1) << 3;
                uint32_t b0, b1, b2, b3;
                ldsm_x4(b0, b1, b2, b3,
                        sK + (uint32_t)(n * AHS + k0 + koff) * 2);
                mma_f16(s[np * 2][0], s[np * 2][1], s[np * 2][2], s[np * 2][3],
                        a0, a1, a2, a3, b0, b1);
                mma_f16(s[np * 2 + 1][0], s[np * 2 + 1][1], s[np * 2 + 1][2], s[np * 2 + 1][3],
                        a0, a1, a2, a3, b2, b3);
            }
        }

        const float scale = 0.125f;
        bool diag = (jt == qb);
        int row0 = warp * 16 + lq;
        #pragma unroll
        for (int nt = 0; nt < 8; nt++) {
            int col = nt * 8 + 2 * lr;
            s[nt][0] *= scale; s[nt][1] *= scale;
            s[nt][2] *= scale; s[nt][3] *= scale;
            if (diag) {
                if (col     > row0)     s[nt][0] = -CUDART_INF_F;
                if (col + 1 > row0)     s[nt][1] = -CUDART_INF_F;
                if (col     > row0 + 8) s[nt][2] = -CUDART_INF_F;
                if (col + 1 > row0 + 8) s[nt][3] = -CUDART_INF_F;
            }
        }

        {
            float rm = -CUDART_INF_F;
            #pragma unroll
            for (int nt = 0; nt < 8; nt++) rm = fmaxf(rm, fmaxf(s[nt][0], s[nt][1]));
            rm = fmaxf(rm, __shfl_xor_sync(0xffffffffu, rm, 1));
            rm = fmaxf(rm, __shfl_xor_sync(0xffffffffu, rm, 2));
            float mn = fmaxf(m0, rm);
            float alpha = __expf(m0 - mn);
            float ps = 0.f;
            #pragma unroll
            for (int nt = 0; nt < 8; nt++) {
                s[nt][0] = __expf(s[nt][0] - mn);
                s[nt][1] = __expf(s[nt][1] - mn);
                ps += s[nt][0] + s[nt][1];
            }
            ps += __shfl_xor_sync(0xffffffffu, ps, 1);
            ps += __shfl_xor_sync(0xffffffffu, ps, 2);
            l0 = l0 * alpha + ps;
            m0 = mn;
            #pragma unroll
            for (int nt = 0; nt < 8; nt++) { o[nt][0] *= alpha; o[nt][1] *= alpha; }
        }
        {
            float rm = -CUDART_INF_F;
            #pragma unroll
            for (int nt = 0; nt < 8; nt++) rm = fmaxf(rm, fmaxf(s[nt][2], s[nt][3]));
            rm = fmaxf(rm, __shfl_xor_sync(0xffffffffu, rm, 1));
            rm = fmaxf(rm, __shfl_xor_sync(0xffffffffu, rm, 2));
            float mn = fmaxf(m1, rm);
            float alpha = __expf(m1 - mn);
            float ps = 0.f;
            #pragma unroll
            for (int nt = 0; nt < 8; nt++) {
                s[nt][2] = __expf(s[nt][2] - mn);
                s[nt][3] = __expf(s[nt][3] - mn);
                ps += s[nt][2] + s[nt][3];
            }
            ps += __shfl_xor_sync(0xffffffffu, ps, 1);
            ps += __shfl_xor_sync(0xffffffffu, ps, 2);
            l1 = l1 * alpha + ps;
            m1 = mn;
            #pragma unroll
            for (int nt = 0; nt < 8; nt++) { o[nt][2] *= alpha; o[nt][3] *= alpha; }
        }

        #pragma unroll
        for (int nt = 0; nt < 8; nt++) {
            *(__half2*)(prow + lq * AHS + nt * 8 + 2 * lr) =
                __floats2half2_rn(s[nt][0], s[nt][1]);
            *(__half2*)(prow + (lq + 8) * AHS + nt * 8 + 2 * lr) =
                __floats2half2_rn(s[nt][2], s[nt][3]);
        }
        __syncwarp();

        #pragma unroll
        for (int ks = 0; ks < 4; ks++) {
            int k0 = ks * 16;
            uint32_t a0, a1, a2, a3;
            ldsm_x4(a0, a1, a2, a3,
                    sPw + (uint32_t)((lane & 15) * AHS + k0 + ((lane >> 4) << 3)) * 2);
            #pragma unroll
            for (int dp = 0; dp < 4; dp++) {
                uint32_t b0, b1, b2, b3;
                ldsm_x4t(b0, b1, b2, b3,
                         sV + (uint32_t)((k0 + (lane & 15)) * AHS
                                         + dp * 16 + ((lane >> 4) << 3)) * 2);
                mma_f16(o[dp * 2][0], o[dp * 2][1], o[dp * 2][2], o[dp * 2][3],
                        a0, a1, a2, a3, b0, b1);
                mma_f16(o[dp * 2 + 1][0], o[dp * 2 + 1][1], o[dp * 2 + 1][2], o[dp * 2 + 1][3],
                        a0, a1, a2, a3, b2, b3);
            }
        }
        __syncwarp();
    }

    float inv0 = 1.0f / l0, inv1 = 1.0f / l1;
    size_t r0 = (size_t)(bb * TSEQ + qb * 64 + warp * 16 + lq);
    size_t r1 = r0 + 8;
    #pragma unroll
    for (int nt = 0; nt < 8; nt++) {
        int col = h * HEADD + nt * 8 + 2 * lr;
        *(__half2*)(Out + r0 * EMB + col) = __floats2half2_rn(o[nt][0] * inv0, o[nt][1] * inv0);
        *(__half2*)(Out + r1 * EMB + col) = __floats2half2_rn(o[nt][2] * inv1, o[nt][3] * inv1);
    }
}

// ---------------------------------------------------------------------------
// Launch
// ---------------------------------------------------------------------------
extern "C" void kernel_launch(void* const* d_in, const int* in_sizes, int n_in,
                              void* d_out, int out_size)
{
    const float* x      = (const float*)d_in[0];
    const float* ln1_g  = (const float*)d_in[1];
    const float* ln1_b  = (const float*)d_in[2];
    const float* wq     = (const float*)d_in[3];
    const float* wk     = (const float*)d_in[4];
    const float* wv     = (const float*)d_in[5];
    const float* w_proj = (const float*)d_in[6];
    const float* b_proj = (const float*)d_in[7];
    const float* ln2_g  = (const float*)d_in[8];
    const float* ln2_b  = (const float*)d_in[9];
    const float* w1     = (const float*)d_in[10];
    const float* b1     = (const float*)d_in[11];
    const float* w2     = (const float*)d_in[12];
    const float* b2     = (const float*)d_in[13];
    float* out = (float*)d_out;

    __half *h, *qkv, *attn, *mid;
    float  *out1;
    __half *wqkvT, *wpT, *w1T, *w2T;
    cudaGetSymbolAddress((void**)&h,     g_h);
    cudaGetSymbolAddress((void**)&qkv,   g_qkv);
    cudaGetSymbolAddress((void**)&attn,  g_attn);
    cudaGetSymbolAddress((void**)&out1,  g_out1);
    cudaGetSymbolAddress((void**)&mid,   g_mid);
    cudaGetSymbolAddress((void**)&wqkvT, g_wqkvT);
    cudaGetSymbolAddress((void**)&wpT,   g_wpT);
    cudaGetSymbolAddress((void**)&w1T,   g_w1T);
    cudaGetSymbolAddress((void**)&w2T,   g_w2T);

    cudaFuncSetAttribute(gemm_h_kernel<false, false>,
                         cudaFuncAttributeMaxDynamicSharedMemorySize, G2_SMEM);
    cudaFuncSetAttribute(gemm_h_kernel<false, true>,
                         cudaFuncAttributeMaxDynamicSharedMemorySize, G2_SMEM);
    cudaFuncSetAttribute(gemm_h_kernel<true, true>,
                         cudaFuncAttributeMaxDynamicSharedMemorySize, G2_SMEM);
    cudaFuncSetAttribute(attn_h_kernel,
                         cudaFuncAttributeMaxDynamicSharedMemorySize, AH_SMEM);

    // 0. All 6 weight transposes in one launch
    TransArgs ta;
    ta.in[0] = wq;     ta.out[0] = wqkvT;                         ta.K[0] = EMB;   ta.N[0] = EMB;
    ta.in[1] = wk;     ta.out[1] = wqkvT + (size_t)EMB * EMB;     ta.K[1] = EMB;   ta.N[1] = EMB;
    ta.in[2] = wv;     ta.out[2] = wqkvT + (size_t)2 * EMB * EMB; ta.K[2] = EMB;   ta.N[2] = EMB;
    ta.in[3] = w_proj; ta.out[3] = wpT;                           ta.K[3] = EMB;   ta.N[3] = EMB;
    ta.in[4] = w1;     ta.out[4] = w1T;                           ta.K[4] = EMB;   ta.N[4] = FFDIM;
    ta.in[5] = w2;     ta.out[5] = w2T;                           ta.K[5] = FFDIM; ta.N[5] = EMB;
    int total = 0;
    for (int i = 0; i < 6; i++) {
        ta.off[i] = total;
        total += (ta.N[i] / 32) * (ta.K[i] / 32);
    }
    transpose6_kernel<<<total, dim3(32, 8)>>>(ta);

    // 1. LN1 -> half
    ln_kernel<<<MROWS, 256>>>(x, ln1_g, ln1_b, h);

    // 2. Fused QKV projection
    dim3 gQKV(QKV_N / 256, MROWS / 128);
    gemm_h_kernel<false, true><<<gQKV, 256, G2_SMEM>>>(h, wqkvT, nullptr, nullptr, qkv, QKV_N, EMB);

    // 3. Causal flash attention (double-buffered KV)
    attn_h_kernel<<<dim3(TSEQ / 64, NHEAD, BSZ), 128, AH_SMEM>>>(qkv, attn);

    // 4. out1 = x + attn @ w_proj + b_proj
    dim3 gE(EMB / 256, MROWS / 128);
    gemm_h_kernel<false, false><<<gE, 256, G2_SMEM>>>(attn, wpT, b_proj, x, out1, EMB, EMB);

    // 5. LN2 -> half
    ln_kernel<<<MROWS, 256>>>(out1, ln2_g, ln2_b, h);

    // 6. mid = gelu(h @ w1 + b1)
    dim3 gF(FFDIM / 256, MROWS / 128);
    gemm_h_kernel<true, true><<<gF, 256, G2_SMEM>>>(h, w1T, b1, nullptr, mid, FFDIM, EMB);

    // 7. out = out1 + mid @ w2 + b2
    gemm_h_kernel<false, false><<<gE, 256, G2_SMEM>>>(mid, w2T, b2, out1, out, EMB, FFDIM);
}

// round 12
// speedup vs baseline: 6.1291x; 1.0573x over previous
#include <cuda_runtime.h>
#include <cuda_fp16.h>
#include <math_constants.h>
#include <math.h>
#include <stdint.h>

#define BSZ   8
#define TSEQ  1024
#define EMB   1024
#define NHEAD 16
#define HEADD 64
#define MROWS (BSZ * TSEQ)   // 8192
#define FFDIM 4096
#define QKV_N 3072

// ---------------------------------------------------------------------------
// Scratch
// ---------------------------------------------------------------------------
__device__ __half g_h    [(size_t)MROWS * EMB];
__device__ __half g_qkv  [(size_t)MROWS * QKV_N];
__device__ __half g_attn [(size_t)MROWS * EMB];
__device__ float  g_out1 [(size_t)MROWS * EMB];
__device__ __half g_mid  [(size_t)MROWS * FFDIM];
__device__ __half g_wqkvT[(size_t)QKV_N * EMB];
__device__ __half g_wpT  [(size_t)EMB * EMB];
__device__ __half g_w1T  [(size_t)EMB * FFDIM];
__device__ __half g_w2T  [(size_t)FFDIM * EMB];

// ---------------------------------------------------------------------------
// Helpers
// ---------------------------------------------------------------------------
__device__ __forceinline__ uint32_t smem_u32(const void* p) {
    uint32_t a;
    asm("{ .reg .u64 t; cvta.to.shared.u64 t, %1; cvt.u32.u64 %0, t; }" : "=r"(a) : "l"(p));
    return a;
}

__device__ __forceinline__ void cp16(uint32_t dst, const void* src) {
    asm volatile("cp.async.cg.shared.global [%0], [%1], 16;" :: "r"(dst), "l"(src) : "memory");
}
__device__ __forceinline__ void cp_commit() {
    asm volatile("cp.async.commit_group;" ::: "memory");
}
template<int N>
__device__ __forceinline__ void cp_wait() {
    asm volatile("cp.async.wait_group %0;" :: "n"(N) : "memory");
}

__device__ __forceinline__ void ldsm_x4(uint32_t& r0, uint32_t& r1, uint32_t& r2, uint32_t& r3,
                                        uint32_t addr) {
    asm volatile("ldmatrix.sync.aligned.m8n8.x4.shared.b16 {%0,%1,%2,%3}, [%4];"
                 : "=r"(r0), "=r"(r1), "=r"(r2), "=r"(r3) : "r"(addr));
}
__device__ __forceinline__ void ldsm_x4t(uint32_t& r0, uint32_t& r1, uint32_t& r2, uint32_t& r3,
                                         uint32_t addr) {
    asm volatile("ldmatrix.sync.aligned.m8n8.x4.trans.shared.b16 {%0,%1,%2,%3}, [%4];"
                 : "=r"(r0), "=r"(r1), "=r"(r2), "=r"(r3) : "r"(addr));
}

__device__ __forceinline__ void mma_f16(float& c0, float& c1, float& c2, float& c3,
                                        uint32_t a0, uint32_t a1, uint32_t a2, uint32_t a3,
                                        uint32_t b0, uint32_t b1) {
    asm volatile(
        "mma.sync.aligned.m16n8k16.row.col.f32.f16.f16.f32 "
        "{%0,%1,%2,%3}, {%4,%5,%6,%7}, {%8,%9}, {%0,%1,%2,%3};"
        : "+f"(c0), "+f"(c1), "+f"(c2), "+f"(c3)
        : "r"(a0), "r"(a1), "r"(a2), "r"(a3), "r"(b0), "r"(b1));
}

// Fast GELU: tanh-form with HW tanh.approx (sm_75+)
__device__ __forceinline__ float gelu_fast(float x) {
    float u = x * (0.7978845608028654f + 0.035677408136300125f * x * x);
    float t;
    asm("tanh.approx.f32 %0, %1;" : "=f"(t) : "f"(u));
    return 0.5f * x * (1.0f + t);
}

// ---------------------------------------------------------------------------
// Batched transpose + fp16 of all 6 weight matrices in ONE launch.
// ---------------------------------------------------------------------------
struct TransArgs {
    const float* in[6];
    __half*      out[6];
    int K[6], N[6];
    int off[6];
};

__global__ __launch_bounds__(256)
void transpose6_kernel(TransArgs A)
{
    __shared__ float t[32][33];
    int tb = blockIdx.x;
    int m = 0;
    #pragma unroll
    for (int i = 1; i < 6; i++) if (tb >= A.off[i]) m = i;
    int lt = tb - A.off[m];
    int N = A.N[m], K = A.K[m];
    int ntx = N >> 5;
    int n0 = (lt % ntx) * 32, k0 = (lt / ntx) * 32;
    const float* in = A.in[m];
    __half* out = A.out[m];

    int tx = threadIdx.x, ty = threadIdx.y;
    #pragma unroll
    for (int i = 0; i < 32; i += 8)
        t[ty + i][tx] = in[(size_t)(k0 + ty + i) * N + n0 + tx];
    __syncthreads();
    #pragma unroll
    for (int i = 0; i < 32; i += 8)
        out[(size_t)(n0 + ty + i) * K + k0 + tx] = __float2half_rn(t[tx][ty + i]);
}

// ---------------------------------------------------------------------------
// LayerNorm: float in -> half out
// ---------------------------------------------------------------------------
__global__ __launch_bounds__(256)
void ln_kernel(const float* __restrict__ x, const float* __restrict__ g,
               const float* __restrict__ b, __half* __restrict__ out)
{
    int row = blockIdx.x;
    int t   = threadIdx.x;
    const float4* xr = (const float4*)(x + (size_t)row * EMB);
    float4 v = xr[t];
    float s  = v.x + v.y + v.z + v.w;
    float ss = v.x * v.x + v.y * v.y + v.z * v.z + v.w * v.w;
    #pragma unroll
    for (int o = 16; o; o >>= 1) {
        s  += __shfl_xor_sync(0xffffffffu, s,  o);
        ss += __shfl_xor_sync(0xffffffffu, ss, o);
    }
    __shared__ float rs_[8], rss_[8];
    __shared__ float mu_s, rstd_s;
    int warp = t >> 5, lane = t & 31;
    if (lane == 0) { rs_[warp] = s; rss_[warp] = ss; }
    __syncthreads();
    if (t == 0) {
        float S = 0.f, SS = 0.f;
        #pragma unroll
        for (int i = 0; i < 8; i++) { S += rs_[i]; SS += rss_[i]; }
        float mu  = S * (1.0f / EMB);
        float var = SS * (1.0f / EMB) - mu * mu;
        mu_s = mu;
        rstd_s = rsqrtf(var + 1e-5f);
    }
    __syncthreads();
    float mu = mu_s, r = rstd_s;
    float4 gv = ((const float4*)g)[t];
    float4 bv = ((const float4*)b)[t];
    __half2* orow = (__half2*)(out + (size_t)row * EMB);
    orow[2 * t]     = __floats2half2_rn((v.x - mu) * r * gv.x + bv.x,
                                        (v.y - mu) * r * gv.y + bv.y);
    orow[2 * t + 1] = __floats2half2_rn((v.z - mu) * r * gv.z + bv.z,
                                        (v.w - mu) * r * gv.w + bv.w);
}

// ---------------------------------------------------------------------------
// fp16 mma GEMM: CTA 128x256, BK=32, 8 warps (64x64), 3-stage cp.async.
// ---------------------------------------------------------------------------
#define G2_STRIDE 40
#define G2_ATILE (128 * G2_STRIDE * 2)
#define G2_BTILE (256 * G2_STRIDE * 2)
#define G2_STAGE (G2_ATILE + G2_BTILE)
#define G2_SMEM  (3 * G2_STAGE)          // 92160 B

template<bool GELU, bool HALF_OUT>
__global__ __launch_bounds__(256)
void gemm_h_kernel(const __half* __restrict__ A, const __half* __restrict__ Bt,
                   const float* __restrict__ bias, const float* __restrict__ res,
                   void* __restrict__ Cv, int N_, int K_)
{
    extern __shared__ char smem[];
    const uint32_t sb = smem_u32(smem);
    int tid  = threadIdx.x;
    int lane = tid & 31, warp = tid >> 5;
    int wm = warp >> 2;
    int wn = warp & 3;
    int rowBase = blockIdx.y * 128;
    int colBase = blockIdx.x * 256;
    const int C_CHUNKS = K_ >> 5;

    auto load_chunk = [&](int c, int st) {
        int k0 = c << 5;
        uint32_t aB = sb + st * G2_STAGE;
        uint32_t bB = aB + G2_ATILE;
        #pragma unroll
        for (int s = 0; s < 2; s++) {
            int idx = tid + s * 256;
            int r = idx >> 2, ch = idx & 3;
            cp16(aB + (uint32_t)(r * G2_STRIDE + ch * 8) * 2,
                 A + (size_t)(rowBase + r) * K_ + k0 + ch * 8);
        }
        #pragma unroll
        for (int s = 0; s < 4; s++) {
            int idx = tid + s * 256;
            int r = idx >> 2, ch = idx & 3;
            cp16(bB + (uint32_t)(r * G2_STRIDE + ch * 8) * 2,
                 Bt + (size_t)(colBase + r) * K_ + k0 + ch * 8);
        }
        cp_commit();
    };

    float acc[4][8][4];
    #pragma unroll
    for (int i = 0; i < 4; i++)
        #pragma unroll
        for (int j = 0; j < 8; j++)
            #pragma unroll
            for (int r = 0; r < 4; r++) acc[i][j][r] = 0.f;

    load_chunk(0, 0);
    load_chunk(1, 1);

    for (int c = 0; c < C_CHUNKS; c++) {
        if (c + 2 < C_CHUNKS) load_chunk(c + 2, (c + 2) % 3);
        else cp_commit();
        cp_wait<2>();
        __syncthreads();

        int st = c % 3;
        uint32_t aBase = sb + st * G2_STAGE;
        uint32_t bBase = aBase + G2_ATILE;

        #pragma unroll
        for (int ks = 0; ks < 2; ks++) {
            int k0 = ks * 16;
            uint32_t a[4][4];
            #pragma unroll
            for (int mt = 0; mt < 4; mt++) {
                uint32_t addr = aBase +
                    (uint32_t)((wm * 64 + mt * 16 + (lane & 15)) * G2_STRIDE
                               + k0 + ((lane >> 4) << 3)) * 2;
                ldsm_x4(a[mt][0], a[mt][1], a[mt][2], a[mt][3], addr);
            }
            uint32_t bf[8][2];
            #pragma unroll
            for (int np = 0; np < 4; np++) {
                int n = wn * 64 + np * 16 + ((lane >> 4) << 3) + (lane & 7);
                int koff = ((lane >> 3) & 1) << 3;
                uint32_t addr = bBase + (uint32_t)(n * G2_STRIDE + k0 + koff) * 2;
                ldsm_x4(bf[np * 2][0], bf[np * 2][1], bf[np * 2 + 1][0], bf[np * 2 + 1][1], addr);
            }
            #pragma unroll
            for (int mt = 0; mt < 4; mt++)
                #pragma unroll
                for (int nt = 0; nt < 8; nt++)
                    mma_f16(acc[mt][nt][0], acc[mt][nt][1], acc[mt][nt][2], acc[mt][nt][3],
                            a[mt][0], a[mt][1], a[mt][2], a[mt][3],
                            bf[nt][0], bf[nt][1]);
        }
        __syncthreads();
    }

    int lq = lane >> 2, lr = lane & 3;
    __half* Ch = (__half*)Cv;
    float*  Cf = (float*)Cv;
    #pragma unroll
    for (int mt = 0; mt < 4; mt++) {
        int row0 = rowBase + wm * 64 + mt * 16 + lq;
        #pragma unroll
        for (int nt = 0; nt < 8; nt++) {
            int col = colBase + wn * 64 + nt * 8 + lr * 2;
            float2 p0 = make_float2(acc[mt][nt][0], acc[mt][nt][1]);
            float2 p1 = make_float2(acc[mt][nt][2], acc[mt][nt][3]);
            if (bias) {
                float2 bv = *(const float2*)(bias + col);
                p0.x += bv.x; p0.y += bv.y;
                p1.x += bv.x; p1.y += bv.y;
            }
            if (res) {
                float2 r0 = *(const float2*)(res + (size_t)row0 * N_ + col);
                float2 r1 = *(const float2*)(res + (size_t)(row0 + 8) * N_ + col);
                p0.x += r0.x; p0.y += r0.y;
                p1.x += r1.x; p1.y += r1.y;
            }
            if (GELU) {
                p0.x = gelu_fast(p0.x);
                p0.y = gelu_fast(p0.y);
                p1.x = gelu_fast(p1.x);
                p1.y = gelu_fast(p1.y);
            }
            if (HALF_OUT) {
                *(__half2*)(Ch + (size_t)row0 * N_ + col) = __floats2half2_rn(p0.x, p0.y);
                *(__half2*)(Ch + (size_t)(row0 + 8) * N_ + col) = __floats2half2_rn(p1.x, p1.y);
            } else {
                *(float2*)(Cf + (size_t)row0 * N_ + col) = p0;
                *(float2*)(Cf + (size_t)(row0 + 8) * N_ + col) = p1;
            }
        }
    }
}

// ---------------------------------------------------------------------------
// fp16 flash attention, cp.async double-buffered K/V.
// Each CTA processes TWO Q tiles (qb0 and 15-qb0) -> uniform 17 KV iterations.
// ---------------------------------------------------------------------------
#define AHS 72
#define AKV (64 * AHS)
#define AH_SMEM (6 * AKV * 2)             // 55296 B

__global__ __launch_bounds__(128)
void attn_h_kernel(const __half* __restrict__ QKV, __half* __restrict__ Out)
{
    extern __shared__ char smraw[];
    __half* sm = (__half*)smraw;
    __half* Qs = sm;
    __half* Ks = sm + AKV;
    __half* Vs = sm + 3 * AKV;
    __half* Ps = sm + 5 * AKV;
    const uint32_t sQ = smem_u32(Qs), sK0 = smem_u32(Ks), sV0 = smem_u32(Vs),
                   sP = smem_u32(Ps);

    int qb0 = blockIdx.x, h = blockIdx.y, bb = blockIdx.z;
    int tid = threadIdx.x;
    int lane = tid & 31, warp = tid >> 5;
    int lq = lane >> 2, lr = lane & 3;

    const __half* Qp = QKV + h * HEADD;
    const __half* Kp = QKV + EMB + h * HEADD;
    const __half* Vp = QKV + 2 * EMB + h * HEADD;

    auto load_kv = [&](int jt, int b) {
        size_t kbase = (size_t)(bb * TSEQ + jt * 64) * QKV_N;
        uint32_t kB = sK0 + (uint32_t)(b * AKV) * 2;
        uint32_t vB = sV0 + (uint32_t)(b * AKV) * 2;
        #pragma unroll
        for (int s = 0; s < 4; s++) {
            int idx = tid + s * 128;
            int r = idx >> 3, ch = idx & 7;
            cp16(kB + (uint32_t)(r * AHS + ch * 8) * 2,
                 Kp + kbase + (size_t)r * QKV_N + ch * 8);
            cp16(vB + (uint32_t)(r * AHS + ch * 8) * 2,
                 Vp + kbase + (size_t)r * QKV_N + ch * 8);
        }
        cp_commit();
    };

    const uint32_t sPw = sP + (uint32_t)(warp * 16 * AHS) * 2;
    __half* prow = Ps + warp * 16 * AHS;

    #pragma unroll
    for (int rep = 0; rep < 2; rep++) {
        int qb = rep ? (TSEQ / 64 - 1 - qb0) : qb0;

        __syncthreads();   // all warps done with prior rep's smem

        // Load Q tile
        size_t qbase = (size_t)(bb * TSEQ + qb * 64) * QKV_N;
        #pragma unroll
        for (int s = 0; s < 4; s++) {
            int idx = tid + s * 128;
            int r = idx >> 3, ch = idx & 7;
            *(float4*)(Qs + r * AHS + ch * 8) =
                *(const float4*)(Qp + qbase + (size_t)r * QKV_N + ch * 8);
        }
        load_kv(0, 0);

        float m0 = -CUDART_INF_F, m1 = -CUDART_INF_F;
        float l0 = 0.f, l1 = 0.f;
        float o[8][4];
        #pragma unroll
        for (int nt = 0; nt < 8; nt++)
            #pragma unroll
            for (int r = 0; r < 4; r++) o[nt][r] = 0.f;

        for (int jt = 0; jt <= qb; jt++) {
            cp_wait<0>();
            __syncthreads();
            if (jt < qb) load_kv(jt + 1, (jt + 1) & 1);

            uint32_t sK = sK0 + (uint32_t)((jt & 1) * AKV) * 2;
            uint32_t sV = sV0 + (uint32_t)((jt & 1) * AKV) * 2;

            float s[8][4];
            #pragma unroll
            for (int nt = 0; nt < 8; nt++)
                #pragma unroll
                for (int r = 0; r < 4; r++) s[nt][r] = 0.f;

            #pragma unroll
            for (int ks = 0; ks < 4; ks++) {
                int k0 = ks * 16;
                uint32_t a0, a1, a2, a3;
                ldsm_x4(a0, a1, a2, a3,
                        sQ + (uint32_t)((warp * 16 + (lane & 15)) * AHS
                                        + k0 + ((lane >> 4) << 3)) * 2);
                #pragma unroll
                for (int np = 0; np < 4; np++) {
                    int n = np * 16 + ((lane >> 4) << 3) + (lane & 7);
                    int koff = ((lane >> 3) & 1) << 3;
                    uint32_t b0, b1, b2, b3;
                    ldsm_x4(b0, b1, b2, b3,
                            sK + (uint32_t)(n * AHS + k0 + koff) * 2);
                    mma_f16(s[np * 2][0], s[np * 2][1], s[np * 2][2], s[np * 2][3],
                            a0, a1, a2, a3, b0, b1);
                    mma_f16(s[np * 2 + 1][0], s[np * 2 + 1][1], s[np * 2 + 1][2], s[np * 2 + 1][3],
                            a0, a1, a2, a3, b2, b3);
                }
            }

            const float scale = 0.125f;
            bool diag = (jt == qb);
            int row0 = warp * 16 + lq;
            #pragma unroll
            for (int nt = 0; nt < 8; nt++) {
                int col = nt * 8 + 2 * lr;
                s[nt][0] *= scale; s[nt][1] *= scale;
                s[nt][2] *= scale; s[nt][3] *= scale;
                if (diag) {
                    if (col     > row0)     s[nt][0] = -CUDART_INF_F;
                    if (col + 1 > row0)     s[nt][1] = -CUDART_INF_F;
                    if (col     > row0 + 8) s[nt][2] = -CUDART_INF_F;
                    if (col + 1 > row0 + 8) s[nt][3] = -CUDART_INF_F;
                }
            }

            {
                float rm = -CUDART_INF_F;
                #pragma unroll
                for (int nt = 0; nt < 8; nt++) rm = fmaxf(rm, fmaxf(s[nt][0], s[nt][1]));
                rm = fmaxf(rm, __shfl_xor_sync(0xffffffffu, rm, 1));
                rm = fmaxf(rm, __shfl_xor_sync(0xffffffffu, rm, 2));
                float mn = fmaxf(m0, rm);
                float alpha = __expf(m0 - mn);
                float ps = 0.f;
                #pragma unroll
                for (int nt = 0; nt < 8; nt++) {
                    s[nt][0] = __expf(s[nt][0] - mn);
                    s[nt][1] = __expf(s[nt][1] - mn);
                    ps += s[nt][0] + s[nt][1];
                }
                ps += __shfl_xor_sync(0xffffffffu, ps, 1);
                ps += __shfl_xor_sync(0xffffffffu, ps, 2);
                l0 = l0 * alpha + ps;
                m0 = mn;
                #pragma unroll
                for (int nt = 0; nt < 8; nt++) { o[nt][0] *= alpha; o[nt][1] *= alpha; }
            }
            {
                float rm = -CUDART_INF_F;
                #pragma unroll
                for (int nt = 0; nt < 8; nt++) rm = fmaxf(rm, fmaxf(s[nt][2], s[nt][3]));
                rm = fmaxf(rm, __shfl_xor_sync(0xffffffffu, rm, 1));
                rm = fmaxf(rm, __shfl_xor_sync(0xffffffffu, rm, 2));
                float mn = fmaxf(m1, rm);
                float alpha = __expf(m1 - mn);
                float ps = 0.f;
                #pragma unroll
                for (int nt = 0; nt < 8; nt++) {
                    s[nt][2] = __expf(s[nt][2] - mn);
                    s[nt][3] = __expf(s[nt][3] - mn);
                    ps += s[nt][2] + s[nt][3];
                }
                ps += __shfl_xor_sync(0xffffffffu, ps, 1);
                ps += __shfl_xor_sync(0xffffffffu, ps, 2);
                l1 = l1 * alpha + ps;
                m1 = mn;
                #pragma unroll
                for (int nt = 0; nt < 8; nt++) { o[nt][2] *= alpha; o[nt][3] *= alpha; }
            }

            #pragma unroll
            for (int nt = 0; nt < 8; nt++) {
                *(__half2*)(prow + lq * AHS + nt * 8 + 2 * lr) =
                    __floats2half2_rn(s[nt][0], s[nt][1]);
                *(__half2*)(prow + (lq + 8) * AHS + nt * 8 + 2 * lr) =
                    __floats2half2_rn(s[nt][2], s[nt][3]);
            }
            __syncwarp();

            #pragma unroll
            for (int ks = 0; ks < 4; ks++) {
                int k0 = ks * 16;
                uint32_t a0, a1, a2, a3;
                ldsm_x4(a0, a1, a2, a3,
                        sPw + (uint32_t)((lane & 15) * AHS + k0 + ((lane >> 4) << 3)) * 2);
                #pragma unroll
                for (int dp = 0; dp < 4; dp++) {
                    uint32_t b0, b1, b2, b3;
                    ldsm_x4t(b0, b1, b2, b3,
                             sV + (uint32_t)((k0 + (lane & 15)) * AHS
                                             + dp * 16 + ((lane >> 4) << 3)) * 2);
                    mma_f16(o[dp * 2][0], o[dp * 2][1], o[dp * 2][2], o[dp * 2][3],
                            a0, a1, a2, a3, b0, b1);
                    mma_f16(o[dp * 2 + 1][0], o[dp * 2 + 1][1], o[dp * 2 + 1][2], o[dp * 2 + 1][3],
                            a0, a1, a2, a3, b2, b3);
                }
            }
            __syncwarp();
        }

        float inv0 = 1.0f / l0, inv1 = 1.0f / l1;
        size_t r0 = (size_t)(bb * TSEQ + qb * 64 + warp * 16 + lq);
        size_t r1 = r0 + 8;
        #pragma unroll
        for (int nt = 0; nt < 8; nt++) {
            int col = h * HEADD + nt * 8 + 2 * lr;
            *(__half2*)(Out + r0 * EMB + col) =
                __floats2half2_rn(o[nt][0] * inv0, o[nt][1] * inv0);
            *(__half2*)(Out + r1 * EMB + col) =
                __floats2half2_rn(o[nt][2] * inv1, o[nt][3] * inv1);
        }
    }
}

// ---------------------------------------------------------------------------
// Launch
// ---------------------------------------------------------------------------
extern "C" void kernel_launch(void* const* d_in, const int* in_sizes, int n_in,
                              void* d_out, int out_size)
{
    const float* x      = (const float*)d_in[0];
    const float* ln1_g  = (const float*)d_in[1];
    const float* ln1_b  = (const float*)d_in[2];
    const float* wq     = (const float*)d_in[3];
    const float* wk     = (const float*)d_in[4];
    const float* wv     = (const float*)d_in[5];
    const float* w_proj = (const float*)d_in[6];
    const float* b_proj = (const float*)d_in[7];
    const float* ln2_g  = (const float*)d_in[8];
    const float* ln2_b  = (const float*)d_in[9];
    const float* w1     = (const float*)d_in[10];
    const float* b1     = (const float*)d_in[11];
    const float* w2     = (const float*)d_in[12];
    const float* b2     = (const float*)d_in[13];
    float* out = (float*)d_out;

    __half *h, *qkv, *attn, *mid;
    float  *out1;
    __half *wqkvT, *wpT, *w1T, *w2T;
    cudaGetSymbolAddress((void**)&h,     g_h);
    cudaGetSymbolAddress((void**)&qkv,   g_qkv);
    cudaGetSymbolAddress((void**)&attn,  g_attn);
    cudaGetSymbolAddress((void**)&out1,  g_out1);
    cudaGetSymbolAddress((void**)&mid,   g_mid);
    cudaGetSymbolAddress((void**)&wqkvT, g_wqkvT);
    cudaGetSymbolAddress((void**)&wpT,   g_wpT);
    cudaGetSymbolAddress((void**)&w1T,   g_w1T);
    cudaGetSymbolAddress((void**)&w2T,   g_w2T);

    cudaFuncSetAttribute(gemm_h_kernel<false, false>,
                         cudaFuncAttributeMaxDynamicSharedMemorySize, G2_SMEM);
    cudaFuncSetAttribute(gemm_h_kernel<false, true>,
                         cudaFuncAttributeMaxDynamicSharedMemorySize, G2_SMEM);
    cudaFuncSetAttribute(gemm_h_kernel<true, true>,
                         cudaFuncAttributeMaxDynamicSharedMemorySize, G2_SMEM);
    cudaFuncSetAttribute(attn_h_kernel,
                         cudaFuncAttributeMaxDynamicSharedMemorySize, AH_SMEM);

    // 0. All 6 weight transposes in one launch
    TransArgs ta;
    ta.in[0] = wq;     ta.out[0] = wqkvT;                         ta.K[0] = EMB;   ta.N[0] = EMB;
    ta.in[1] = wk;     ta.out[1] = wqkvT + (size_t)EMB * EMB;     ta.K[1] = EMB;   ta.N[1] = EMB;
    ta.in[2] = wv;     ta.out[2] = wqkvT + (size_t)2 * EMB * EMB; ta.K[2] = EMB;   ta.N[2] = EMB;
    ta.in[3] = w_proj; ta.out[3] = wpT;                           ta.K[3] = EMB;   ta.N[3] = EMB;
    ta.in[4] = w1;     ta.out[4] = w1T;                           ta.K[4] = EMB;   ta.N[4] = FFDIM;
    ta.in[5] = w2;     ta.out[5] = w2T;                           ta.K[5] = FFDIM; ta.N[5] = EMB;
    int total = 0;
    for (int i = 0; i < 6; i++) {
        ta.off[i] = total;
        total += (ta.N[i] / 32) * (ta.K[i] / 32);
    }
    transpose6_kernel<<<total, dim3(32, 8)>>>(ta);

    // 1. LN1 -> half
    ln_kernel<<<MROWS, 256>>>(x, ln1_g, ln1_b, h);

    // 2. Fused QKV projection
    dim3 gQKV(QKV_N / 256, MROWS / 128);
    gemm_h_kernel<false, true><<<gQKV, 256, G2_SMEM>>>(h, wqkvT, nullptr, nullptr, qkv, QKV_N, EMB);

    // 3. Causal flash attention (2 Q-tiles per CTA, uniform work)
    attn_h_kernel<<<dim3(TSEQ / 128, NHEAD, BSZ), 128, AH_SMEM>>>(qkv, attn);

    // 4. out1 = x + attn @ w_proj + b_proj
    dim3 gE(EMB / 256, MROWS / 128);
    gemm_h_kernel<false, false><<<gE, 256, G2_SMEM>>>(attn, wpT, b_proj, x, out1, EMB, EMB);

    // 5. LN2 -> half
    ln_kernel<<<MROWS, 256>>>(out1, ln2_g, ln2_b, h);

    // 6. mid = gelu(h @ w1 + b1)  (fast tanh GELU)
    dim3 gF(FFDIM / 256, MROWS / 128);
    gemm_h_kernel<true, true><<<gF, 256, G2_SMEM>>>(h, w1T, b1, nullptr, mid, FFDIM, EMB);

    // 7. out = out1 + mid @ w2 + b2
    gemm_h_kernel<false, false><<<gE, 256, G2_SMEM>>>(mid, w2T, b2, out1, out, EMB, FFDIM);
}

// round 13
// speedup vs baseline: 7.2777x; 1.1874x over previous
#include <cuda_runtime.h>
#include <cuda_fp16.h>
#include <math_constants.h>
#include <math.h>
#include <stdint.h>

#define BSZ   8
#define TSEQ  1024
#define EMB   1024
#define NHEAD 16
#define HEADD 64
#define MROWS (BSZ * TSEQ)   // 8192
#define FFDIM 4096
#define QKV_N 3072

// ---------------------------------------------------------------------------
// Scratch
// ---------------------------------------------------------------------------
__device__ __half g_h    [(size_t)MROWS * EMB];
__device__ __half g_qkv  [(size_t)MROWS * QKV_N];
__device__ __half g_attn [(size_t)MROWS * EMB];
__device__ float  g_out1 [(size_t)MROWS * EMB];
__device__ __half g_mid  [(size_t)MROWS * FFDIM];
__device__ __half g_wqkvT[(size_t)QKV_N * EMB];
__device__ __half g_wpT  [(size_t)EMB * EMB];
__device__ __half g_w1T  [(size_t)EMB * FFDIM];
__device__ __half g_w2T  [(size_t)FFDIM * EMB];

// ---------------------------------------------------------------------------
// Helpers
// ---------------------------------------------------------------------------
__device__ __forceinline__ uint32_t smem_u32(const void* p) {
    uint32_t a;
    asm("{ .reg .u64 t; cvta.to.shared.u64 t, %1; cvt.u32.u64 %0, t; }" : "=r"(a) : "l"(p));
    return a;
}

__device__ __forceinline__ void cp16(uint32_t dst, const void* src) {
    asm volatile("cp.async.cg.shared.global [%0], [%1], 16;" :: "r"(dst), "l"(src) : "memory");
}
__device__ __forceinline__ void cp_commit() {
    asm volatile("cp.async.commit_group;" ::: "memory");
}
template<int N>
__device__ __forceinline__ void cp_wait() {
    asm volatile("cp.async.wait_group %0;" :: "n"(N) : "memory");
}

__device__ __forceinline__ void ldsm_x4(uint32_t& r0, uint32_t& r1, uint32_t& r2, uint32_t& r3,
                                        uint32_t addr) {
    asm volatile("ldmatrix.sync.aligned.m8n8.x4.shared.b16 {%0,%1,%2,%3}, [%4];"
                 : "=r"(r0), "=r"(r1), "=r"(r2), "=r"(r3) : "r"(addr));
}
__device__ __forceinline__ void ldsm_x4t(uint32_t& r0, uint32_t& r1, uint32_t& r2, uint32_t& r3,
                                         uint32_t addr) {
    asm volatile("ldmatrix.sync.aligned.m8n8.x4.trans.shared.b16 {%0,%1,%2,%3}, [%4];"
                 : "=r"(r0), "=r"(r1), "=r"(r2), "=r"(r3) : "r"(addr));
}

__device__ __forceinline__ void mma_f16(float& c0, float& c1, float& c2, float& c3,
                                        uint32_t a0, uint32_t a1, uint32_t a2, uint32_t a3,
                                        uint32_t b0, uint32_t b1) {
    asm volatile(
        "mma.sync.aligned.m16n8k16.row.col.f32.f16.f16.f32 "
        "{%0,%1,%2,%3}, {%4,%5,%6,%7}, {%8,%9}, {%0,%1,%2,%3};"
        : "+f"(c0), "+f"(c1), "+f"(c2), "+f"(c3)
        : "r"(a0), "r"(a1), "r"(a2), "r"(a3), "r"(b0), "r"(b1));
}

// Fast GELU: tanh-form with HW tanh.approx
__device__ __forceinline__ float gelu_fast(float x) {
    float u = x * (0.7978845608028654f + 0.035677408136300125f * x * x);
    float t;
    asm("tanh.approx.f32 %0, %1;" : "=f"(t) : "f"(u));
    return 0.5f * x * (1.0f + t);
}

// ---------------------------------------------------------------------------
// Fused prep: 6 weight transposes (float->half, [K][N]->[N][K]) + LN1, one launch.
// ---------------------------------------------------------------------------
struct PrepArgs {
    const float* in[6];
    __half*      out[6];
    int K[6], N[6];
    int off[6];
    int trans_total;     // total transpose tiles; blocks beyond do LN rows
};

__global__ __launch_bounds__(256)
void prep_kernel(PrepArgs A, const float* __restrict__ x, const float* __restrict__ lg,
                 const float* __restrict__ lb, __half* __restrict__ lnout)
{
    int blk = blockIdx.x;
    int tid = threadIdx.x;

    if (blk < A.trans_total) {
        __shared__ float t[32][33];
        int m = 0;
        #pragma unroll
        for (int i = 1; i < 6; i++) if (blk >= A.off[i]) m = i;
        int lt = blk - A.off[m];
        int N = A.N[m], K = A.K[m];
        int ntx = N >> 5;
        int n0 = (lt % ntx) * 32, k0 = (lt / ntx) * 32;
        const float* in = A.in[m];
        __half* out = A.out[m];
        int tx = tid & 31, ty = tid >> 5;
        #pragma unroll
        for (int i = 0; i < 32; i += 8)
            t[ty + i][tx] = in[(size_t)(k0 + ty + i) * N + n0 + tx];
        __syncthreads();
        #pragma unroll
        for (int i = 0; i < 32; i += 8)
            out[(size_t)(n0 + ty + i) * K + k0 + tx] = __float2half_rn(t[tx][ty + i]);
        return;
    }

    // LayerNorm row
    int row = blk - A.trans_total;
    const float4* xr = (const float4*)(x + (size_t)row * EMB);
    float4 v = xr[tid];
    float s  = v.x + v.y + v.z + v.w;
    float ss = v.x * v.x + v.y * v.y + v.z * v.z + v.w * v.w;
    #pragma unroll
    for (int o = 16; o; o >>= 1) {
        s  += __shfl_xor_sync(0xffffffffu, s,  o);
        ss += __shfl_xor_sync(0xffffffffu, ss, o);
    }
    __shared__ float rs_[8], rss_[8];
    __shared__ float mu_s, rstd_s;
    int warp = tid >> 5, lane = tid & 31;
    if (lane == 0) { rs_[warp] = s; rss_[warp] = ss; }
    __syncthreads();
    if (tid == 0) {
        float S = 0.f, SS = 0.f;
        #pragma unroll
        for (int i = 0; i < 8; i++) { S += rs_[i]; SS += rss_[i]; }
        float mu  = S * (1.0f / EMB);
        float var = SS * (1.0f / EMB) - mu * mu;
        mu_s = mu;
        rstd_s = rsqrtf(var + 1e-5f);
    }
    __syncthreads();
    float mu = mu_s, r = rstd_s;
    float4 gv = ((const float4*)lg)[tid];
    float4 bv = ((const float4*)lb)[tid];
    __half2* orow = (__half2*)(lnout + (size_t)row * EMB);
    orow[2 * tid]     = __floats2half2_rn((v.x - mu) * r * gv.x + bv.x,
                                          (v.y - mu) * r * gv.y + bv.y);
    orow[2 * tid + 1] = __floats2half2_rn((v.z - mu) * r * gv.z + bv.z,
                                          (v.w - mu) * r * gv.w + bv.w);
}

// ---------------------------------------------------------------------------
// LayerNorm (standalone, for LN2): float in -> half out
// ---------------------------------------------------------------------------
__global__ __launch_bounds__(256)
void ln_kernel(const float* __restrict__ x, const float* __restrict__ g,
               const float* __restrict__ b, __half* __restrict__ out)
{
    int row = blockIdx.x;
    int t   = threadIdx.x;
    const float4* xr = (const float4*)(x + (size_t)row * EMB);
    float4 v = xr[t];
    float s  = v.x + v.y + v.z + v.w;
    float ss = v.x * v.x + v.y * v.y + v.z * v.z + v.w * v.w;
    #pragma unroll
    for (int o = 16; o; o >>= 1) {
        s  += __shfl_xor_sync(0xffffffffu, s,  o);
        ss += __shfl_xor_sync(0xffffffffu, ss, o);
    }
    __shared__ float rs_[8], rss_[8];
    __shared__ float mu_s, rstd_s;
    int warp = t >> 5, lane = t & 31;
    if (lane == 0) { rs_[warp] = s; rss_[warp] = ss; }
    __syncthreads();
    if (t == 0) {
        float S = 0.f, SS = 0.f;
        #pragma unroll
        for (int i = 0; i < 8; i++) { S += rs_[i]; SS += rss_[i]; }
        float mu  = S * (1.0f / EMB);
        float var = SS * (1.0f / EMB) - mu * mu;
        mu_s = mu;
        rstd_s = rsqrtf(var + 1e-5f);
    }
    __syncthreads();
    float mu = mu_s, r = rstd_s;
    float4 gv = ((const float4*)g)[t];
    float4 bv = ((const float4*)b)[t];
    __half2* orow = (__half2*)(out + (size_t)row * EMB);
    orow[2 * t]     = __floats2half2_rn((v.x - mu) * r * gv.x + bv.x,
                                        (v.y - mu) * r * gv.y + bv.y);
    orow[2 * t + 1] = __floats2half2_rn((v.z - mu) * r * gv.z + bv.z,
                                        (v.w - mu) * r * gv.w + bv.w);
}

// ---------------------------------------------------------------------------
// fp16 mma GEMM v3: CTA 128x256, BK=64, 8 warps (64x64), 3-stage cp.async,
// ONE barrier per K-chunk (prefetch issued post-barrier, distance 2).
// smem rows stride 72 halves -> conflict-free ldmatrix.
// ---------------------------------------------------------------------------
#define G3_STRIDE 72
#define G3_ATILE (128 * G3_STRIDE * 2)   // 18432 B
#define G3_BTILE (256 * G3_STRIDE * 2)   // 36864 B
#define G3_STAGE (G3_ATILE + G3_BTILE)   // 55296 B
#define G3_SMEM  (3 * G3_STAGE)          // 165888 B

template<bool GELU, bool HALF_OUT>
__global__ __launch_bounds__(256)
void gemm_h_kernel(const __half* __restrict__ A, const __half* __restrict__ Bt,
                   const float* __restrict__ bias, const float* __restrict__ res,
                   void* __restrict__ Cv, int N_, int K_)
{
    extern __shared__ char smem[];
    const uint32_t sb = smem_u32(smem);
    int tid  = threadIdx.x;
    int lane = tid & 31, warp = tid >> 5;
    int wm = warp >> 2;
    int wn = warp & 3;
    int rowBase = blockIdx.y * 128;
    int colBase = blockIdx.x * 256;
    const int C_CHUNKS = K_ >> 6;

    auto load_chunk = [&](int c, int st) {
        int k0 = c << 6;
        uint32_t aB = sb + st * G3_STAGE;
        uint32_t bB = aB + G3_ATILE;
        #pragma unroll
        for (int s = 0; s < 4; s++) {          // A: 1024 x 16B
            int idx = tid + s * 256;
            int r = idx >> 3, ch = idx & 7;
            cp16(aB + (uint32_t)(r * G3_STRIDE + ch * 8) * 2,
                 A + (size_t)(rowBase + r) * K_ + k0 + ch * 8);
        }
        #pragma unroll
        for (int s = 0; s < 8; s++) {          // B: 2048 x 16B
            int idx = tid + s * 256;
            int r = idx >> 3, ch = idx & 7;
            cp16(bB + (uint32_t)(r * G3_STRIDE + ch * 8) * 2,
                 Bt + (size_t)(colBase + r) * K_ + k0 + ch * 8);
        }
        cp_commit();
    };

    float acc[4][8][4];
    #pragma unroll
    for (int i = 0; i < 4; i++)
        #pragma unroll
        for (int j = 0; j < 8; j++)
            #pragma unroll
            for (int r = 0; r < 4; r++) acc[i][j][r] = 0.f;

    load_chunk(0, 0);
    load_chunk(1, 1);

    for (int c = 0; c < C_CHUNKS; c++) {
        cp_wait<1>();            // chunk c resident (chunk c+1 may be in flight)
        __syncthreads();         // all warps past chunk c-1's compute
        if (c + 2 < C_CHUNKS) load_chunk(c + 2, (c + 2) % 3);
        else cp_commit();        // empty group keeps wait<1> invariant at tail

        uint32_t aBase = sb + (c % 3) * G3_STAGE;
        uint32_t bBase = aBase + G3_ATILE;

        #pragma unroll
        for (int ks = 0; ks < 4; ks++) {
            int k0 = ks * 16;
            uint32_t a[4][4];
            #pragma unroll
            for (int mt = 0; mt < 4; mt++) {
                uint32_t addr = aBase +
                    (uint32_t)((wm * 64 + mt * 16 + (lane & 15)) * G3_STRIDE
                               + k0 + ((lane >> 4) << 3)) * 2;
                ldsm_x4(a[mt][0], a[mt][1], a[mt][2], a[mt][3], addr);
            }
            uint32_t bf[8][2];
            #pragma unroll
            for (int np = 0; np < 4; np++) {
                int n = wn * 64 + np * 16 + ((lane >> 4) << 3) + (lane & 7);
                int koff = ((lane >> 3) & 1) << 3;
                uint32_t addr = bBase + (uint32_t)(n * G3_STRIDE + k0 + koff) * 2;
                ldsm_x4(bf[np * 2][0], bf[np * 2][1], bf[np * 2 + 1][0], bf[np * 2 + 1][1], addr);
            }
            #pragma unroll
            for (int mt = 0; mt < 4; mt++)
                #pragma unroll
                for (int nt = 0; nt < 8; nt++)
                    mma_f16(acc[mt][nt][0], acc[mt][nt][1], acc[mt][nt][2], acc[mt][nt][3],
                            a[mt][0], a[mt][1], a[mt][2], a[mt][3],
                            bf[nt][0], bf[nt][1]);
        }
    }

    int lq = lane >> 2, lr = lane & 3;
    __half* Ch = (__half*)Cv;
    float*  Cf = (float*)Cv;
    #pragma unroll
    for (int mt = 0; mt < 4; mt++) {
        int row0 = rowBase + wm * 64 + mt * 16 + lq;
        #pragma unroll
        for (int nt = 0; nt < 8; nt++) {
            int col = colBase + wn * 64 + nt * 8 + lr * 2;
            float2 p0 = make_float2(acc[mt][nt][0], acc[mt][nt][1]);
            float2 p1 = make_float2(acc[mt][nt][2], acc[mt][nt][3]);
            if (bias) {
                float2 bv = *(const float2*)(bias + col);
                p0.x += bv.x; p0.y += bv.y;
                p1.x += bv.x; p1.y += bv.y;
            }
            if (res) {
                float2 r0 = *(const float2*)(res + (size_t)row0 * N_ + col);
                float2 r1 = *(const float2*)(res + (size_t)(row0 + 8) * N_ + col);
                p0.x += r0.x; p0.y += r0.y;
                p1.x += r1.x; p1.y += r1.y;
            }
            if (GELU) {
                p0.x = gelu_fast(p0.x);
                p0.y = gelu_fast(p0.y);
                p1.x = gelu_fast(p1.x);
                p1.y = gelu_fast(p1.y);
            }
            if (HALF_OUT) {
                *(__half2*)(Ch + (size_t)row0 * N_ + col) = __floats2half2_rn(p0.x, p0.y);
                *(__half2*)(Ch + (size_t)(row0 + 8) * N_ + col) = __floats2half2_rn(p1.x, p1.y);
            } else {
                *(float2*)(Cf + (size_t)row0 * N_ + col) = p0;
                *(float2*)(Cf + (size_t)(row0 + 8) * N_ + col) = p1;
            }
        }
    }
}

// ---------------------------------------------------------------------------
// fp16 flash attention, cp.async double-buffered K/V.
// Each CTA processes TWO Q tiles (qb0 and 15-qb0) -> uniform 17 KV iterations.
// ---------------------------------------------------------------------------
#define AHS 72
#define AKV (64 * AHS)
#define AH_SMEM (6 * AKV * 2)             // 55296 B

__global__ __launch_bounds__(128)
void attn_h_kernel(const __half* __restrict__ QKV, __half* __restrict__ Out)
{
    extern __shared__ char smraw[];
    __half* sm = (__half*)smraw;
    __half* Qs = sm;
    __half* Ks = sm + AKV;
    __half* Vs = sm + 3 * AKV;
    __half* Ps = sm + 5 * AKV;
    const uint32_t sQ = smem_u32(Qs), sK0 = smem_u32(Ks), sV0 = smem_u32(Vs),
                   sP = smem_u32(Ps);

    int qb0 = blockIdx.x, h = blockIdx.y, bb = blockIdx.z;
    int tid = threadIdx.x;
    int lane = tid & 31, warp = tid >> 5;
    int lq = lane >> 2, lr = lane & 3;

    const __half* Qp = QKV + h * HEADD;
    const __half* Kp = QKV + EMB + h * HEADD;
    const __half* Vp = QKV + 2 * EMB + h * HEADD;

    auto load_kv = [&](int jt, int b) {
        size_t kbase = (size_t)(bb * TSEQ + jt * 64) * QKV_N;
        uint32_t kB = sK0 + (uint32_t)(b * AKV) * 2;
        uint32_t vB = sV0 + (uint32_t)(b * AKV) * 2;
        #pragma unroll
        for (int s = 0; s < 4; s++) {
            int idx = tid + s * 128;
            int r = idx >> 3, ch = idx & 7;
            cp16(kB + (uint32_t)(r * AHS + ch * 8) * 2,
                 Kp + kbase + (size_t)r * QKV_N + ch * 8);
            cp16(vB + (uint32_t)(r * AHS + ch * 8) * 2,
                 Vp + kbase + (size_t)r * QKV_N + ch * 8);
        }
        cp_commit();
    };

    const uint32_t sPw = sP + (uint32_t)(warp * 16 * AHS) * 2;
    __half* prow = Ps + warp * 16 * AHS;

    #pragma unroll
    for (int rep = 0; rep < 2; rep++) {
        int qb = rep ? (TSEQ / 64 - 1 - qb0) : qb0;

        __syncthreads();

        size_t qbase = (size_t)(bb * TSEQ + qb * 64) * QKV_N;
        #pragma unroll
        for (int s = 0; s < 4; s++) {
            int idx = tid + s * 128;
            int r = idx >> 3, ch = idx & 7;
            *(float4*)(Qs + r * AHS + ch * 8) =
                *(const float4*)(Qp + qbase + (size_t)r * QKV_N + ch * 8);
        }
        load_kv(0, 0);

        float m0 = -CUDART_INF_F, m1 = -CUDART_INF_F;
        float l0 = 0.f, l1 = 0.f;
        float o[8][4];
        #pragma unroll
        for (int nt = 0; nt < 8; nt++)
            #pragma unroll
            for (int r = 0; r < 4; r++) o[nt][r] = 0.f;

        for (int jt = 0; jt <= qb; jt++) {
            cp_wait<0>();
            __syncthreads();
            if (jt < qb) load_kv(jt + 1, (jt + 1) & 1);

            uint32_t sK = sK0 + (uint32_t)((jt & 1) * AKV) * 2;
            uint32_t sV = sV0 + (uint32_t)((jt & 1) * AKV) * 2;

            float s[8][4];
            #pragma unroll
            for (int nt = 0; nt < 8; nt++)
                #pragma unroll
                for (int r = 0; r < 4; r++) s[nt][r] = 0.f;

            #pragma unroll
            for (int ks = 0; ks < 4; ks++) {
                int k0 = ks * 16;
                uint32_t a0, a1, a2, a3;
                ldsm_x4(a0, a1, a2, a3,
                        sQ + (uint32_t)((warp * 16 + (lane & 15)) * AHS
                                        + k0 + ((lane >> 4) << 3)) * 2);
                #pragma unroll
                for (int np = 0; np < 4; np++) {
                    int n = np * 16 + ((lane >> 4) << 3) + (lane & 7);
                    int koff = ((lane >> 3) & 1) << 3;
                    uint32_t b0, b1, b2, b3;
                    ldsm_x4(b0, b1, b2, b3,
                            sK + (uint32_t)(n * AHS + k0 + koff) * 2);
                    mma_f16(s[np * 2][0], s[np * 2][1], s[np * 2][2], s[np * 2][3],
                            a0, a1, a2, a3, b0, b1);
                    mma_f16(s[np * 2 + 1][0], s[np * 2 + 1][1], s[np * 2 + 1][2], s[np * 2 + 1][3],
                            a0, a1, a2, a3, b2, b3);
                }
            }

            const float scale = 0.125f;
            bool diag = (jt == qb);
            int row0 = warp * 16 + lq;
            #pragma unroll
            for (int nt = 0; nt < 8; nt++) {
                int col = nt * 8 + 2 * lr;
                s[nt][0] *= scale; s[nt][1] *= scale;
                s[nt][2] *= scale; s[nt][3] *= scale;
                if (diag) {
                    if (col     > row0)     s[nt][0] = -CUDART_INF_F;
                    if (col + 1 > row0)     s[nt][1] = -CUDART_INF_F;
                    if (col     > row0 + 8) s[nt][2] = -CUDART_INF_F;
                    if (col + 1 > row0 + 8) s[nt][3] = -CUDART_INF_F;
                }
            }

            {
                float rm = -CUDART_INF_F;
                #pragma unroll
                for (int nt = 0; nt < 8; nt++) rm = fmaxf(rm, fmaxf(s[nt][0], s[nt][1]));
                rm = fmaxf(rm, __shfl_xor_sync(0xffffffffu, rm, 1));
                rm = fmaxf(rm, __shfl_xor_sync(0xffffffffu, rm, 2));
                float mn = fmaxf(m0, rm);
                float alpha = __expf(m0 - mn);
                float ps = 0.f;
                #pragma unroll
                for (int nt = 0; nt < 8; nt++) {
                    s[nt][0] = __expf(s[nt][0] - mn);
                    s[nt][1] = __expf(s[nt][1] - mn);
                    ps += s[nt][0] + s[nt][1];
                }
                ps += __shfl_xor_sync(0xffffffffu, ps, 1);
                ps += __shfl_xor_sync(0xffffffffu, ps, 2);
                l0 = l0 * alpha + ps;
                m0 = mn;
                #pragma unroll
                for (int nt = 0; nt < 8; nt++) { o[nt][0] *= alpha; o[nt][1] *= alpha; }
            }
            {
                float rm = -CUDART_INF_F;
                #pragma unroll
                for (int nt = 0; nt < 8; nt++) rm = fmaxf(rm, fmaxf(s[nt][2], s[nt][3]));
                rm = fmaxf(rm, __shfl_xor_sync(0xffffffffu, rm, 1));
                rm = fmaxf(rm, __shfl_xor_sync(0xffffffffu, rm, 2));
                float mn = fmaxf(m1, rm);
                float alpha = __expf(m1 - mn);
                float ps = 0.f;
                #pragma unroll
                for (int nt = 0; nt < 8; nt++) {
                    s[nt][2] = __expf(s[nt][2] - mn);
                    s[nt][3] = __expf(s[nt][3] - mn);
                    ps += s[nt][2] + s[nt][3];
                }
                ps += __shfl_xor_sync(0xffffffffu, ps, 1);
                ps += __shfl_xor_sync(0xffffffffu, ps, 2);
                l1 = l1 * alpha + ps;
                m1 = mn;
                #pragma unroll
                for (int nt = 0; nt < 8; nt++) { o[nt][2] *= alpha; o[nt][3] *= alpha; }
            }

            #pragma unroll
            for (int nt = 0; nt < 8; nt++) {
                *(__half2*)(prow + lq * AHS + nt * 8 + 2 * lr) =
                    __floats2half2_rn(s[nt][0], s[nt][1]);
                *(__half2*)(prow + (lq + 8) * AHS + nt * 8 + 2 * lr) =
                    __floats2half2_rn(s[nt][2], s[nt][3]);
            }
            __syncwarp();

            #pragma unroll
            for (int ks = 0; ks < 4; ks++) {
                int k0 = ks * 16;
                uint32_t a0, a1, a2, a3;
                ldsm_x4(a0, a1, a2, a3,
                        sPw + (uint32_t)((lane & 15) * AHS + k0 + ((lane >> 4) << 3)) * 2);
                #pragma unroll
                for (int dp = 0; dp < 4; dp++) {
                    uint32_t b0, b1, b2, b3;
                    ldsm_x4t(b0, b1, b2, b3,
                             sV + (uint32_t)((k0 + (lane & 15)) * AHS
                                             + dp * 16 + ((lane >> 4) << 3)) * 2);
                    mma_f16(o[dp * 2][0], o[dp * 2][1], o[dp * 2][2], o[dp * 2][3],
                            a0, a1, a2, a3, b0, b1);
                    mma_f16(o[dp * 2 + 1][0], o[dp * 2 + 1][1], o[dp * 2 + 1][2], o[dp * 2 + 1][3],
                            a0, a1, a2, a3, b2, b3);
                }
            }
            __syncwarp();
        }

        float inv0 = 1.0f / l0, inv1 = 1.0f / l1;
        size_t r0 = (size_t)(bb * TSEQ + qb * 64 + warp * 16 + lq);
        size_t r1 = r0 + 8;
        #pragma unroll
        for (int nt = 0; nt < 8; nt++) {
            int col = h * HEADD + nt * 8 + 2 * lr;
            *(__half2*)(Out + r0 * EMB + col) =
                __floats2half2_rn(o[nt][0] * inv0, o[nt][1] * inv0);
            *(__half2*)(Out + r1 * EMB + col) =
                __floats2half2_rn(o[nt][2] * inv1, o[nt][3] * inv1);
        }
    }
}

// ---------------------------------------------------------------------------
// Launch
// ---------------------------------------------------------------------------
extern "C" void kernel_launch(void* const* d_in, const int* in_sizes, int n_in,
                              void* d_out, int out_size)
{
    const float* x      = (const float*)d_in[0];
    const float* ln1_g  = (const float*)d_in[1];
    const float* ln1_b  = (const float*)d_in[2];
    const float* wq     = (const float*)d_in[3];
    const float* wk     = (const float*)d_in[4];
    const float* wv     = (const float*)d_in[5];
    const float* w_proj = (const float*)d_in[6];
    const float* b_proj = (const float*)d_in[7];
    const float* ln2_g  = (const float*)d_in[8];
    const float* ln2_b  = (const float*)d_in[9];
    const float* w1     = (const float*)d_in[10];
    const float* b1     = (const float*)d_in[11];
    const float* w2     = (const float*)d_in[12];
    const float* b2     = (const float*)d_in[13];
    float* out = (float*)d_out;

    __half *h, *qkv, *attn, *mid;
    float  *out1;
    __half *wqkvT, *wpT, *w1T, *w2T;
    cudaGetSymbolAddress((void**)&h,     g_h);
    cudaGetSymbolAddress((void**)&qkv,   g_qkv);
    cudaGetSymbolAddress((void**)&attn,  g_attn);
    cudaGetSymbolAddress((void**)&out1,  g_out1);
    cudaGetSymbolAddress((void**)&mid,   g_mid);
    cudaGetSymbolAddress((void**)&wqkvT, g_wqkvT);
    cudaGetSymbolAddress((void**)&wpT,   g_wpT);
    cudaGetSymbolAddress((void**)&w1T,   g_w1T);
    cudaGetSymbolAddress((void**)&w2T,   g_w2T);

    cudaFuncSetAttribute(gemm_h_kernel<false, false>,
                         cudaFuncAttributeMaxDynamicSharedMemorySize, G3_SMEM);
    cudaFuncSetAttribute(gemm_h_kernel<false, true>,
                         cudaFuncAttributeMaxDynamicSharedMemorySize, G3_SMEM);
    cudaFuncSetAttribute(gemm_h_kernel<true, true>,
                         cudaFuncAttributeMaxDynamicSharedMemorySize, G3_SMEM);
    cudaFuncSetAttribute(attn_h_kernel,
                         cudaFuncAttributeMaxDynamicSharedMemorySize, AH_SMEM);

    // 0. Prep: 6 transposes + LN1 in one launch
    PrepArgs pa;
    pa.in[0] = wq;     pa.out[0] = wqkvT;                         pa.K[0] = EMB;   pa.N[0] = EMB;
    pa.in[1] = wk;     pa.out[1] = wqkvT + (size_t)EMB * EMB;     pa.K[1] = EMB;   pa.N[1] = EMB;
    pa.in[2] = wv;     pa.out[2] = wqkvT + (size_t)2 * EMB * EMB; pa.K[2] = EMB;   pa.N[2] = EMB;
    pa.in[3] = w_proj; pa.out[3] = wpT;                           pa.K[3] = EMB;   pa.N[3] = EMB;
    pa.in[4] = w1;     pa.out[4] = w1T;                           pa.K[4] = EMB;   pa.N[4] = FFDIM;
    pa.in[5] = w2;     pa.out[5] = w2T;                           pa.K[5] = FFDIM; pa.N[5] = EMB;
    int total = 0;
    for (int i = 0; i < 6; i++) {
        pa.off[i] = total;
        total += (pa.N[i] / 32) * (pa.K[i] / 32);
    }
    pa.trans_total = total;
    prep_kernel<<<total + MROWS, 256>>>(pa, x, ln1_g, ln1_b, h);

    // 2. Fused QKV projection
    dim3 gQKV(QKV_N / 256, MROWS / 128);
    gemm_h_kernel<false, true><<<gQKV, 256, G3_SMEM>>>(h, wqkvT, nullptr, nullptr, qkv, QKV_N, EMB);

    // 3. Causal flash attention
    attn_h_kernel<<<dim3(TSEQ / 128, NHEAD, BSZ), 128, AH_SMEM>>>(qkv, attn);

    // 4. out1 = x + attn @ w_proj + b_proj
    dim3 gE(EMB / 256, MROWS / 128);
    gemm_h_kernel<false, false><<<gE, 256, G3_SMEM>>>(attn, wpT, b_proj, x, out1, EMB, EMB);

    // 5. LN2 -> half
    ln_kernel<<<MROWS, 256>>>(out1, ln2_g, ln2_b, h);

    // 6. mid = gelu(h @ w1 + b1)
    dim3 gF(FFDIM / 256, MROWS / 128);
    gemm_h_kernel<true, true><<<gF, 256, G3_SMEM>>>(h, w1T, b1, nullptr, mid, FFDIM, EMB);

    // 7. out = out1 + mid @ w2 + b2
    gemm_h_kernel<false, false><<<gE, 256, G3_SMEM>>>(mid, w2T, b2, out1, out, EMB, FFDIM);
}

// round 14
// speedup vs baseline: 7.5752x; 1.0409x over previous
#include <cuda_runtime.h>
#include <cuda_fp16.h>
#include <math_constants.h>
#include <math.h>
#include <stdint.h>

#define BSZ   8
#define TSEQ  1024
#define EMB   1024
#define NHEAD 16
#define HEADD 64
#define MROWS (BSZ * TSEQ)   // 8192
#define FFDIM 4096
#define QKV_N 3072

// ---------------------------------------------------------------------------
// Scratch
// ---------------------------------------------------------------------------
__device__ __half g_h    [(size_t)MROWS * EMB];
__device__ __half g_qkv  [(size_t)MROWS * QKV_N];
__device__ __half g_attn [(size_t)MROWS * EMB];
__device__ float  g_out1 [(size_t)MROWS * EMB];
__device__ __half g_mid  [(size_t)MROWS * FFDIM];
__device__ __half g_wqkvT[(size_t)QKV_N * EMB];
__device__ __half g_wpT  [(size_t)EMB * EMB];
__device__ __half g_w1T  [(size_t)EMB * FFDIM];
__device__ __half g_w2T  [(size_t)FFDIM * EMB];

// ---------------------------------------------------------------------------
// Helpers
// ---------------------------------------------------------------------------
__device__ __forceinline__ uint32_t smem_u32(const void* p) {
    uint32_t a;
    asm("{ .reg .u64 t; cvta.to.shared.u64 t, %1; cvt.u32.u64 %0, t; }" : "=r"(a) : "l"(p));
    return a;
}

__device__ __forceinline__ void cp16(uint32_t dst, const void* src) {
    asm volatile("cp.async.cg.shared.global [%0], [%1], 16;" :: "r"(dst), "l"(src) : "memory");
}
__device__ __forceinline__ void cp_commit() {
    asm volatile("cp.async.commit_group;" ::: "memory");
}
template<int N>
__device__ __forceinline__ void cp_wait() {
    asm volatile("cp.async.wait_group %0;" :: "n"(N) : "memory");
}

__device__ __forceinline__ void ldsm_x4(uint32_t& r0, uint32_t& r1, uint32_t& r2, uint32_t& r3,
                                        uint32_t addr) {
    asm volatile("ldmatrix.sync.aligned.m8n8.x4.shared.b16 {%0,%1,%2,%3}, [%4];"
                 : "=r"(r0), "=r"(r1), "=r"(r2), "=r"(r3) : "r"(addr));
}
__device__ __forceinline__ void ldsm_x4t(uint32_t& r0, uint32_t& r1, uint32_t& r2, uint32_t& r3,
                                         uint32_t addr) {
    asm volatile("ldmatrix.sync.aligned.m8n8.x4.trans.shared.b16 {%0,%1,%2,%3}, [%4];"
                 : "=r"(r0), "=r"(r1), "=r"(r2), "=r"(r3) : "r"(addr));
}

__device__ __forceinline__ void mma_f16(float& c0, float& c1, float& c2, float& c3,
                                        uint32_t a0, uint32_t a1, uint32_t a2, uint32_t a3,
                                        uint32_t b0, uint32_t b1) {
    asm volatile(
        "mma.sync.aligned.m16n8k16.row.col.f32.f16.f16.f32 "
        "{%0,%1,%2,%3}, {%4,%5,%6,%7}, {%8,%9}, {%0,%1,%2,%3};"
        : "+f"(c0), "+f"(c1), "+f"(c2), "+f"(c3)
        : "r"(a0), "r"(a1), "r"(a2), "r"(a3), "r"(b0), "r"(b1));
}

// Fast GELU: tanh-form with HW tanh.approx
__device__ __forceinline__ float gelu_fast(float x) {
    float u = x * (0.7978845608028654f + 0.035677408136300125f * x * x);
    float t;
    asm("tanh.approx.f32 %0, %1;" : "=f"(t) : "f"(u));
    return 0.5f * x * (1.0f + t);
}

// ---------------------------------------------------------------------------
// Fused prep: 6 weight transposes + LN1, one launch.
// ---------------------------------------------------------------------------
struct PrepArgs {
    const float* in[6];
    __half*      out[6];
    int K[6], N[6];
    int off[6];
    int trans_total;
};

__global__ __launch_bounds__(256)
void prep_kernel(PrepArgs A, const float* __restrict__ x, const float* __restrict__ lg,
                 const float* __restrict__ lb, __half* __restrict__ lnout)
{
    int blk = blockIdx.x;
    int tid = threadIdx.x;

    if (blk < A.trans_total) {
        __shared__ float t[32][33];
        int m = 0;
        #pragma unroll
        for (int i = 1; i < 6; i++) if (blk >= A.off[i]) m = i;
        int lt = blk - A.off[m];
        int N = A.N[m], K = A.K[m];
        int ntx = N >> 5;
        int n0 = (lt % ntx) * 32, k0 = (lt / ntx) * 32;
        const float* in = A.in[m];
        __half* out = A.out[m];
        int tx = tid & 31, ty = tid >> 5;
        #pragma unroll
        for (int i = 0; i < 32; i += 8)
            t[ty + i][tx] = in[(size_t)(k0 + ty + i) * N + n0 + tx];
        __syncthreads();
        #pragma unroll
        for (int i = 0; i < 32; i += 8)
            out[(size_t)(n0 + ty + i) * K + k0 + tx] = __float2half_rn(t[tx][ty + i]);
        return;
    }

    int row = blk - A.trans_total;
    const float4* xr = (const float4*)(x + (size_t)row * EMB);
    float4 v = xr[tid];
    float s  = v.x + v.y + v.z + v.w;
    float ss = v.x * v.x + v.y * v.y + v.z * v.z + v.w * v.w;
    #pragma unroll
    for (int o = 16; o; o >>= 1) {
        s  += __shfl_xor_sync(0xffffffffu, s,  o);
        ss += __shfl_xor_sync(0xffffffffu, ss, o);
    }
    __shared__ float rs_[8], rss_[8];
    __shared__ float mu_s, rstd_s;
    int warp = tid >> 5, lane = tid & 31;
    if (lane == 0) { rs_[warp] = s; rss_[warp] = ss; }
    __syncthreads();
    if (tid == 0) {
        float S = 0.f, SS = 0.f;
        #pragma unroll
        for (int i = 0; i < 8; i++) { S += rs_[i]; SS += rss_[i]; }
        float mu  = S * (1.0f / EMB);
        float var = SS * (1.0f / EMB) - mu * mu;
        mu_s = mu;
        rstd_s = rsqrtf(var + 1e-5f);
    }
    __syncthreads();
    float mu = mu_s, r = rstd_s;
    float4 gv = ((const float4*)lg)[tid];
    float4 bv = ((const float4*)lb)[tid];
    __half2* orow = (__half2*)(lnout + (size_t)row * EMB);
    orow[2 * tid]     = __floats2half2_rn((v.x - mu) * r * gv.x + bv.x,
                                          (v.y - mu) * r * gv.y + bv.y);
    orow[2 * tid + 1] = __floats2half2_rn((v.z - mu) * r * gv.z + bv.z,
                                          (v.w - mu) * r * gv.w + bv.w);
}

// ---------------------------------------------------------------------------
// LayerNorm (standalone, for LN2)
// ---------------------------------------------------------------------------
__global__ __launch_bounds__(256)
void ln_kernel(const float* __restrict__ x, const float* __restrict__ g,
               const float* __restrict__ b, __half* __restrict__ out)
{
    int row = blockIdx.x;
    int t   = threadIdx.x;
    const float4* xr = (const float4*)(x + (size_t)row * EMB);
    float4 v = xr[t];
    float s  = v.x + v.y + v.z + v.w;
    float ss = v.x * v.x + v.y * v.y + v.z * v.z + v.w * v.w;
    #pragma unroll
    for (int o = 16; o; o >>= 1) {
        s  += __shfl_xor_sync(0xffffffffu, s,  o);
        ss += __shfl_xor_sync(0xffffffffu, ss, o);
    }
    __shared__ float rs_[8], rss_[8];
    __shared__ float mu_s, rstd_s;
    int warp = t >> 5, lane = t & 31;
    if (lane == 0) { rs_[warp] = s; rss_[warp] = ss; }
    __syncthreads();
    if (t == 0) {
        float S = 0.f, SS = 0.f;
        #pragma unroll
        for (int i = 0; i < 8; i++) { S += rs_[i]; SS += rss_[i]; }
        float mu  = S * (1.0f / EMB);
        float var = SS * (1.0f / EMB) - mu * mu;
        mu_s = mu;
        rstd_s = rsqrtf(var + 1e-5f);
    }
    __syncthreads();
    float mu = mu_s, r = rstd_s;
    float4 gv = ((const float4*)g)[t];
    float4 bv = ((const float4*)b)[t];
    __half2* orow = (__half2*)(out + (size_t)row * EMB);
    orow[2 * t]     = __floats2half2_rn((v.x - mu) * r * gv.x + bv.x,
                                        (v.y - mu) * r * gv.y + bv.y);
    orow[2 * t + 1] = __floats2half2_rn((v.z - mu) * r * gv.z + bv.z,
                                        (v.w - mu) * r * gv.w + bv.w);
}

// ---------------------------------------------------------------------------
// fp16 mma GEMM v4: CTA 128x128, 128 threads (4 warps, warp tile 64x64),
// BK=64, 3-stage cp.async, ONE barrier per chunk, 2 CTAs/SM.
// ---------------------------------------------------------------------------
#define G4_STRIDE 72
#define G4_ATILE (128 * G4_STRIDE * 2)   // 18432 B
#define G4_STAGE (2 * G4_ATILE)          // 36864 B (A+B)
#define G4_SMEM  (3 * G4_STAGE)          // 110592 B -> 2 CTAs/SM

template<bool GELU, bool HALF_OUT>
__global__ __launch_bounds__(128, 2)
void gemm_h_kernel(const __half* __restrict__ A, const __half* __restrict__ Bt,
                   const float* __restrict__ bias, const float* __restrict__ res,
                   void* __restrict__ Cv, int N_, int K_)
{
    extern __shared__ char smem[];
    const uint32_t sb = smem_u32(smem);
    int tid  = threadIdx.x;
    int lane = tid & 31, warp = tid >> 5;
    int wm = warp >> 1;   // 0..1 (64-row slab)
    int wn = warp & 1;    // 0..1 (64-col slab)
    int rowBase = blockIdx.y * 128;
    int colBase = blockIdx.x * 128;
    const int C_CHUNKS = K_ >> 6;

    auto load_chunk = [&](int c, int st) {
        int k0 = c << 6;
        uint32_t aB = sb + st * G4_STAGE;
        uint32_t bB = aB + G4_ATILE;
        #pragma unroll
        for (int s = 0; s < 8; s++) {          // A: 1024 x 16B
            int idx = tid + s * 128;
            int r = idx >> 3, ch = idx & 7;
            cp16(aB + (uint32_t)(r * G4_STRIDE + ch * 8) * 2,
                 A + (size_t)(rowBase + r) * K_ + k0 + ch * 8);
        }
        #pragma unroll
        for (int s = 0; s < 8; s++) {          // B: 1024 x 16B
            int idx = tid + s * 128;
            int r = idx >> 3, ch = idx & 7;
            cp16(bB + (uint32_t)(r * G4_STRIDE + ch * 8) * 2,
                 Bt + (size_t)(colBase + r) * K_ + k0 + ch * 8);
        }
        cp_commit();
    };

    float acc[4][8][4];
    #pragma unroll
    for (int i = 0; i < 4; i++)
        #pragma unroll
        for (int j = 0; j < 8; j++)
            #pragma unroll
            for (int r = 0; r < 4; r++) acc[i][j][r] = 0.f;

    load_chunk(0, 0);
    load_chunk(1, 1);

    for (int c = 0; c < C_CHUNKS; c++) {
        cp_wait<1>();
        __syncthreads();
        if (c + 2 < C_CHUNKS) load_chunk(c + 2, (c + 2) % 3);
        else cp_commit();

        uint32_t aBase = sb + (c % 3) * G4_STAGE;
        uint32_t bBase = aBase + G4_ATILE;

        #pragma unroll
        for (int ks = 0; ks < 4; ks++) {
            int k0 = ks * 16;
            uint32_t a[4][4];
            #pragma unroll
            for (int mt = 0; mt < 4; mt++) {
                uint32_t addr = aBase +
                    (uint32_t)((wm * 64 + mt * 16 + (lane & 15)) * G4_STRIDE
                               + k0 + ((lane >> 4) << 3)) * 2;
                ldsm_x4(a[mt][0], a[mt][1], a[mt][2], a[mt][3], addr);
            }
            uint32_t bf[8][2];
            #pragma unroll
            for (int np = 0; np < 4; np++) {
                int n = wn * 64 + np * 16 + ((lane >> 4) << 3) + (lane & 7);
                int koff = ((lane >> 3) & 1) << 3;
                uint32_t addr = bBase + (uint32_t)(n * G4_STRIDE + k0 + koff) * 2;
                ldsm_x4(bf[np * 2][0], bf[np * 2][1], bf[np * 2 + 1][0], bf[np * 2 + 1][1], addr);
            }
            #pragma unroll
            for (int mt = 0; mt < 4; mt++)
                #pragma unroll
                for (int nt = 0; nt < 8; nt++)
                    mma_f16(acc[mt][nt][0], acc[mt][nt][1], acc[mt][nt][2], acc[mt][nt][3],
                            a[mt][0], a[mt][1], a[mt][2], a[mt][3],
                            bf[nt][0], bf[nt][1]);
        }
    }

    int lq = lane >> 2, lr = lane & 3;
    __half* Ch = (__half*)Cv;
    float*  Cf = (float*)Cv;
    #pragma unroll
    for (int mt = 0; mt < 4; mt++) {
        int row0 = rowBase + wm * 64 + mt * 16 + lq;
        #pragma unroll
        for (int nt = 0; nt < 8; nt++) {
            int col = colBase + wn * 64 + nt * 8 + lr * 2;
            float2 p0 = make_float2(acc[mt][nt][0], acc[mt][nt][1]);
            float2 p1 = make_float2(acc[mt][nt][2], acc[mt][nt][3]);
            if (bias) {
                float2 bv = *(const float2*)(bias + col);
                p0.x += bv.x; p0.y += bv.y;
                p1.x += bv.x; p1.y += bv.y;
            }
            if (res) {
                float2 r0 = *(const float2*)(res + (size_t)row0 * N_ + col);
                float2 r1 = *(const float2*)(res + (size_t)(row0 + 8) * N_ + col);
                p0.x += r0.x; p0.y += r0.y;
                p1.x += r1.x; p1.y += r1.y;
            }
            if (GELU) {
                p0.x = gelu_fast(p0.x);
                p0.y = gelu_fast(p0.y);
                p1.x = gelu_fast(p1.x);
                p1.y = gelu_fast(p1.y);
            }
            if (HALF_OUT) {
                *(__half2*)(Ch + (size_t)row0 * N_ + col) = __floats2half2_rn(p0.x, p0.y);
                *(__half2*)(Ch + (size_t)(row0 + 8) * N_ + col) = __floats2half2_rn(p1.x, p1.y);
            } else {
                *(float2*)(Cf + (size_t)row0 * N_ + col) = p0;
                *(float2*)(Cf + (size_t)(row0 + 8) * N_ + col) = p1;
            }
        }
    }
}

// ---------------------------------------------------------------------------
// fp16 flash attention, cp.async double-buffered K/V, 2 Q-tiles per CTA.
// ---------------------------------------------------------------------------
#define AHS 72
#define AKV (64 * AHS)
#define AH_SMEM (6 * AKV * 2)             // 55296 B

__global__ __launch_bounds__(128)
void attn_h_kernel(const __half* __restrict__ QKV, __half* __restrict__ Out)
{
    extern __shared__ char smraw[];
    __half* sm = (__half*)smraw;
    __half* Qs = sm;
    __half* Ks = sm + AKV;
    __half* Vs = sm + 3 * AKV;
    __half* Ps = sm + 5 * AKV;
    const uint32_t sQ = smem_u32(Qs), sK0 = smem_u32(Ks), sV0 = smem_u32(Vs),
                   sP = smem_u32(Ps);

    int qb0 = blockIdx.x, h = blockIdx.y, bb = blockIdx.z;
    int tid = threadIdx.x;
    int lane = tid & 31, warp = tid >> 5;
    int lq = lane >> 2, lr = lane & 3;

    const __half* Qp = QKV + h * HEADD;
    const __half* Kp = QKV + EMB + h * HEADD;
    const __half* Vp = QKV + 2 * EMB + h * HEADD;

    auto load_kv = [&](int jt, int b) {
        size_t kbase = (size_t)(bb * TSEQ + jt * 64) * QKV_N;
        uint32_t kB = sK0 + (uint32_t)(b * AKV) * 2;
        uint32_t vB = sV0 + (uint32_t)(b * AKV) * 2;
        #pragma unroll
        for (int s = 0; s < 4; s++) {
            int idx = tid + s * 128;
            int r = idx >> 3, ch = idx & 7;
            cp16(kB + (uint32_t)(r * AHS + ch * 8) * 2,
                 Kp + kbase + (size_t)r * QKV_N + ch * 8);
            cp16(vB + (uint32_t)(r * AHS + ch * 8) * 2,
                 Vp + kbase + (size_t)r * QKV_N + ch * 8);
        }
        cp_commit();
    };

    const uint32_t sPw = sP + (uint32_t)(warp * 16 * AHS) * 2;
    __half* prow = Ps + warp * 16 * AHS;

    #pragma unroll
    for (int rep = 0; rep < 2; rep++) {
        int qb = rep ? (TSEQ / 64 - 1 - qb0) : qb0;

        __syncthreads();

        size_t qbase = (size_t)(bb * TSEQ + qb * 64) * QKV_N;
        #pragma unroll
        for (int s = 0; s < 4; s++) {
            int idx = tid + s * 128;
            int r = idx >> 3, ch = idx & 7;
            *(float4*)(Qs + r * AHS + ch * 8) =
                *(const float4*)(Qp + qbase + (size_t)r * QKV_N + ch * 8);
        }
        load_kv(0, 0);

        float m0 = -CUDART_INF_F, m1 = -CUDART_INF_F;
        float l0 = 0.f, l1 = 0.f;
        float o[8][4];
        #pragma unroll
        for (int nt = 0; nt < 8; nt++)
            #pragma unroll
            for (int r = 0; r < 4; r++) o[nt][r] = 0.f;

        for (int jt = 0; jt <= qb; jt++) {
            cp_wait<0>();
            __syncthreads();
            if (jt < qb) load_kv(jt + 1, (jt + 1) & 1);

            uint32_t sK = sK0 + (uint32_t)((jt & 1) * AKV) * 2;
            uint32_t sV = sV0 + (uint32_t)((jt & 1) * AKV) * 2;

            float s[8][4];
            #pragma unroll
            for (int nt = 0; nt < 8; nt++)
                #pragma unroll
                for (int r = 0; r < 4; r++) s[nt][r] = 0.f;

            #pragma unroll
            for (int ks = 0; ks < 4; ks++) {
                int k0 = ks * 16;
                uint32_t a0, a1, a2, a3;
                ldsm_x4(a0, a1, a2, a3,
                        sQ + (uint32_t)((warp * 16 + (lane & 15)) * AHS
                                        + k0 + ((lane >> 4) << 3)) * 2);
                #pragma unroll
                for (int np = 0; np < 4; np++) {
                    int n = np * 16 + ((lane >> 4) << 3) + (lane & 7);
                    int koff = ((lane >> 3) & 1) << 3;
                    uint32_t b0, b1, b2, b3;
                    ldsm_x4(b0, b1, b2, b3,
                            sK + (uint32_t)(n * AHS + k0 + koff) * 2);
                    mma_f16(s[np * 2][0], s[np * 2][1], s[np * 2][2], s[np * 2][3],
                            a0, a1, a2, a3, b0, b1);
                    mma_f16(s[np * 2 + 1][0], s[np * 2 + 1][1], s[np * 2 + 1][2], s[np * 2 + 1][3],
                            a0, a1, a2, a3, b2, b3);
                }
            }

            const float scale = 0.125f;
            bool diag = (jt == qb);
            int row0 = warp * 16 + lq;
            #pragma unroll
            for (int nt = 0; nt < 8; nt++) {
                int col = nt * 8 + 2 * lr;
                s[nt][0] *= scale; s[nt][1] *= scale;
                s[nt][2] *= scale; s[nt][3] *= scale;
                if (diag) {
                    if (col     > row0)     s[nt][0] = -CUDART_INF_F;
                    if (col + 1 > row0)     s[nt][1] = -CUDART_INF_F;
                    if (col     > row0 + 8) s[nt][2] = -CUDART_INF_F;
                    if (col + 1 > row0 + 8) s[nt][3] = -CUDART_INF_F;
                }
            }

            {
                float rm = -CUDART_INF_F;
                #pragma unroll
                for (int nt = 0; nt < 8; nt++) rm = fmaxf(rm, fmaxf(s[nt][0], s[nt][1]));
                rm = fmaxf(rm, __shfl_xor_sync(0xffffffffu, rm, 1));
                rm = fmaxf(rm, __shfl_xor_sync(0xffffffffu, rm, 2));
                float mn = fmaxf(m0, rm);
                float alpha = __expf(m0 - mn);
                float ps = 0.f;
                #pragma unroll
                for (int nt = 0; nt < 8; nt++) {
                    s[nt][0] = __expf(s[nt][0] - mn);
                    s[nt][1] = __expf(s[nt][1] - mn);
                    ps += s[nt][0] + s[nt][1];
                }
                ps += __shfl_xor_sync(0xffffffffu, ps, 1);
                ps += __shfl_xor_sync(0xffffffffu, ps, 2);
                l0 = l0 * alpha + ps;
                m0 = mn;
                #pragma unroll
                for (int nt = 0; nt < 8; nt++) { o[nt][0] *= alpha; o[nt][1] *= alpha; }
            }
            {
                float rm = -CUDART_INF_F;
                #pragma unroll
                for (int nt = 0; nt < 8; nt++) rm = fmaxf(rm, fmaxf(s[nt][2], s[nt][3]));
                rm = fmaxf(rm, __shfl_xor_sync(0xffffffffu, rm, 1));
                rm = fmaxf(rm, __shfl_xor_sync(0xffffffffu, rm, 2));
                float mn = fmaxf(m1, rm);
                float alpha = __expf(m1 - mn);
                float ps = 0.f;
                #pragma unroll
                for (int nt = 0; nt < 8; nt++) {
                    s[nt][2] = __expf(s[nt][2] - mn);
                    s[nt][3] = __expf(s[nt][3] - mn);
                    ps += s[nt][2] + s[nt][3];
                }
                ps += __shfl_xor_sync(0xffffffffu, ps, 1);
                ps += __shfl_xor_sync(0xffffffffu, ps, 2);
                l1 = l1 * alpha + ps;
                m1 = mn;
                #pragma unroll
                for (int nt = 0; nt < 8; nt++) { o[nt][2] *= alpha; o[nt][3] *= alpha; }
            }

            #pragma unroll
            for (int nt = 0; nt < 8; nt++) {
                *(__half2*)(prow + lq * AHS + nt * 8 + 2 * lr) =
                    __floats2half2_rn(s[nt][0], s[nt][1]);
                *(__half2*)(prow + (lq + 8) * AHS + nt * 8 + 2 * lr) =
                    __floats2half2_rn(s[nt][2], s[nt][3]);
            }
            __syncwarp();

            #pragma unroll
            for (int ks = 0; ks < 4; ks++) {
                int k0 = ks * 16;
                uint32_t a0, a1, a2, a3;
                ldsm_x4(a0, a1, a2, a3,
                        sPw + (uint32_t)((lane & 15) * AHS + k0 + ((lane >> 4) << 3)) * 2);
                #pragma unroll
                for (int dp = 0; dp < 4; dp++) {
                    uint32_t b0, b1, b2, b3;
                    ldsm_x4t(b0, b1, b2, b3,
                             sV + (uint32_t)((k0 + (lane & 15)) * AHS
                                             + dp * 16 + ((lane >> 4) << 3)) * 2);
                    mma_f16(o[dp * 2][0], o[dp * 2][1], o[dp * 2][2], o[dp * 2][3],
                            a0, a1, a2, a3, b0, b1);
                    mma_f16(o[dp * 2 + 1][0], o[dp * 2 + 1][1], o[dp * 2 + 1][2], o[dp * 2 + 1][3],
                            a0, a1, a2, a3, b2, b3);
                }
            }
            __syncwarp();
        }

        float inv0 = 1.0f / l0, inv1 = 1.0f / l1;
        size_t r0 = (size_t)(bb * TSEQ + qb * 64 + warp * 16 + lq);
        size_t r1 = r0 + 8;
        #pragma unroll
        for (int nt = 0; nt < 8; nt++) {
            int col = h * HEADD + nt * 8 + 2 * lr;
            *(__half2*)(Out + r0 * EMB + col) =
                __floats2half2_rn(o[nt][0] * inv0, o[nt][1] * inv0);
            *(__half2*)(Out + r1 * EMB + col) =
                __floats2half2_rn(o[nt][2] * inv1, o[nt][3] * inv1);
        }
    }
}

// ---------------------------------------------------------------------------
// Launch
// ---------------------------------------------------------------------------
extern "C" void kernel_launch(void* const* d_in, const int* in_sizes, int n_in,
                              void* d_out, int out_size)
{
    const float* x      = (const float*)d_in[0];
    const float* ln1_g  = (const float*)d_in[1];
    const float* ln1_b  = (const float*)d_in[2];
    const float* wq     = (const float*)d_in[3];
    const float* wk     = (const float*)d_in[4];
    const float* wv     = (const float*)d_in[5];
    const float* w_proj = (const float*)d_in[6];
    const float* b_proj = (const float*)d_in[7];
    const float* ln2_g  = (const float*)d_in[8];
    const float* ln2_b  = (const float*)d_in[9];
    const float* w1     = (const float*)d_in[10];
    const float* b1     = (const float*)d_in[11];
    const float* w2     = (const float*)d_in[12];
    const float* b2     = (const float*)d_in[13];
    float* out = (float*)d_out;

    __half *h, *qkv, *attn, *mid;
    float  *out1;
    __half *wqkvT, *wpT, *w1T, *w2T;
    cudaGetSymbolAddress((void**)&h,     g_h);
    cudaGetSymbolAddress((void**)&qkv,   g_qkv);
    cudaGetSymbolAddress((void**)&attn,  g_attn);
    cudaGetSymbolAddress((void**)&out1,  g_out1);
    cudaGetSymbolAddress((void**)&mid,   g_mid);
    cudaGetSymbolAddress((void**)&wqkvT, g_wqkvT);
    cudaGetSymbolAddress((void**)&wpT,   g_wpT);
    cudaGetSymbolAddress((void**)&w1T,   g_w1T);
    cudaGetSymbolAddress((void**)&w2T,   g_w2T);

    cudaFuncSetAttribute(gemm_h_kernel<false, false>,
                         cudaFuncAttributeMaxDynamicSharedMemorySize, G4_SMEM);
    cudaFuncSetAttribute(gemm_h_kernel<false, true>,
                         cudaFuncAttributeMaxDynamicSharedMemorySize, G4_SMEM);
    cudaFuncSetAttribute(gemm_h_kernel<true, true>,
                         cudaFuncAttributeMaxDynamicSharedMemorySize, G4_SMEM);
    cudaFuncSetAttribute(attn_h_kernel,
                         cudaFuncAttributeMaxDynamicSharedMemorySize, AH_SMEM);

    // 0. Prep: 6 transposes + LN1 in one launch
    PrepArgs pa;
    pa.in[0] = wq;     pa.out[0] = wqkvT;                         pa.K[0] = EMB;   pa.N[0] = EMB;
    pa.in[1] = wk;     pa.out[1] = wqkvT + (size_t)EMB * EMB;     pa.K[1] = EMB;   pa.N[1] = EMB;
    pa.in[2] = wv;     pa.out[2] = wqkvT + (size_t)2 * EMB * EMB; pa.K[2] = EMB;   pa.N[2] = EMB;
    pa.in[3] = w_proj; pa.out[3] = wpT;                           pa.K[3] = EMB;   pa.N[3] = EMB;
    pa.in[4] = w1;     pa.out[4] = w1T;                           pa.K[4] = EMB;   pa.N[4] = FFDIM;
    pa.in[5] = w2;     pa.out[5] = w2T;                           pa.K[5] = FFDIM; pa.N[5] = EMB;
    int total = 0;
    for (int i = 0; i < 6; i++) {
        pa.off[i] = total;
        total += (pa.N[i] / 32) * (pa.K[i] / 32);
    }
    pa.trans_total = total;
    prep_kernel<<<total + MROWS, 256>>>(pa, x, ln1_g, ln1_b, h);

    // 2. Fused QKV projection
    dim3 gQKV(QKV_N / 128, MROWS / 128);
    gemm_h_kernel<false, true><<<gQKV, 128, G4_SMEM>>>(h, wqkvT, nullptr, nullptr, qkv, QKV_N, EMB);

    // 3. Causal flash attention
    attn_h_kernel<<<dim3(TSEQ / 128, NHEAD, BSZ), 128, AH_SMEM>>>(qkv, attn);

    // 4. out1 = x + attn @ w_proj + b_proj
    dim3 gE(EMB / 128, MROWS / 128);
    gemm_h_kernel<false, false><<<gE, 128, G4_SMEM>>>(attn, wpT, b_proj, x, out1, EMB, EMB);

    // 5. LN2 -> half
    ln_kernel<<<MROWS, 256>>>(out1, ln2_g, ln2_b, h);

    // 6. mid = gelu(h @ w1 + b1)
    dim3 gF(FFDIM / 128, MROWS / 128);
    gemm_h_kernel<true, true><<<gF, 128, G4_SMEM>>>(h, w1T, b1, nullptr, mid, FFDIM, EMB);

    // 7. out = out1 + mid @ w2 + b2
    gemm_h_kernel<false, false><<<gE, 128, G4_SMEM>>>(mid, w2T, b2, out1, out, EMB, FFDIM);
}

// round 15
// speedup vs baseline: 7.7406x; 1.0218x over previous
#include <cuda_runtime.h>
#include <cuda_fp16.h>
#include <math_constants.h>
#include <math.h>
#include <stdint.h>

#define BSZ   8
#define TSEQ  1024
#define EMB   1024
#define NHEAD 16
#define HEADD 64
#define MROWS (BSZ * TSEQ)   // 8192
#define FFDIM 4096
#define QKV_N 3072

// ---------------------------------------------------------------------------
// Scratch
// ---------------------------------------------------------------------------
__device__ __half g_h    [(size_t)MROWS * EMB];
__device__ __half g_qkv  [(size_t)MROWS * QKV_N];
__device__ __half g_attn [(size_t)MROWS * EMB];
__device__ float  g_out1 [(size_t)MROWS * EMB];
__device__ __half g_mid  [(size_t)MROWS * FFDIM];
__device__ __half g_wqkvT[(size_t)QKV_N * EMB];
__device__ __half g_wpT  [(size_t)EMB * EMB];
__device__ __half g_w1T  [(size_t)EMB * FFDIM];
__device__ __half g_w2T  [(size_t)FFDIM * EMB];

// ---------------------------------------------------------------------------
// Helpers
// ---------------------------------------------------------------------------
__device__ __forceinline__ uint32_t smem_u32(const void* p) {
    uint32_t a;
    asm("{ .reg .u64 t; cvta.to.shared.u64 t, %1; cvt.u32.u64 %0, t; }" : "=r"(a) : "l"(p));
    return a;
}

__device__ __forceinline__ void cp16(uint32_t dst, const void* src) {
    asm volatile("cp.async.cg.shared.global [%0], [%1], 16;" :: "r"(dst), "l"(src) : "memory");
}
__device__ __forceinline__ void cp_commit() {
    asm volatile("cp.async.commit_group;" ::: "memory");
}
template<int N>
__device__ __forceinline__ void cp_wait() {
    asm volatile("cp.async.wait_group %0;" :: "n"(N) : "memory");
}

__device__ __forceinline__ void ldsm_x4(uint32_t& r0, uint32_t& r1, uint32_t& r2, uint32_t& r3,
                                        uint32_t addr) {
    asm volatile("ldmatrix.sync.aligned.m8n8.x4.shared.b16 {%0,%1,%2,%3}, [%4];"
                 : "=r"(r0), "=r"(r1), "=r"(r2), "=r"(r3) : "r"(addr));
}
__device__ __forceinline__ void ldsm_x4t(uint32_t& r0, uint32_t& r1, uint32_t& r2, uint32_t& r3,
                                         uint32_t addr) {
    asm volatile("ldmatrix.sync.aligned.m8n8.x4.trans.shared.b16 {%0,%1,%2,%3}, [%4];"
                 : "=r"(r0), "=r"(r1), "=r"(r2), "=r"(r3) : "r"(addr));
}

__device__ __forceinline__ void mma_f16(float& c0, float& c1, float& c2, float& c3,
                                        uint32_t a0, uint32_t a1, uint32_t a2, uint32_t a3,
                                        uint32_t b0, uint32_t b1) {
    asm volatile(
        "mma.sync.aligned.m16n8k16.row.col.f32.f16.f16.f32 "
        "{%0,%1,%2,%3}, {%4,%5,%6,%7}, {%8,%9}, {%0,%1,%2,%3};"
        : "+f"(c0), "+f"(c1), "+f"(c2), "+f"(c3)
        : "r"(a0), "r"(a1), "r"(a2), "r"(a3), "r"(b0), "r"(b1));
}

// Fast GELU: tanh-form with HW tanh.approx
__device__ __forceinline__ float gelu_fast(float x) {
    float u = x * (0.7978845608028654f + 0.035677408136300125f * x * x);
    float t;
    asm("tanh.approx.f32 %0, %1;" : "=f"(t) : "f"(u));
    return 0.5f * x * (1.0f + t);
}

// ---------------------------------------------------------------------------
// Fused prep: 6 weight transposes + LN1, one launch.
// ---------------------------------------------------------------------------
struct PrepArgs {
    const float* in[6];
    __half*      out[6];
    int K[6], N[6];
    int off[6];
    int trans_total;
};

__global__ __launch_bounds__(256)
void prep_kernel(PrepArgs A, const float* __restrict__ x, const float* __restrict__ lg,
                 const float* __restrict__ lb, __half* __restrict__ lnout)
{
    int blk = blockIdx.x;
    int tid = threadIdx.x;

    if (blk < A.trans_total) {
        __shared__ float t[32][33];
        int m = 0;
        #pragma unroll
        for (int i = 1; i < 6; i++) if (blk >= A.off[i]) m = i;
        int lt = blk - A.off[m];
        int N = A.N[m], K = A.K[m];
        int ntx = N >> 5;
        int n0 = (lt % ntx) * 32, k0 = (lt / ntx) * 32;
        const float* in = A.in[m];
        __half* out = A.out[m];
        int tx = tid & 31, ty = tid >> 5;
        #pragma unroll
        for (int i = 0; i < 32; i += 8)
            t[ty + i][tx] = in[(size_t)(k0 + ty + i) * N + n0 + tx];
        __syncthreads();
        #pragma unroll
        for (int i = 0; i < 32; i += 8)
            out[(size_t)(n0 + ty + i) * K + k0 + tx] = __float2half_rn(t[tx][ty + i]);
        return;
    }

    int row = blk - A.trans_total;
    const float4* xr = (const float4*)(x + (size_t)row * EMB);
    float4 v = xr[tid];
    float s  = v.x + v.y + v.z + v.w;
    float ss = v.x * v.x + v.y * v.y + v.z * v.z + v.w * v.w;
    #pragma unroll
    for (int o = 16; o; o >>= 1) {
        s  += __shfl_xor_sync(0xffffffffu, s,  o);
        ss += __shfl_xor_sync(0xffffffffu, ss, o);
    }
    __shared__ float rs_[8], rss_[8];
    __shared__ float mu_s, rstd_s;
    int warp = tid >> 5, lane = tid & 31;
    if (lane == 0) { rs_[warp] = s; rss_[warp] = ss; }
    __syncthreads();
    if (tid == 0) {
        float S = 0.f, SS = 0.f;
        #pragma unroll
        for (int i = 0; i < 8; i++) { S += rs_[i]; SS += rss_[i]; }
        float mu  = S * (1.0f / EMB);
        float var = SS * (1.0f / EMB) - mu * mu;
        mu_s = mu;
        rstd_s = rsqrtf(var + 1e-5f);
    }
    __syncthreads();
    float mu = mu_s, r = rstd_s;
    float4 gv = ((const float4*)lg)[tid];
    float4 bv = ((const float4*)lb)[tid];
    __half2* orow = (__half2*)(lnout + (size_t)row * EMB);
    orow[2 * tid]     = __floats2half2_rn((v.x - mu) * r * gv.x + bv.x,
                                          (v.y - mu) * r * gv.y + bv.y);
    orow[2 * tid + 1] = __floats2half2_rn((v.z - mu) * r * gv.z + bv.z,
                                          (v.w - mu) * r * gv.w + bv.w);
}

// ---------------------------------------------------------------------------
// LayerNorm (standalone, for LN2)
// ---------------------------------------------------------------------------
__global__ __launch_bounds__(256)
void ln_kernel(const float* __restrict__ x, const float* __restrict__ g,
               const float* __restrict__ b, __half* __restrict__ out)
{
    int row = blockIdx.x;
    int t   = threadIdx.x;
    const float4* xr = (const float4*)(x + (size_t)row * EMB);
    float4 v = xr[t];
    float s  = v.x + v.y + v.z + v.w;
    float ss = v.x * v.x + v.y * v.y + v.z * v.z + v.w * v.w;
    #pragma unroll
    for (int o = 16; o; o >>= 1) {
        s  += __shfl_xor_sync(0xffffffffu, s,  o);
        ss += __shfl_xor_sync(0xffffffffu, ss, o);
    }
    __shared__ float rs_[8], rss_[8];
    __shared__ float mu_s, rstd_s;
    int warp = t >> 5, lane = t & 31;
    if (lane == 0) { rs_[warp] = s; rss_[warp] = ss; }
    __syncthreads();
    if (t == 0) {
        float S = 0.f, SS = 0.f;
        #pragma unroll
        for (int i = 0; i < 8; i++) { S += rs_[i]; SS += rss_[i]; }
        float mu  = S * (1.0f / EMB);
        float var = SS * (1.0f / EMB) - mu * mu;
        mu_s = mu;
        rstd_s = rsqrtf(var + 1e-5f);
    }
    __syncthreads();
    float mu = mu_s, r = rstd_s;
    float4 gv = ((const float4*)g)[t];
    float4 bv = ((const float4*)b)[t];
    __half2* orow = (__half2*)(out + (size_t)row * EMB);
    orow[2 * t]     = __floats2half2_rn((v.x - mu) * r * gv.x + bv.x,
                                        (v.y - mu) * r * gv.y + bv.y);
    orow[2 * t + 1] = __floats2half2_rn((v.z - mu) * r * gv.z + bv.z,
                                        (v.w - mu) * r * gv.w + bv.w);
}

// ---------------------------------------------------------------------------
// fp16 mma GEMM v5: CTA 128x128, 256 threads (8 warps, warp tile 64x32),
// BK=64, 3-stage cp.async, ONE barrier per chunk, 2 CTAs/SM (16 warps/SM).
// ---------------------------------------------------------------------------
#define G5_STRIDE 72
#define G5_ATILE (128 * G5_STRIDE * 2)   // 18432 B
#define G5_STAGE (2 * G5_ATILE)          // 36864 B (A+B)
#define G5_SMEM  (3 * G5_STAGE)          // 110592 B -> 2 CTAs/SM

template<bool GELU, bool HALF_OUT>
__global__ __launch_bounds__(256, 2)
void gemm_h_kernel(const __half* __restrict__ A, const __half* __restrict__ Bt,
                   const float* __restrict__ bias, const float* __restrict__ res,
                   void* __restrict__ Cv, int N_, int K_)
{
    extern __shared__ char smem[];
    const uint32_t sb = smem_u32(smem);
    int tid  = threadIdx.x;
    int lane = tid & 31, warp = tid >> 5;
    int wm = warp >> 2;   // 0..1 (64-row slab)
    int wn = warp & 3;    // 0..3 (32-col slab)
    int rowBase = blockIdx.y * 128;
    int colBase = blockIdx.x * 128;
    const int C_CHUNKS = K_ >> 6;

    auto load_chunk = [&](int c, int st) {
        int k0 = c << 6;
        uint32_t aB = sb + st * G5_STAGE;
        uint32_t bB = aB + G5_ATILE;
        #pragma unroll
        for (int s = 0; s < 4; s++) {          // A: 1024 x 16B
            int idx = tid + s * 256;
            int r = idx >> 3, ch = idx & 7;
            cp16(aB + (uint32_t)(r * G5_STRIDE + ch * 8) * 2,
                 A + (size_t)(rowBase + r) * K_ + k0 + ch * 8);
        }
        #pragma unroll
        for (int s = 0; s < 4; s++) {          // B: 1024 x 16B
            int idx = tid + s * 256;
            int r = idx >> 3, ch = idx & 7;
            cp16(bB + (uint32_t)(r * G5_STRIDE + ch * 8) * 2,
                 Bt + (size_t)(colBase + r) * K_ + k0 + ch * 8);
        }
        cp_commit();
    };

    float acc[4][4][4];
    #pragma unroll
    for (int i = 0; i < 4; i++)
        #pragma unroll
        for (int j = 0; j < 4; j++)
            #pragma unroll
            for (int r = 0; r < 4; r++) acc[i][j][r] = 0.f;

    load_chunk(0, 0);
    load_chunk(1, 1);

    for (int c = 0; c < C_CHUNKS; c++) {
        cp_wait<1>();
        __syncthreads();
        if (c + 2 < C_CHUNKS) load_chunk(c + 2, (c + 2) % 3);
        else cp_commit();

        uint32_t aBase = sb + (c % 3) * G5_STAGE;
        uint32_t bBase = aBase + G5_ATILE;

        #pragma unroll
        for (int ks = 0; ks < 4; ks++) {
            int k0 = ks * 16;
            uint32_t a[4][4];
            #pragma unroll
            for (int mt = 0; mt < 4; mt++) {
                uint32_t addr = aBase +
                    (uint32_t)((wm * 64 + mt * 16 + (lane & 15)) * G5_STRIDE
                               + k0 + ((lane >> 4) << 3)) * 2;
                ldsm_x4(a[mt][0], a[mt][1], a[mt][2], a[mt][3], addr);
            }
            uint32_t bf[4][2];
            {
                // two n16 groups cover the 32-col slab
                int n = wn * 32 + ((lane >> 4) << 3) + (lane & 7);
                int koff = ((lane >> 3) & 1) << 3;
                ldsm_x4(bf[0][0], bf[0][1], bf[1][0], bf[1][1],
                        bBase + (uint32_t)(n * G5_STRIDE + k0 + koff) * 2);
                ldsm_x4(bf[2][0], bf[2][1], bf[3][0], bf[3][1],
                        bBase + (uint32_t)((n + 16) * G5_STRIDE + k0 + koff) * 2);
            }
            #pragma unroll
            for (int mt = 0; mt < 4; mt++)
                #pragma unroll
                for (int nt = 0; nt < 4; nt++)
                    mma_f16(acc[mt][nt][0], acc[mt][nt][1], acc[mt][nt][2], acc[mt][nt][3],
                            a[mt][0], a[mt][1], a[mt][2], a[mt][3],
                            bf[nt][0], bf[nt][1]);
        }
    }

    int lq = lane >> 2, lr = lane & 3;
    __half* Ch = (__half*)Cv;
    float*  Cf = (float*)Cv;
    #pragma unroll
    for (int mt = 0; mt < 4; mt++) {
        int row0 = rowBase + wm * 64 + mt * 16 + lq;
        #pragma unroll
        for (int nt = 0; nt < 4; nt++) {
            int col = colBase + wn * 32 + nt * 8 + lr * 2;
            float2 p0 = make_float2(acc[mt][nt][0], acc[mt][nt][1]);
            float2 p1 = make_float2(acc[mt][nt][2], acc[mt][nt][3]);
            if (bias) {
                float2 bv = *(const float2*)(bias + col);
                p0.x += bv.x; p0.y += bv.y;
                p1.x += bv.x; p1.y += bv.y;
            }
            if (res) {
                float2 r0 = *(const float2*)(res + (size_t)row0 * N_ + col);
                float2 r1 = *(const float2*)(res + (size_t)(row0 + 8) * N_ + col);
                p0.x += r0.x; p0.y += r0.y;
                p1.x += r1.x; p1.y += r1.y;
            }
            if (GELU) {
                p0.x = gelu_fast(p0.x);
                p0.y = gelu_fast(p0.y);
                p1.x = gelu_fast(p1.x);
                p1.y = gelu_fast(p1.y);
            }
            if (HALF_OUT) {
                *(__half2*)(Ch + (size_t)row0 * N_ + col) = __floats2half2_rn(p0.x, p0.y);
                *(__half2*)(Ch + (size_t)(row0 + 8) * N_ + col) = __floats2half2_rn(p1.x, p1.y);
            } else {
                *(float2*)(Cf + (size_t)row0 * N_ + col) = p0;
                *(float2*)(Cf + (size_t)(row0 + 8) * N_ + col) = p1;
            }
        }
    }
}

// ---------------------------------------------------------------------------
// fp16 flash attention, cp.async double-buffered K/V, 2 Q-tiles per CTA.
// ---------------------------------------------------------------------------
#define AHS 72
#define AKV (64 * AHS)
#define AH_SMEM (6 * AKV * 2)             // 55296 B

__global__ __launch_bounds__(128)
void attn_h_kernel(const __half* __restrict__ QKV, __half* __restrict__ Out)
{
    extern __shared__ char smraw[];
    __half* sm = (__half*)smraw;
    __half* Qs = sm;
    __half* Ks = sm + AKV;
    __half* Vs = sm + 3 * AKV;
    __half* Ps = sm + 5 * AKV;
    const uint32_t sQ = smem_u32(Qs), sK0 = smem_u32(Ks), sV0 = smem_u32(Vs),
                   sP = smem_u32(Ps);

    int qb0 = blockIdx.x, h = blockIdx.y, bb = blockIdx.z;
    int tid = threadIdx.x;
    int lane = tid & 31, warp = tid >> 5;
    int lq = lane >> 2, lr = lane & 3;

    const __half* Qp = QKV + h * HEADD;
    const __half* Kp = QKV + EMB + h * HEADD;
    const __half* Vp = QKV + 2 * EMB + h * HEADD;

    auto load_kv = [&](int jt, int b) {
        size_t kbase = (size_t)(bb * TSEQ + jt * 64) * QKV_N;
        uint32_t kB = sK0 + (uint32_t)(b * AKV) * 2;
        uint32_t vB = sV0 + (uint32_t)(b * AKV) * 2;
        #pragma unroll
        for (int s = 0; s < 4; s++) {
            int idx = tid + s * 128;
            int r = idx >> 3, ch = idx & 7;
            cp16(kB + (uint32_t)(r * AHS + ch * 8) * 2,
                 Kp + kbase + (size_t)r * QKV_N + ch * 8);
            cp16(vB + (uint32_t)(r * AHS + ch * 8) * 2,
                 Vp + kbase + (size_t)r * QKV_N + ch * 8);
        }
        cp_commit();
    };

    const uint32_t sPw = sP + (uint32_t)(warp * 16 * AHS) * 2;
    __half* prow = Ps + warp * 16 * AHS;

    #pragma unroll
    for (int rep = 0; rep < 2; rep++) {
        int qb = rep ? (TSEQ / 64 - 1 - qb0) : qb0;

        __syncthreads();

        size_t qbase = (size_t)(bb * TSEQ + qb * 64) * QKV_N;
        #pragma unroll
        for (int s = 0; s < 4; s++) {
            int idx = tid + s * 128;
            int r = idx >> 3, ch = idx & 7;
            *(float4*)(Qs + r * AHS + ch * 8) =
                *(const float4*)(Qp + qbase + (size_t)r * QKV_N + ch * 8);
        }
        load_kv(0, 0);

        float m0 = -CUDART_INF_F, m1 = -CUDART_INF_F;
        float l0 = 0.f, l1 = 0.f;
        float o[8][4];
        #pragma unroll
        for (int nt = 0; nt < 8; nt++)
            #pragma unroll
            for (int r = 0; r < 4; r++) o[nt][r] = 0.f;

        for (int jt = 0; jt <= qb; jt++) {
            cp_wait<0>();
            __syncthreads();
            if (jt < qb) load_kv(jt + 1, (jt + 1) & 1);

            uint32_t sK = sK0 + (uint32_t)((jt & 1) * AKV) * 2;
            uint32_t sV = sV0 + (uint32_t)((jt & 1) * AKV) * 2;

            float s[8][4];
            #pragma unroll
            for (int nt = 0; nt < 8; nt++)
                #pragma unroll
                for (int r = 0; r < 4; r++) s[nt][r] = 0.f;

            #pragma unroll
            for (int ks = 0; ks < 4; ks++) {
                int k0 = ks * 16;
                uint32_t a0, a1, a2, a3;
                ldsm_x4(a0, a1, a2, a3,
                        sQ + (uint32_t)((warp * 16 + (lane & 15)) * AHS
                                        + k0 + ((lane >> 4) << 3)) * 2);
                #pragma unroll
                for (int np = 0; np < 4; np++) {
                    int n = np * 16 + ((lane >> 4) << 3) + (lane & 7);
                    int koff = ((lane >> 3) & 1) << 3;
                    uint32_t b0, b1, b2, b3;
                    ldsm_x4(b0, b1, b2, b3,
                            sK + (uint32_t)(n * AHS + k0 + koff) * 2);
                    mma_f16(s[np * 2][0], s[np * 2][1], s[np * 2][2], s[np * 2][3],
                            a0, a1, a2, a3, b0, b1);
                    mma_f16(s[np * 2 + 1][0], s[np * 2 + 1][1], s[np * 2 + 1][2], s[np * 2 + 1][3],
                            a0, a1, a2, a3, b2, b3);
                }
            }

            const float scale = 0.125f;
            bool diag = (jt == qb);
            int row0 = warp * 16 + lq;
            #pragma unroll
            for (int nt = 0; nt < 8; nt++) {
                int col = nt * 8 + 2 * lr;
                s[nt][0] *= scale; s[nt][1] *= scale;
                s[nt][2] *= scale; s[nt][3] *= scale;
                if (diag) {
                    if (col     > row0)     s[nt][0] = -CUDART_INF_F;
                    if (col + 1 > row0)     s[nt][1] = -CUDART_INF_F;
                    if (col     > row0 + 8) s[nt][2] = -CUDART_INF_F;
                    if (col + 1 > row0 + 8) s[nt][3] = -CUDART_INF_F;
                }
            }

            {
                float rm = -CUDART_INF_F;
                #pragma unroll
                for (int nt = 0; nt < 8; nt++) rm = fmaxf(rm, fmaxf(s[nt][0], s[nt][1]));
                rm = fmaxf(rm, __shfl_xor_sync(0xffffffffu, rm, 1));
                rm = fmaxf(rm, __shfl_xor_sync(0xffffffffu, rm, 2));
                float mn = fmaxf(m0, rm);
                float alpha = __expf(m0 - mn);
                float ps = 0.f;
                #pragma unroll
                for (int nt = 0; nt < 8; nt++) {
                    s[nt][0] = __expf(s[nt][0] - mn);
                    s[nt][1] = __expf(s[nt][1] - mn);
                    ps += s[nt][0] + s[nt][1];
                }
                ps += __shfl_xor_sync(0xffffffffu, ps, 1);
                ps += __shfl_xor_sync(0xffffffffu, ps, 2);
                l0 = l0 * alpha + ps;
                m0 = mn;
                #pragma unroll
                for (int nt = 0; nt < 8; nt++) { o[nt][0] *= alpha; o[nt][1] *= alpha; }
            }
            {
                float rm = -CUDART_INF_F;
                #pragma unroll
                for (int nt = 0; nt < 8; nt++) rm = fmaxf(rm, fmaxf(s[nt][2], s[nt][3]));
                rm = fmaxf(rm, __shfl_xor_sync(0xffffffffu, rm, 1));
                rm = fmaxf(rm, __shfl_xor_sync(0xffffffffu, rm, 2));
                float mn = fmaxf(m1, rm);
                float alpha = __expf(m1 - mn);
                float ps = 0.f;
                #pragma unroll
                for (int nt = 0; nt < 8; nt++) {
                    s[nt][2] = __expf(s[nt][2] - mn);
                    s[nt][3] = __expf(s[nt][3] - mn);
                    ps += s[nt][2] + s[nt][3];
                }
                ps += __shfl_xor_sync(0xffffffffu, ps, 1);
                ps += __shfl_xor_sync(0xffffffffu, ps, 2);
                l1 = l1 * alpha + ps;
                m1 = mn;
                #pragma unroll
                for (int nt = 0; nt < 8; nt++) { o[nt][2] *= alpha; o[nt][3] *= alpha; }
            }

            #pragma unroll
            for (int nt = 0; nt < 8; nt++) {
                *(__half2*)(prow + lq * AHS + nt * 8 + 2 * lr) =
                    __floats2half2_rn(s[nt][0], s[nt][1]);
                *(__half2*)(prow + (lq + 8) * AHS + nt * 8 + 2 * lr) =
                    __floats2half2_rn(s[nt][2], s[nt][3]);
            }
            __syncwarp();

            #pragma unroll
            for (int ks = 0; ks < 4; ks++) {
                int k0 = ks * 16;
                uint32_t a0, a1, a2, a3;
                ldsm_x4(a0, a1, a2, a3,
                        sPw + (uint32_t)((lane & 15) * AHS + k0 + ((lane >> 4) << 3)) * 2);
                #pragma unroll
                for (int dp = 0; dp < 4; dp++) {
                    uint32_t b0, b1, b2, b3;
                    ldsm_x4t(b0, b1, b2, b3,
                             sV + (uint32_t)((k0 + (lane & 15)) * AHS
                                             + dp * 16 + ((lane >> 4) << 3)) * 2);
                    mma_f16(o[dp * 2][0], o[dp * 2][1], o[dp * 2][2], o[dp * 2][3],
                            a0, a1, a2, a3, b0, b1);
                    mma_f16(o[dp * 2 + 1][0], o[dp * 2 + 1][1], o[dp * 2 + 1][2], o[dp * 2 + 1][3],
                            a0, a1, a2, a3, b2, b3);
                }
            }
            __syncwarp();
        }

        float inv0 = 1.0f / l0, inv1 = 1.0f / l1;
        size_t r0 = (size_t)(bb * TSEQ + qb * 64 + warp * 16 + lq);
        size_t r1 = r0 + 8;
        #pragma unroll
        for (int nt = 0; nt < 8; nt++) {
            int col = h * HEADD + nt * 8 + 2 * lr;
            *(__half2*)(Out + r0 * EMB + col) =
                __floats2half2_rn(o[nt][0] * inv0, o[nt][1] * inv0);
            *(__half2*)(Out + r1 * EMB + col) =
                __floats2half2_rn(o[nt][2] * inv1, o[nt][3] * inv1);
        }
    }
}

// ---------------------------------------------------------------------------
// Launch
// ---------------------------------------------------------------------------
extern "C" void kernel_launch(void* const* d_in, const int* in_sizes, int n_in,
                              void* d_out, int out_size)
{
    const float* x      = (const float*)d_in[0];
    const float* ln1_g  = (const float*)d_in[1];
    const float* ln1_b  = (const float*)d_in[2];
    const float* wq     = (const float*)d_in[3];
    const float* wk     = (const float*)d_in[4];
    const float* wv     = (const float*)d_in[5];
    const float* w_proj = (const float*)d_in[6];
    const float* b_proj = (const float*)d_in[7];
    const float* ln2_g  = (const float*)d_in[8];
    const float* ln2_b  = (const float*)d_in[9];
    const float* w1     = (const float*)d_in[10];
    const float* b1     = (const float*)d_in[11];
    const float* w2     = (const float*)d_in[12];
    const float* b2     = (const float*)d_in[13];
    float* out = (float*)d_out;

    __half *h, *qkv, *attn, *mid;
    float  *out1;
    __half *wqkvT, *wpT, *w1T, *w2T;
    cudaGetSymbolAddress((void**)&h,     g_h);
    cudaGetSymbolAddress((void**)&qkv,   g_qkv);
    cudaGetSymbolAddress((void**)&attn,  g_attn);
    cudaGetSymbolAddress((void**)&out1,  g_out1);
    cudaGetSymbolAddress((void**)&mid,   g_mid);
    cudaGetSymbolAddress((void**)&wqkvT, g_wqkvT);
    cudaGetSymbolAddress((void**)&wpT,   g_wpT);
    cudaGetSymbolAddress((void**)&w1T,   g_w1T);
    cudaGetSymbolAddress((void**)&w2T,   g_w2T);

    cudaFuncSetAttribute(gemm_h_kernel<false, false>,
                         cudaFuncAttributeMaxDynamicSharedMemorySize, G5_SMEM);
    cudaFuncSetAttribute(gemm_h_kernel<false, true>,
                         cudaFuncAttributeMaxDynamicSharedMemorySize, G5_SMEM);
    cudaFuncSetAttribute(gemm_h_kernel<true, true>,
                         cudaFuncAttributeMaxDynamicSharedMemorySize, G5_SMEM);
    cudaFuncSetAttribute(attn_h_kernel,
                         cudaFuncAttributeMaxDynamicSharedMemorySize, AH_SMEM);

    // 0. Prep: 6 transposes + LN1 in one launch
    PrepArgs pa;
    pa.in[0] = wq;     pa.out[0] = wqkvT;                         pa.K[0] = EMB;   pa.N[0] = EMB;
    pa.in[1] = wk;     pa.out[1] = wqkvT + (size_t)EMB * EMB;     pa.K[1] = EMB;   pa.N[1] = EMB;
    pa.in[2] = wv;     pa.out[2] = wqkvT + (size_t)2 * EMB * EMB; pa.K[2] = EMB;   pa.N[2] = EMB;
    pa.in[3] = w_proj; pa.out[3] = wpT;                           pa.K[3] = EMB;   pa.N[3] = EMB;
    pa.in[4] = w1;     pa.out[4] = w1T;                           pa.K[4] = EMB;   pa.N[4] = FFDIM;
    pa.in[5] = w2;     pa.out[5] = w2T;                           pa.K[5] = FFDIM; pa.N[5] = EMB;
    int total = 0;
    for (int i = 0; i < 6; i++) {
        pa.off[i] = total;
        total += (pa.N[i] / 32) * (pa.K[i] / 32);
    }
    pa.trans_total = total;
    prep_kernel<<<total + MROWS, 256>>>(pa, x, ln1_g, ln1_b, h);

    // 2. Fused QKV projection
    dim3 gQKV(QKV_N / 128, MROWS / 128);
    gemm_h_kernel<false, true><<<gQKV, 256, G5_SMEM>>>(h, wqkvT, nullptr, nullptr, qkv, QKV_N, EMB);

    // 3. Causal flash attention
    attn_h_kernel<<<dim3(TSEQ / 128, NHEAD, BSZ), 128, AH_SMEM>>>(qkv, attn);

    // 4. out1 = x + attn @ w_proj + b_proj
    dim3 gE(EMB / 128, MROWS / 128);
    gemm_h_kernel<false, false><<<gE, 256, G5_SMEM>>>(attn, wpT, b_proj, x, out1, EMB, EMB);

    // 5. LN2 -> half
    ln_kernel<<<MROWS, 256>>>(out1, ln2_g, ln2_b, h);

    // 6. mid = gelu(h @ w1 + b1)
    dim3 gF(FFDIM / 128, MROWS / 128);
    gemm_h_kernel<true, true><<<gF, 256, G5_SMEM>>>(h, w1T, b1, nullptr, mid, FFDIM, EMB);

    // 7. out = out1 + mid @ w2 + b2
    gemm_h_kernel<false, false><<<gE, 256, G5_SMEM>>>(mid, w2T, b2, out1, out, EMB, FFDIM);
}